// round 11
// baseline (speedup 1.0000x reference)
#include <cuda_runtime.h>
#include <cuda_fp16.h>
#include <cstdint>

// ---------------------------------------------------------------------------
// LiteMLA on sm_103a.
// Four-stream batch-split pipeline; single-sync 3-stage GEMM mainloops.
// qkv GEMM: fp16 hi/lo x hi/lo, 3 mma products. proj: 2 products.
// dwpw: depthwise f32x2 -> register-tiled pointwise -> fused vk (all heads).
// ---------------------------------------------------------------------------

#define BATCH 8
#define C3 768
#define NPIX 4096
#define WIDTH 64

__device__ float g_qkv[(size_t)BATCH * C3 * NPIX];
__device__ float g_s3q[(size_t)BATCH * 32 * 8 * NPIX];
__device__ float g_s5q[(size_t)BATCH * 32 * 8 * NPIX];
__device__ float g_vk [(size_t)BATCH * 96 * 72];

__device__ __half g_xt_h [(size_t)BATCH * 256 * NPIX];
__device__ __half g_xt_l [(size_t)BATCH * 256 * NPIX];
__device__ __half g_at_h [(size_t)BATCH * C3 * NPIX];
__device__ __half g_wq_h [C3 * 256];
__device__ __half g_wq_l [C3 * 256];
__device__ __half g_wp_h [256 * C3];
__device__ __half g_wp_l [256 * C3];

// ---------------------------------------------------------------------------
typedef unsigned long long ull;

__device__ __forceinline__ uint32_t smem_u32(const void* p) {
    uint32_t a;
    asm("{ .reg .u64 t; cvta.to.shared.u64 t, %1; cvt.u32.u64 %0, t; }"
        : "=r"(a) : "l"(p));
    return a;
}
__device__ __forceinline__ ull pk2(float lo, float hi) {
    ull r;
    asm("mov.b64 %0, {%1, %2};" : "=l"(r)
        : "r"(__float_as_uint(lo)), "r"(__float_as_uint(hi)));
    return r;
}
__device__ __forceinline__ void ffma2(ull& d, ull a, ull b) {
    asm("fma.rn.f32x2 %0, %1, %2, %0;" : "+l"(d) : "l"(a), "l"(b));
}
__device__ __forceinline__ float f2lo(ull v) {
    return __uint_as_float((unsigned)(v & 0xffffffffull));
}
__device__ __forceinline__ float f2hi(ull v) {
    return __uint_as_float((unsigned)(v >> 32));
}

#define CP_ASYNC16(s, g) \
    asm volatile("cp.async.cg.shared.global [%0], [%1], 16;" :: "r"(s), "l"(g))
#define CP_COMMIT() asm volatile("cp.async.commit_group;" ::: "memory")
#define CP_WAIT(n)  asm volatile("cp.async.wait_group %0;" :: "n"(n) : "memory")

__device__ __forceinline__ void ldsm4(uint32_t addr, uint32_t* r) {
    asm volatile("ldmatrix.sync.aligned.m8n8.x4.shared.b16 {%0,%1,%2,%3}, [%4];"
                 : "=r"(r[0]), "=r"(r[1]), "=r"(r[2]), "=r"(r[3]) : "r"(addr));
}
__device__ __forceinline__ void ldsm4t(uint32_t addr, uint32_t* r) {
    asm volatile("ldmatrix.sync.aligned.m8n8.x4.trans.shared.b16 {%0,%1,%2,%3}, [%4];"
                 : "=r"(r[0]), "=r"(r[1]), "=r"(r[2]), "=r"(r[3]) : "r"(addr));
}
__device__ __forceinline__ void mma_f16(float* d, const uint32_t* a,
                                        const uint32_t* b) {
    asm volatile(
        "mma.sync.aligned.m16n8k16.row.col.f32.f16.f16.f32 "
        "{%0,%1,%2,%3}, {%4,%5,%6,%7}, {%8,%9}, {%0,%1,%2,%3};"
        : "+f"(d[0]), "+f"(d[1]), "+f"(d[2]), "+f"(d[3])
        : "r"(a[0]), "r"(a[1]), "r"(a[2]), "r"(a[3]), "r"(b[0]), "r"(b[1]));
}

#define A_PITCH 80
#define B_PITCH 272

// ---------------------------------------------------------------------------
// 3-product GEMM (qkv): single-sync 3-stage ring, 2 CTAs/SM.
// ---------------------------------------------------------------------------
#define OFF_AL  10240
#define OFF_BH  20480
#define OFF_BL  29184
#define STG2    37888

__device__ __forceinline__ void stage_load(
    uint32_t sbase, const __half* gA_h, const __half* gA_l,
    const __half* gB_h, const __half* gB_l, int K, int N, int kc, int tid)
{
    const int op = tid >> 6;
    const int t  = tid & 63;
    if (op < 2) {
        const __half* g = ((op == 0) ? gA_h : gA_l) + kc * 32;
        const uint32_t sb = sbase + op * OFF_AL;
#pragma unroll
        for (int it = 0; it < 8; it++) {
            int chunk = t + it * 64;
            int row = chunk >> 2, c = chunk & 3;
            CP_ASYNC16(sb + row * A_PITCH + c * 16, g + (size_t)row * K + c * 8);
        }
    } else {
        const __half* g = ((op == 2) ? gB_h : gB_l) + (size_t)kc * 32 * N;
        const uint32_t sb = sbase + ((op == 2) ? OFF_BH : OFF_BL);
#pragma unroll
        for (int it = 0; it < 8; it++) {
            int chunk = t + it * 64;
            int row = chunk >> 4, c = chunk & 15;
            CP_ASYNC16(sb + row * B_PITCH + c * 16, g + (size_t)row * N + c * 8);
        }
    }
}

__global__ __launch_bounds__(256, 2)
void gemm_f16(const __half* __restrict__ Ah, const __half* __restrict__ Al,
              const __half* __restrict__ Bmh, const __half* __restrict__ Bml,
              const float* __restrict__ bias, float* __restrict__ C,
              int M, int N, int K)
{
    extern __shared__ __align__(16) char smem[];
    const uint32_t sm0 = smem_u32(smem);

    const int tid  = threadIdx.x;
    const int wid  = tid >> 5;
    const int lane = tid & 31;
    const int n0 = blockIdx.x * 128;
    const int m0 = blockIdx.y * 128;
    const int b  = blockIdx.z;

    const int wm = (wid >> 1) * 32;
    const int wn = (wid & 1) * 64;

    const __half* gA_h = Ah + (size_t)m0 * K;
    const __half* gA_l = Al + (size_t)m0 * K;
    const __half* gB_h = Bmh + (size_t)b * K * N + n0;
    const __half* gB_l = Bml + (size_t)b * K * N + n0;

    float acc[2][8][4];
#pragma unroll
    for (int t = 0; t < 2; t++)
#pragma unroll
        for (int nt = 0; nt < 8; nt++)
#pragma unroll
            for (int i = 0; i < 4; i++) acc[t][nt][i] = 0.f;

    const int nk = K / 32;

    stage_load(sm0, gA_h, gA_l, gB_h, gB_l, K, N, 0, tid);
    CP_COMMIT();
    if (nk > 1) {
        stage_load(sm0 + STG2, gA_h, gA_l, gB_h, gB_l, K, N, 1, tid);
        CP_COMMIT();
    }

    const int a_row = lane & 15;
    const int a_hi  = (lane >> 4) * 16;
    const int b_kr = (lane & 7) + ((lane >> 3) & 1) * 8;
    const int b_nc = (lane >> 4) * 8;

    for (int kc = 0; kc < nk; kc++) {
        // wait for stage kc: at most 1 outstanding newer group allowed
        if (kc + 1 < nk) CP_WAIT(1); else CP_WAIT(0);
        __syncthreads();   // single barrier: buf (kc+2)%3 was last read at kc-1

        if (kc + 2 < nk) {
            stage_load(sm0 + ((kc + 2) % 3) * STG2,
                       gA_h, gA_l, gB_h, gB_l, K, N, kc + 2, tid);
            CP_COMMIT();
        }

        const uint32_t sb  = sm0 + (kc % 3) * STG2;
        const uint32_t aAh = sb;
        const uint32_t aAl = sb + OFF_AL;
        const uint32_t aBh = sb + OFF_BH;
        const uint32_t aBl = sb + OFF_BL;

#pragma unroll
        for (int j = 0; j < 2; j++) {
            uint32_t ah[2][4], al[2][4];
#pragma unroll
            for (int t = 0; t < 2; t++) {
                uint32_t off = (uint32_t)(wm + t * 16 + a_row) * A_PITCH + j * 32 + a_hi;
                ldsm4(aAh + off, ah[t]);
                ldsm4(aAl + off, al[t]);
            }
            uint32_t bh[4][4], bl[4][4];
#pragma unroll
            for (int p = 0; p < 4; p++) {
                uint32_t off = (uint32_t)(j * 16 + b_kr) * B_PITCH +
                               (uint32_t)(wn + p * 16 + b_nc) * 2;
                ldsm4t(aBh + off, bh[p]);
                ldsm4t(aBl + off, bl[p]);
            }
            // products grouped by type: maximally independent chains
#pragma unroll
            for (int t = 0; t < 2; t++)
#pragma unroll
                for (int nt = 0; nt < 8; nt++)
                    mma_f16(acc[t][nt], ah[t], &bh[nt >> 1][(nt & 1) * 2]);
#pragma unroll
            for (int t = 0; t < 2; t++)
#pragma unroll
                for (int nt = 0; nt < 8; nt++)
                    mma_f16(acc[t][nt], ah[t], &bl[nt >> 1][(nt & 1) * 2]);
#pragma unroll
            for (int t = 0; t < 2; t++)
#pragma unroll
                for (int nt = 0; nt < 8; nt++)
                    mma_f16(acc[t][nt], al[t], &bh[nt >> 1][(nt & 1) * 2]);
        }
    }

    const int l4 = lane >> 2;
    const int l2 = (lane & 3) * 2;
#pragma unroll
    for (int t = 0; t < 2; t++) {
        const int m_lo = m0 + wm + t * 16 + l4;
        const float bi_lo = bias[m_lo];
        const float bi_hi = bias[m_lo + 8];
        float* c_lo = C + ((size_t)b * M + m_lo) * N + n0 + wn + l2;
        float* c_hi = c_lo + (size_t)8 * N;
#pragma unroll
        for (int nt = 0; nt < 8; nt++) {
            float2 v0 = {acc[t][nt][0] + bi_lo, acc[t][nt][1] + bi_lo};
            float2 v1 = {acc[t][nt][2] + bi_hi, acc[t][nt][3] + bi_hi};
            *(float2*)(c_lo + nt * 8) = v0;
            *(float2*)(c_hi + nt * 8) = v1;
        }
    }
}

// ---------------------------------------------------------------------------
// 2-product GEMM (proj): single-sync 3-stage ring.
// ---------------------------------------------------------------------------
#define P2_AL   10240
#define P2_BH   20480
#define P2_STG  29184

__device__ __forceinline__ void stage_load_2p(
    uint32_t sbase, const __half* gA_h, const __half* gA_l,
    const __half* gB_h, int K, int N, int kc, int tid)
{
    if (tid < 128) {
        const int op = tid >> 6;
        const int t  = tid & 63;
        const __half* g = ((op == 0) ? gA_h : gA_l) + kc * 32;
        const uint32_t sb = sbase + op * P2_AL;
#pragma unroll
        for (int it = 0; it < 8; it++) {
            int chunk = t + it * 64;
            int row = chunk >> 2, c = chunk & 3;
            CP_ASYNC16(sb + row * A_PITCH + c * 16, g + (size_t)row * K + c * 8);
        }
    } else {
        const int t = tid - 128;
        const __half* g = gB_h + (size_t)kc * 32 * N;
        const uint32_t sb = sbase + P2_BH;
#pragma unroll
        for (int it = 0; it < 4; it++) {
            int chunk = t + it * 128;
            int row = chunk >> 4, c = chunk & 15;
            CP_ASYNC16(sb + row * B_PITCH + c * 16, g + (size_t)row * N + c * 8);
        }
    }
}

__global__ __launch_bounds__(256, 2)
void gemm_f16_2p(const __half* __restrict__ Ah, const __half* __restrict__ Al,
                 const __half* __restrict__ Bmh,
                 const float* __restrict__ bias, float* __restrict__ C,
                 int M, int N, int K)
{
    extern __shared__ __align__(16) char smem[];
    const uint32_t sm0 = smem_u32(smem);

    const int tid  = threadIdx.x;
    const int wid  = tid >> 5;
    const int lane = tid & 31;
    const int n0 = blockIdx.x * 128;
    const int m0 = blockIdx.y * 128;
    const int b  = blockIdx.z;

    const int wm = (wid >> 1) * 32;
    const int wn = (wid & 1) * 64;

    const __half* gA_h = Ah + (size_t)m0 * K;
    const __half* gA_l = Al + (size_t)m0 * K;
    const __half* gB_h = Bmh + (size_t)b * K * N + n0;

    float acc[2][8][4];
#pragma unroll
    for (int t = 0; t < 2; t++)
#pragma unroll
        for (int nt = 0; nt < 8; nt++)
#pragma unroll
            for (int i = 0; i < 4; i++) acc[t][nt][i] = 0.f;

    const int nk = K / 32;

    stage_load_2p(sm0, gA_h, gA_l, gB_h, K, N, 0, tid);
    CP_COMMIT();
    if (nk > 1) {
        stage_load_2p(sm0 + P2_STG, gA_h, gA_l, gB_h, K, N, 1, tid);
        CP_COMMIT();
    }

    const int a_row = lane & 15;
    const int a_hi  = (lane >> 4) * 16;
    const int b_kr = (lane & 7) + ((lane >> 3) & 1) * 8;
    const int b_nc = (lane >> 4) * 8;

    for (int kc = 0; kc < nk; kc++) {
        if (kc + 1 < nk) CP_WAIT(1); else CP_WAIT(0);
        __syncthreads();

        if (kc + 2 < nk) {
            stage_load_2p(sm0 + ((kc + 2) % 3) * P2_STG,
                          gA_h, gA_l, gB_h, K, N, kc + 2, tid);
            CP_COMMIT();
        }

        const uint32_t sb  = sm0 + (kc % 3) * P2_STG;
        const uint32_t aAh = sb;
        const uint32_t aAl = sb + P2_AL;
        const uint32_t aBh = sb + P2_BH;

#pragma unroll
        for (int j = 0; j < 2; j++) {
            uint32_t ah[2][4], al[2][4];
#pragma unroll
            for (int t = 0; t < 2; t++) {
                uint32_t off = (uint32_t)(wm + t * 16 + a_row) * A_PITCH + j * 32 + a_hi;
                ldsm4(aAh + off, ah[t]);
                ldsm4(aAl + off, al[t]);
            }
            uint32_t bh[4][4];
#pragma unroll
            for (int p = 0; p < 4; p++) {
                uint32_t off = (uint32_t)(j * 16 + b_kr) * B_PITCH +
                               (uint32_t)(wn + p * 16 + b_nc) * 2;
                ldsm4t(aBh + off, bh[p]);
            }
#pragma unroll
            for (int t = 0; t < 2; t++)
#pragma unroll
                for (int nt = 0; nt < 8; nt++)
                    mma_f16(acc[t][nt], ah[t], &bh[nt >> 1][(nt & 1) * 2]);
#pragma unroll
            for (int t = 0; t < 2; t++)
#pragma unroll
                for (int nt = 0; nt < 8; nt++)
                    mma_f16(acc[t][nt], al[t], &bh[nt >> 1][(nt & 1) * 2]);
        }
    }

    const int l4 = lane >> 2;
    const int l2 = (lane & 3) * 2;
#pragma unroll
    for (int t = 0; t < 2; t++) {
        const int m_lo = m0 + wm + t * 16 + l4;
        const float bi_lo = bias[m_lo];
        const float bi_hi = bias[m_lo + 8];
        float* c_lo = C + ((size_t)b * M + m_lo) * N + n0 + wn + l2;
        float* c_hi = c_lo + (size_t)8 * N;
#pragma unroll
        for (int nt = 0; nt < 8; nt++) {
            float2 v0 = {acc[t][nt][0] + bi_lo, acc[t][nt][1] + bi_lo};
            float2 v1 = {acc[t][nt][2] + bi_hi, acc[t][nt][3] + bi_hi};
            *(float2*)(c_lo + nt * 8) = v0;
            *(float2*)(c_hi + nt * 8) = v1;
        }
    }
}

// ---------------------------------------------------------------------------
__global__ void wsplit_kernel(const float* __restrict__ w,
                              __half* __restrict__ hi,
                              __half* __restrict__ lo, int n)
{
    int i = blockIdx.x * 256 + threadIdx.x;
    if (i < n) {
        float v = w[i];
        __half h = __float2half_rn(v);
        hi[i] = h;
        lo[i] = __float2half_rn(v - __half2float(h));
    }
}

// ---------------------------------------------------------------------------
// dwpw (unchanged from R9/R10)
// ---------------------------------------------------------------------------
#define OFF_SIN   0
#define OFF_D3    17408
#define OFF_D5    41984
#define OFF_W5P   66560
#define OFF_W3P   71360
#define OFF_PWP   73088
#define OFF_PWB   82304
#define OFF_DB5   82688
#define OFF_DB3   82880
#define OFF_STASH 83072
#define DW_SMEM   91264

__global__ __launch_bounds__(256, 2)
void dwpw_kernel(const float* __restrict__ qkv,
                 const float* __restrict__ dw3_w, const float* __restrict__ dw3_b,
                 const float* __restrict__ pw3_w, const float* __restrict__ pw3_b,
                 const float* __restrict__ dw5_w, const float* __restrict__ dw5_b,
                 const float* __restrict__ pw5_w, const float* __restrict__ pw5_b,
                 float* __restrict__ s3q, float* __restrict__ s5q,
                 float* __restrict__ vkg)
{
    extern __shared__ __align__(16) char sm[];
    float* sin_  = (float*)(sm + OFF_SIN);
    float* d3s   = (float*)(sm + OFF_D3);
    float* d5s   = (float*)(sm + OFF_D5);
    ull*   kvq   = (ull*)(sm + OFF_D3);
    float* red   = (float*)(sm + OFF_PWP);
    float* stash = (float*)(sm + OFF_STASH);
    ull*   w5p   = (ull*)(sm + OFF_W5P);
    ull*   w3p   = (ull*)(sm + OFF_W3P);
    ull*   pwp   = (ull*)(sm + OFF_PWP);
    ull*   pwb   = (ull*)(sm + OFF_PWB);
    ull*   db5   = (ull*)(sm + OFF_DB5);
    ull*   db3   = (ull*)(sm + OFF_DB3);

    const int ytile = blockIdx.x;
    const int g     = blockIdx.y;
    const int b     = blockIdx.z;
    const int tid   = threadIdx.x;
    const int y0    = ytile * 4;

    for (int i = tid; i < 600; i += 256) {
        float w = dw5_w[(g * 24 + i / 25) * 25 + i % 25];
        w5p[i] = pk2(w, w);
    }
    for (int i = tid; i < 216; i += 256) {
        float w = dw3_w[(g * 24 + i / 9) * 9 + i % 9];
        w3p[i] = pk2(w, w);
    }
    for (int i = tid; i < 576; i += 256) {
        float a = pw3_w[g * 576 + i];
        float c = pw5_w[g * 576 + i];
        pwp[i] = pk2(a, a);
        pwp[576 + i] = pk2(c, c);
    }
    if (tid < 24) {
        float b3 = pw3_b[g * 24 + tid], b5 = pw5_b[g * 24 + tid];
        pwb[tid] = pk2(b3, b3);
        pwb[24 + tid] = pk2(b5, b5);
        float d3b = dw3_b[g * 24 + tid], d5b = dw5_b[g * 24 + tid];
        db3[tid] = pk2(d3b, d3b);
        db5[tid] = pk2(d5b, d5b);
    }

    const int c  = tid >> 5;
    const int t  = tid & 31;
    const int py = t >> 3;
    const int xo = (t & 7) * 8;

    for (int grp = 0; grp < 3; grp++) {
        __syncthreads();
        const int icb = grp * 8;
        const float* src = qkv + ((size_t)b * C3 + g * 24 + icb) * NPIX;
        for (int i = tid; i < 8 * 8 * 68; i += 256) {
            int xx = i % 68;
            int r  = (i / 68) & 7;
            int cc = i / (68 * 8);
            int yy = y0 - 2 + r;
            int xg = xx - 2;
            float v = 0.f;
            if ((unsigned)yy < 64u && (unsigned)xg < 64u)
                v = src[(size_t)cc * NPIX + yy * WIDTH + xg];
            sin_[(cc * 8 + r) * 68 + xx] = v;
        }
        __syncthreads();

        const int ch = icb + c;
        ull acc5[4], acc3[4];
        {
            ull b5v = db5[ch], b3v = db3[ch];
#pragma unroll
            for (int j = 0; j < 4; j++) { acc5[j] = b5v; acc3[j] = b3v; }
        }
#pragma unroll
        for (int dy = 0; dy < 5; dy++) {
            const ull* row = (const ull*)&sin_[(c * 8 + py + dy) * 68 + xo];
            ull r0 = row[0], r1 = row[1], r2 = row[2],
                r3 = row[3], r4 = row[4], r5 = row[5];
            ull m0 = pk2(f2hi(r0), f2lo(r1));
            ull m1 = pk2(f2hi(r1), f2lo(r2));
            ull m2 = pk2(f2hi(r2), f2lo(r3));
            ull m3 = pk2(f2hi(r3), f2lo(r4));
            ull m4 = pk2(f2hi(r4), f2lo(r5));
            const ull* w5r = &w5p[ch * 25 + dy * 5];
            ull w0 = w5r[0], w1 = w5r[1], w2 = w5r[2], w3v = w5r[3], w4 = w5r[4];

            ffma2(acc5[0], w0, r0); ffma2(acc5[0], w1, m0); ffma2(acc5[0], w2, r1);
            ffma2(acc5[0], w3v, m1); ffma2(acc5[0], w4, r2);
            ffma2(acc5[1], w0, r1); ffma2(acc5[1], w1, m1); ffma2(acc5[1], w2, r2);
            ffma2(acc5[1], w3v, m2); ffma2(acc5[1], w4, r3);
            ffma2(acc5[2], w0, r2); ffma2(acc5[2], w1, m2); ffma2(acc5[2], w2, r3);
            ffma2(acc5[2], w3v, m3); ffma2(acc5[2], w4, r4);
            ffma2(acc5[3], w0, r3); ffma2(acc5[3], w1, m3); ffma2(acc5[3], w2, r4);
            ffma2(acc5[3], w3v, m4); ffma2(acc5[3], w4, r5);

            if (dy >= 1 && dy <= 3) {
                const ull* w3r = &w3p[ch * 9 + (dy - 1) * 3];
                ull u0 = w3r[0], u1 = w3r[1], u2 = w3r[2];
                ffma2(acc3[0], u0, m0); ffma2(acc3[0], u1, r1); ffma2(acc3[0], u2, m1);
                ffma2(acc3[1], u0, m1); ffma2(acc3[1], u1, r2); ffma2(acc3[1], u2, m2);
                ffma2(acc3[2], u0, m2); ffma2(acc3[2], u1, r3); ffma2(acc3[2], u2, m3);
                ffma2(acc3[3], u0, m3); ffma2(acc3[3], u1, r4); ffma2(acc3[3], u2, m4);
            }
        }
        const int ppb = py * 32 + (xo >> 1);
#pragma unroll
        for (int j = 0; j < 4; j++) {
            *(ull*)&d3s[ch * 256 + (ppb + j) * 2] = acc3[j];
            *(ull*)&d5s[ch * 256 + (ppb + j) * 2] = acc5[j];
        }

        if (grp == 1) {
            for (int i = tid; i < 8 * 256; i += 256) {
                int cc = i >> 8, px = i & 255;
                stash[i] = sin_[(cc * 8 + 2 + (px >> 6)) * 68 + 2 + (px & 63)];
            }
        }

        if (grp == 2) {
            const int px = tid;
            const int vy = px >> 6;
            const int vx = px & 63;
            float kk[8], vv[8];
#pragma unroll
            for (int e = 0; e < 8; e++)
                kk[e] = fmaxf(stash[e * 256 + px], 0.f);
#pragma unroll
            for (int d = 0; d < 8; d++)
                vv[d] = sin_[(d * 8 + 2 + vy) * 68 + 2 + vx];

            float vacc[9][8];
#pragma unroll
            for (int d = 0; d < 8; d++)
#pragma unroll
                for (int e = 0; e < 8; e++)
                    vacc[d][e] = vv[d] * kk[e];
#pragma unroll
            for (int e = 0; e < 8; e++) vacc[8][e] = kk[e];

#pragma unroll
            for (int d = 0; d < 9; d++)
#pragma unroll
                for (int e = 0; e < 8; e++) {
                    float v = vacc[d][e];
                    v += __shfl_xor_sync(0xffffffffu, v, 16);
                    v += __shfl_xor_sync(0xffffffffu, v, 8);
                    v += __shfl_xor_sync(0xffffffffu, v, 4);
                    v += __shfl_xor_sync(0xffffffffu, v, 2);
                    v += __shfl_xor_sync(0xffffffffu, v, 1);
                    vacc[d][e] = v;
                }
            __syncthreads();
            const int w    = tid >> 5;
            const int lane = tid & 31;
            if (lane == 0) {
#pragma unroll
                for (int d = 0; d < 9; d++)
#pragma unroll
                    for (int e = 0; e < 8; e++)
                        stash[w * 72 + d * 8 + e] = vacc[d][e];
            }
            __syncthreads();
            if (tid < 72) {
                float s = 0.f;
#pragma unroll
                for (int j = 0; j < 8; j++) s += stash[j * 72 + tid];
                atomicAdd(&vkg[((size_t)b * 96 + g) * 72 + tid], s);
            }
        }
    }
    __syncthreads();

    const int conv = tid >> 7;
    const int tt   = tid & 127;
    const int og   = tt >> 5;
    const int pg   = tt & 31;
    const float* dsrc = conv ? d5s : d3s;
    const ull* wp = &pwp[conv * 576];
    const ull* bb = &pwb[conv * 24];
    float* qout = conv ? s5q : s3q;

    ull acc[6][4];
#pragma unroll
    for (int j = 0; j < 6; j++) {
        ull bv = bb[og * 6 + j];
#pragma unroll
        for (int i = 0; i < 4; i++) acc[j][i] = bv;
    }

#pragma unroll
    for (int ic = 0; ic < 24; ic++) {
        const ulonglong2 dA = *(const ulonglong2*)&dsrc[ic * 256 + pg * 8];
        const ulonglong2 dB = *(const ulonglong2*)&dsrc[ic * 256 + pg * 8 + 4];
        ull dv[4] = {dA.x, dA.y, dB.x, dB.y};
#pragma unroll
        for (int j = 0; j < 6; j++) {
            ull wv = wp[(og * 6 + j) * 24 + ic];
#pragma unroll
            for (int i = 0; i < 4; i++)
                ffma2(acc[j][i], wv, dv[i]);
        }
    }
    __syncthreads();

    {
        const int pair0 = pg * 4;
        const int by = y0 + (pair0 >> 5);
        const int bx = (pair0 & 31) * 2;
        const size_t qbase = (((size_t)b * 32 + g) * 8) * NPIX + by * WIDTH + bx;
#pragma unroll
        for (int j = 0; j < 6; j++) {
            const int o = og * 6 + j;
            if (o < 8) {
#pragma unroll
                for (int i = 0; i < 4; i++)
                    *(float2*)&qout[qbase + (size_t)o * NPIX + i * 2] =
                        make_float2(f2lo(acc[j][i]), f2hi(acc[j][i]));
            } else {
#pragma unroll
                for (int i = 0; i < 4; i++)
                    kvq[(conv * 16 + (o - 8)) * 128 + pair0 + i] = acc[j][i];
            }
        }
    }
    __syncthreads();

    {
        const int w    = tid >> 5;
        const int lane = tid & 31;
        const int cv   = w >> 2;
        const int sub  = w & 3;
        const int pair = sub * 32 + lane;

        ull kvv[16];
#pragma unroll
        for (int ch = 0; ch < 16; ch++)
            kvv[ch] = kvq[(cv * 16 + ch) * 128 + pair];

        float acc2[9][8];
#pragma unroll
        for (int d = 0; d < 9; d++)
#pragma unroll
            for (int e = 0; e < 8; e++) acc2[d][e] = 0.f;

#pragma unroll
        for (int hx = 0; hx < 2; hx++) {
            float kk[8], vv[8];
#pragma unroll
            for (int e = 0; e < 8; e++)
                kk[e] = fmaxf(hx ? f2hi(kvv[e]) : f2lo(kvv[e]), 0.f);
#pragma unroll
            for (int d = 0; d < 8; d++)
                vv[d] = hx ? f2hi(kvv[8 + d]) : f2lo(kvv[8 + d]);
#pragma unroll
            for (int d = 0; d < 8; d++)
#pragma unroll
                for (int e = 0; e < 8; e++)
                    acc2[d][e] += vv[d] * kk[e];
#pragma unroll
            for (int e = 0; e < 8; e++)
                acc2[8][e] += kk[e];
        }

#pragma unroll
        for (int d = 0; d < 9; d++)
#pragma unroll
            for (int e = 0; e < 8; e++) {
                float v = acc2[d][e];
                v += __shfl_xor_sync(0xffffffffu, v, 16);
                v += __shfl_xor_sync(0xffffffffu, v, 8);
                v += __shfl_xor_sync(0xffffffffu, v, 4);
                acc2[d][e] = v;
            }
        if (lane < 4) {
            float* rp = &red[((cv * 16) + sub * 4 + lane) * 72];
#pragma unroll
            for (int d = 0; d < 9; d++)
#pragma unroll
                for (int e = 0; e < 8; e++)
                    rp[d * 8 + e] = acc2[d][e];
        }
    }
    __syncthreads();

    if (tid < 144) {
        const int cv  = tid / 72;
        const int idx = tid % 72;
        float s = 0.f;
#pragma unroll
        for (int j = 0; j < 16; j++)
            s += red[(cv * 16 + j) * 72 + idx];
        atomicAdd(&vkg[((size_t)b * 96 + 32 + cv * 32 + g) * 72 + idx], s);
    }
}

// ---------------------------------------------------------------------------
// attention normalize: 4 CTAs/SM, packed f32x2, z=2 x 4 iterations.
// ---------------------------------------------------------------------------
__global__ __launch_bounds__(256, 4)
void att_kernel(const float* __restrict__ qkv, const float* __restrict__ s3q,
                const float* __restrict__ s5q, const float* __restrict__ vk,
                __half* __restrict__ atth)
{
    const int hh = blockIdx.x;
    const int b  = blockIdx.y;
    const int n0 = blockIdx.z * (NPIX / 2);
    const int src_id = hh >> 5;
    const int g      = hh & 31;
    const float* base;
    if (src_id == 0)      base = qkv + ((size_t)b * C3 + g * 24) * NPIX;
    else if (src_id == 1) base = s3q + (((size_t)b * 32 + g) * 8) * NPIX;
    else                  base = s5q + (((size_t)b * 32 + g) * 8) * NPIX;

    __shared__ ull vsp[72];
    const int tid = threadIdx.x;
    if (tid < 72) {
        float v = vk[((size_t)b * 96 + hh) * 72 + tid];
        vsp[tid] = pk2(v, v);
    }
    __syncthreads();

    __half* oh = atth + ((size_t)b * C3 + hh * 8) * NPIX;

#pragma unroll
    for (int it = 0; it < 4; it++) {
        const int n = n0 + (tid + it * 256) * 2;
        ull qp[8];
#pragma unroll
        for (int e = 0; e < 8; e++) {
            ull raw = *(const ull*)(base + (size_t)e * NPIX + n);
            qp[e] = pk2(fmaxf(f2lo(raw), 0.f), fmaxf(f2hi(raw), 0.f));
        }
        ull den = pk2(1e-15f, 1e-15f);
#pragma unroll
        for (int e = 0; e < 8; e++) ffma2(den, vsp[64 + e], qp[e]);
        const float rd0 = __fdividef(1.f, f2lo(den));
        const float rd1 = __fdividef(1.f, f2hi(den));
#pragma unroll
        for (int d = 0; d < 8; d++) {
            ull num = 0ull;
#pragma unroll
            for (int e = 0; e < 8; e++) ffma2(num, vsp[d * 8 + e], qp[e]);
            __half2 hp;
            hp.x = __float2half_rn(f2lo(num) * rd0);
            hp.y = __float2half_rn(f2hi(num) * rd1);
            *(__half2*)(oh + (size_t)d * NPIX + n) = hp;
        }
    }
}

// ---------------------------------------------------------------------------
struct PipeArgs {
    const float *x, *qkv_b, *dw3_w, *dw3_b, *pw3_w, *pw3_b;
    const float *dw5_w, *dw5_b, *pw5_w, *pw5_b, *proj_b;
    __half *xth, *xtl, *ath, *wqh, *wql, *wph, *wpl;
    float *qkv, *s3q, *s5q, *vkb, *out;
};

static void enqueue_part(cudaStream_t st, const PipeArgs& a, int b0, int nb,
                         cudaEvent_t evW)
{
    const size_t offX = (size_t)b0 * 256 * NPIX;
    const size_t offQ = (size_t)b0 * C3 * NPIX;
    const size_t off3 = (size_t)b0 * 32 * 8 * NPIX;
    const size_t offV = (size_t)b0 * 96 * 72;

    // x split does not depend on weights; runs before the weight barrier
    wsplit_kernel<<<(nb * 256 * NPIX + 255) / 256, 256, 0, st>>>(
        a.x + offX, a.xth + offX, a.xtl + offX, nb * 256 * NPIX);

    cudaStreamWaitEvent(st, evW, 0);   // weights ready before qkv GEMM

    gemm_f16<<<dim3(NPIX / 128, C3 / 128, nb), 256, 3 * STG2, st>>>(
        a.wqh, a.wql, a.xth + offX, a.xtl + offX, a.qkv_b, a.qkv + offQ,
        C3, NPIX, 256);

    dwpw_kernel<<<dim3(16, 32, nb), 256, DW_SMEM, st>>>(
        a.qkv + offQ, a.dw3_w, a.dw3_b, a.pw3_w, a.pw3_b,
        a.dw5_w, a.dw5_b, a.pw5_w, a.pw5_b,
        a.s3q + off3, a.s5q + off3, a.vkb + offV);

    att_kernel<<<dim3(96, nb, 2), 256, 0, st>>>(
        a.qkv + offQ, a.s3q + off3, a.s5q + off3, a.vkb + offV, a.ath + offQ);

    gemm_f16_2p<<<dim3(NPIX / 128, 256 / 128, nb), 256, 3 * P2_STG, st>>>(
        a.wph, a.wpl, a.ath + offQ, a.proj_b, a.out + (size_t)b0 * 256 * NPIX,
        256, NPIX, C3);
}

extern "C" void kernel_launch(void* const* d_in, const int* in_sizes, int n_in,
                              void* d_out, int out_size)
{
    PipeArgs a;
    a.x      = (const float*)d_in[0];
    const float* qkv_w = (const float*)d_in[1];
    a.qkv_b  = (const float*)d_in[2];
    a.dw3_w  = (const float*)d_in[3];
    a.dw3_b  = (const float*)d_in[4];
    a.pw3_w  = (const float*)d_in[5];
    a.pw3_b  = (const float*)d_in[6];
    a.dw5_w  = (const float*)d_in[7];
    a.dw5_b  = (const float*)d_in[8];
    a.pw5_w  = (const float*)d_in[9];
    a.pw5_b  = (const float*)d_in[10];
    const float* proj_w = (const float*)d_in[11];
    a.proj_b = (const float*)d_in[12];
    a.out    = (float*)d_out;

    void *p;
    cudaGetSymbolAddress(&p, g_qkv);  a.qkv = (float*)p;
    cudaGetSymbolAddress(&p, g_s3q);  a.s3q = (float*)p;
    cudaGetSymbolAddress(&p, g_s5q);  a.s5q = (float*)p;
    cudaGetSymbolAddress(&p, g_vk);   a.vkb = (float*)p;
    cudaGetSymbolAddress(&p, g_xt_h); a.xth = (__half*)p;
    cudaGetSymbolAddress(&p, g_xt_l); a.xtl = (__half*)p;
    cudaGetSymbolAddress(&p, g_at_h); a.ath = (__half*)p;
    cudaGetSymbolAddress(&p, g_wq_h); a.wqh = (__half*)p;
    cudaGetSymbolAddress(&p, g_wq_l); a.wql = (__half*)p;
    cudaGetSymbolAddress(&p, g_wp_h); a.wph = (__half*)p;
    cudaGetSymbolAddress(&p, g_wp_l); a.wpl = (__half*)p;

    static bool inited = false;
    static cudaStream_t s[3];
    static cudaEvent_t evW, evF, evJ[3];
    if (!inited) {
        for (int i = 0; i < 3; i++) {
            cudaStreamCreateWithFlags(&s[i], cudaStreamNonBlocking);
            cudaEventCreateWithFlags(&evJ[i], cudaEventDisableTiming);
        }
        cudaEventCreateWithFlags(&evW, cudaEventDisableTiming);
        cudaEventCreateWithFlags(&evF, cudaEventDisableTiming);
        cudaFuncSetAttribute(gemm_f16,
            cudaFuncAttributeMaxDynamicSharedMemorySize, 3 * STG2);
        cudaFuncSetAttribute(gemm_f16_2p,
            cudaFuncAttributeMaxDynamicSharedMemorySize, 3 * P2_STG);
        cudaFuncSetAttribute(dwpw_kernel,
            cudaFuncAttributeMaxDynamicSharedMemorySize, DW_SMEM);
        inited = true;
    }

    // main stream head: vk zero + weight splits
    cudaMemsetAsync(a.vkb, 0, (size_t)BATCH * 96 * 72 * sizeof(float), 0);
    cudaEventRecord(evF, 0);                   // fork point (pre-weights)
    for (int i = 0; i < 3; i++) cudaStreamWaitEvent(s[i], evF, 0);

    wsplit_kernel<<<(C3 * 256 + 255) / 256, 256>>>(qkv_w, a.wqh, a.wql, C3 * 256);
    wsplit_kernel<<<(256 * C3 + 255) / 256, 256>>>(proj_w, a.wph, a.wpl, 256 * C3);
    cudaEventRecord(evW, 0);                   // weights ready

    enqueue_part(0,    a, 0, 2, evW);
    enqueue_part(s[0], a, 2, 2, evW);
    enqueue_part(s[1], a, 4, 2, evW);
    enqueue_part(s[2], a, 6, 2, evW);

    for (int i = 0; i < 3; i++) {
        cudaEventRecord(evJ[i], s[i]);
        cudaStreamWaitEvent(0, evJ[i], 0);
    }
}

// round 12
// speedup vs baseline: 1.0054x; 1.0054x over previous
#include <cuda_runtime.h>
#include <cuda_fp16.h>
#include <cstdint>

// ---------------------------------------------------------------------------
// LiteMLA on sm_103a.
// Four-stream batch-split pipeline (2 batches each) to overlap stage tails.
// qkv GEMM: fp16 hi/lo x hi/lo, 3 mma products, 3-stage cp.async ring.
// proj GEMM: weights hi/lo x att fp16, 2 products, 3-stage ring.
// dwpw: depthwise f32x2 -> register-tiled pointwise -> fused vk (all heads).
// (R10 configuration restored; att z-split 4->2.)
// ---------------------------------------------------------------------------

#define BATCH 8
#define C3 768
#define NPIX 4096
#define WIDTH 64

__device__ float g_qkv[(size_t)BATCH * C3 * NPIX];
__device__ float g_s3q[(size_t)BATCH * 32 * 8 * NPIX];
__device__ float g_s5q[(size_t)BATCH * 32 * 8 * NPIX];
__device__ float g_vk [(size_t)BATCH * 96 * 72];

__device__ __half g_xt_h [(size_t)BATCH * 256 * NPIX];
__device__ __half g_xt_l [(size_t)BATCH * 256 * NPIX];
__device__ __half g_at_h [(size_t)BATCH * C3 * NPIX];
__device__ __half g_wq_h [C3 * 256];
__device__ __half g_wq_l [C3 * 256];
__device__ __half g_wp_h [256 * C3];
__device__ __half g_wp_l [256 * C3];

// ---------------------------------------------------------------------------
typedef unsigned long long ull;

__device__ __forceinline__ uint32_t smem_u32(const void* p) {
    uint32_t a;
    asm("{ .reg .u64 t; cvta.to.shared.u64 t, %1; cvt.u32.u64 %0, t; }"
        : "=r"(a) : "l"(p));
    return a;
}
__device__ __forceinline__ ull pk2(float lo, float hi) {
    ull r;
    asm("mov.b64 %0, {%1, %2};" : "=l"(r)
        : "r"(__float_as_uint(lo)), "r"(__float_as_uint(hi)));
    return r;
}
__device__ __forceinline__ void ffma2(ull& d, ull a, ull b) {
    asm("fma.rn.f32x2 %0, %1, %2, %0;" : "+l"(d) : "l"(a), "l"(b));
}
__device__ __forceinline__ float f2lo(ull v) {
    return __uint_as_float((unsigned)(v & 0xffffffffull));
}
__device__ __forceinline__ float f2hi(ull v) {
    return __uint_as_float((unsigned)(v >> 32));
}

#define CP_ASYNC16(s, g) \
    asm volatile("cp.async.cg.shared.global [%0], [%1], 16;" :: "r"(s), "l"(g))
#define CP_COMMIT() asm volatile("cp.async.commit_group;" ::: "memory")
#define CP_WAIT(n)  asm volatile("cp.async.wait_group %0;" :: "n"(n) : "memory")

__device__ __forceinline__ void ldsm4(uint32_t addr, uint32_t* r) {
    asm volatile("ldmatrix.sync.aligned.m8n8.x4.shared.b16 {%0,%1,%2,%3}, [%4];"
                 : "=r"(r[0]), "=r"(r[1]), "=r"(r[2]), "=r"(r[3]) : "r"(addr));
}
__device__ __forceinline__ void ldsm4t(uint32_t addr, uint32_t* r) {
    asm volatile("ldmatrix.sync.aligned.m8n8.x4.trans.shared.b16 {%0,%1,%2,%3}, [%4];"
                 : "=r"(r[0]), "=r"(r[1]), "=r"(r[2]), "=r"(r[3]) : "r"(addr));
}
__device__ __forceinline__ void mma_f16(float* d, const uint32_t* a,
                                        const uint32_t* b) {
    asm volatile(
        "mma.sync.aligned.m16n8k16.row.col.f32.f16.f16.f32 "
        "{%0,%1,%2,%3}, {%4,%5,%6,%7}, {%8,%9}, {%0,%1,%2,%3};"
        : "+f"(d[0]), "+f"(d[1]), "+f"(d[2]), "+f"(d[3])
        : "r"(a[0]), "r"(a[1]), "r"(a[2]), "r"(a[3]), "r"(b[0]), "r"(b[1]));
}

#define A_PITCH 80
#define B_PITCH 272

// ---------------------------------------------------------------------------
// 3-product GEMM (qkv): C[b] = (Ah+Al)(M,K) @ (Bh+Bl)(b,K,N) + bias
// 3-stage cp.async ring, 2 CTAs/SM.  (R10 version)
// ---------------------------------------------------------------------------
#define OFF_AL  10240
#define OFF_BH  20480
#define OFF_BL  29184
#define STG2    37888

__device__ __forceinline__ void stage_load(
    uint32_t sbase, const __half* gA_h, const __half* gA_l,
    const __half* gB_h, const __half* gB_l, int K, int N, int kc, int tid)
{
    const int op = tid >> 6;
    const int t  = tid & 63;
    if (op < 2) {
        const __half* g = ((op == 0) ? gA_h : gA_l) + kc * 32;
        const uint32_t sb = sbase + op * OFF_AL;
#pragma unroll
        for (int it = 0; it < 8; it++) {
            int chunk = t + it * 64;
            int row = chunk >> 2, c = chunk & 3;
            CP_ASYNC16(sb + row * A_PITCH + c * 16, g + (size_t)row * K + c * 8);
        }
    } else {
        const __half* g = ((op == 2) ? gB_h : gB_l) + (size_t)kc * 32 * N;
        const uint32_t sb = sbase + ((op == 2) ? OFF_BH : OFF_BL);
#pragma unroll
        for (int it = 0; it < 8; it++) {
            int chunk = t + it * 64;
            int row = chunk >> 4, c = chunk & 15;
            CP_ASYNC16(sb + row * B_PITCH + c * 16, g + (size_t)row * N + c * 8);
        }
    }
}

__global__ __launch_bounds__(256, 2)
void gemm_f16(const __half* __restrict__ Ah, const __half* __restrict__ Al,
              const __half* __restrict__ Bmh, const __half* __restrict__ Bml,
              const float* __restrict__ bias, float* __restrict__ C,
              int M, int N, int K)
{
    extern __shared__ __align__(16) char smem[];
    const uint32_t sm0 = smem_u32(smem);

    const int tid  = threadIdx.x;
    const int wid  = tid >> 5;
    const int lane = tid & 31;
    const int n0 = blockIdx.x * 128;
    const int m0 = blockIdx.y * 128;
    const int b  = blockIdx.z;

    const int wm = (wid >> 1) * 32;
    const int wn = (wid & 1) * 64;

    const __half* gA_h = Ah + (size_t)m0 * K;
    const __half* gA_l = Al + (size_t)m0 * K;
    const __half* gB_h = Bmh + (size_t)b * K * N + n0;
    const __half* gB_l = Bml + (size_t)b * K * N + n0;

    float acc[2][8][4];
#pragma unroll
    for (int t = 0; t < 2; t++)
#pragma unroll
        for (int nt = 0; nt < 8; nt++)
#pragma unroll
            for (int i = 0; i < 4; i++) acc[t][nt][i] = 0.f;

    const int nk = K / 32;

    stage_load(sm0, gA_h, gA_l, gB_h, gB_l, K, N, 0, tid);
    CP_COMMIT();
    if (nk > 1) {
        stage_load(sm0 + STG2, gA_h, gA_l, gB_h, gB_l, K, N, 1, tid);
        CP_COMMIT();
    }

    const int a_row = lane & 15;
    const int a_hi  = (lane >> 4) * 16;
    const int b_kr = (lane & 7) + ((lane >> 3) & 1) * 8;
    const int b_nc = (lane >> 4) * 8;

    for (int kc = 0; kc < nk; kc++) {
        if (kc + 2 < nk) {
            stage_load(sm0 + ((kc + 2) % 3) * STG2,
                       gA_h, gA_l, gB_h, gB_l, K, N, kc + 2, tid);
            CP_COMMIT();
        }
        if (kc + 2 < nk)      CP_WAIT(2);
        else if (kc + 1 < nk) CP_WAIT(1);
        else                  CP_WAIT(0);
        __syncthreads();

        const uint32_t sb  = sm0 + (kc % 3) * STG2;
        const uint32_t aAh = sb;
        const uint32_t aAl = sb + OFF_AL;
        const uint32_t aBh = sb + OFF_BH;
        const uint32_t aBl = sb + OFF_BL;

#pragma unroll
        for (int j = 0; j < 2; j++) {
            uint32_t ah[2][4], al[2][4];
#pragma unroll
            for (int t = 0; t < 2; t++) {
                uint32_t off = (uint32_t)(wm + t * 16 + a_row) * A_PITCH + j * 32 + a_hi;
                ldsm4(aAh + off, ah[t]);
                ldsm4(aAl + off, al[t]);
            }
            uint32_t bh[4][4], bl[4][4];
#pragma unroll
            for (int p = 0; p < 4; p++) {
                uint32_t off = (uint32_t)(j * 16 + b_kr) * B_PITCH +
                               (uint32_t)(wn + p * 16 + b_nc) * 2;
                ldsm4t(aBh + off, bh[p]);
                ldsm4t(aBl + off, bl[p]);
            }
#pragma unroll
            for (int t = 0; t < 2; t++)
#pragma unroll
                for (int nt = 0; nt < 8; nt++) {
                    const uint32_t* bhp = &bh[nt >> 1][(nt & 1) * 2];
                    const uint32_t* blp = &bl[nt >> 1][(nt & 1) * 2];
                    mma_f16(acc[t][nt], ah[t], bhp);
                    mma_f16(acc[t][nt], ah[t], blp);
                    mma_f16(acc[t][nt], al[t], bhp);
                }
        }
        __syncthreads();
    }

    const int l4 = lane >> 2;
    const int l2 = (lane & 3) * 2;
#pragma unroll
    for (int t = 0; t < 2; t++) {
        const int m_lo = m0 + wm + t * 16 + l4;
        const float bi_lo = bias[m_lo];
        const float bi_hi = bias[m_lo + 8];
        float* c_lo = C + ((size_t)b * M + m_lo) * N + n0 + wn + l2;
        float* c_hi = c_lo + (size_t)8 * N;
#pragma unroll
        for (int nt = 0; nt < 8; nt++) {
            float2 v0 = {acc[t][nt][0] + bi_lo, acc[t][nt][1] + bi_lo};
            float2 v1 = {acc[t][nt][2] + bi_hi, acc[t][nt][3] + bi_hi};
            *(float2*)(c_lo + nt * 8) = v0;
            *(float2*)(c_hi + nt * 8) = v1;
        }
    }
}

// ---------------------------------------------------------------------------
// 2-product GEMM (proj): 3-stage ring.  (R10 version)
// ---------------------------------------------------------------------------
#define P2_AL   10240
#define P2_BH   20480
#define P2_STG  29184

__device__ __forceinline__ void stage_load_2p(
    uint32_t sbase, const __half* gA_h, const __half* gA_l,
    const __half* gB_h, int K, int N, int kc, int tid)
{
    if (tid < 128) {
        const int op = tid >> 6;
        const int t  = tid & 63;
        const __half* g = ((op == 0) ? gA_h : gA_l) + kc * 32;
        const uint32_t sb = sbase + op * P2_AL;
#pragma unroll
        for (int it = 0; it < 8; it++) {
            int chunk = t + it * 64;
            int row = chunk >> 2, c = chunk & 3;
            CP_ASYNC16(sb + row * A_PITCH + c * 16, g + (size_t)row * K + c * 8);
        }
    } else {
        const int t = tid - 128;
        const __half* g = gB_h + (size_t)kc * 32 * N;
        const uint32_t sb = sbase + P2_BH;
#pragma unroll
        for (int it = 0; it < 4; it++) {
            int chunk = t + it * 128;
            int row = chunk >> 4, c = chunk & 15;
            CP_ASYNC16(sb + row * B_PITCH + c * 16, g + (size_t)row * N + c * 8);
        }
    }
}

__global__ __launch_bounds__(256, 2)
void gemm_f16_2p(const __half* __restrict__ Ah, const __half* __restrict__ Al,
                 const __half* __restrict__ Bmh,
                 const float* __restrict__ bias, float* __restrict__ C,
                 int M, int N, int K)
{
    extern __shared__ __align__(16) char smem[];
    const uint32_t sm0 = smem_u32(smem);

    const int tid  = threadIdx.x;
    const int wid  = tid >> 5;
    const int lane = tid & 31;
    const int n0 = blockIdx.x * 128;
    const int m0 = blockIdx.y * 128;
    const int b  = blockIdx.z;

    const int wm = (wid >> 1) * 32;
    const int wn = (wid & 1) * 64;

    const __half* gA_h = Ah + (size_t)m0 * K;
    const __half* gA_l = Al + (size_t)m0 * K;
    const __half* gB_h = Bmh + (size_t)b * K * N + n0;

    float acc[2][8][4];
#pragma unroll
    for (int t = 0; t < 2; t++)
#pragma unroll
        for (int nt = 0; nt < 8; nt++)
#pragma unroll
            for (int i = 0; i < 4; i++) acc[t][nt][i] = 0.f;

    const int nk = K / 32;

    stage_load_2p(sm0, gA_h, gA_l, gB_h, K, N, 0, tid);
    CP_COMMIT();
    if (nk > 1) {
        stage_load_2p(sm0 + P2_STG, gA_h, gA_l, gB_h, K, N, 1, tid);
        CP_COMMIT();
    }

    const int a_row = lane & 15;
    const int a_hi  = (lane >> 4) * 16;
    const int b_kr = (lane & 7) + ((lane >> 3) & 1) * 8;
    const int b_nc = (lane >> 4) * 8;

    for (int kc = 0; kc < nk; kc++) {
        if (kc + 2 < nk) {
            stage_load_2p(sm0 + ((kc + 2) % 3) * P2_STG,
                          gA_h, gA_l, gB_h, K, N, kc + 2, tid);
            CP_COMMIT();
        }
        if (kc + 2 < nk)      CP_WAIT(2);
        else if (kc + 1 < nk) CP_WAIT(1);
        else                  CP_WAIT(0);
        __syncthreads();

        const uint32_t sb  = sm0 + (kc % 3) * P2_STG;
        const uint32_t aAh = sb;
        const uint32_t aAl = sb + P2_AL;
        const uint32_t aBh = sb + P2_BH;

#pragma unroll
        for (int j = 0; j < 2; j++) {
            uint32_t ah[2][4], al[2][4];
#pragma unroll
            for (int t = 0; t < 2; t++) {
                uint32_t off = (uint32_t)(wm + t * 16 + a_row) * A_PITCH + j * 32 + a_hi;
                ldsm4(aAh + off, ah[t]);
                ldsm4(aAl + off, al[t]);
            }
            uint32_t bh[4][4];
#pragma unroll
            for (int p = 0; p < 4; p++) {
                uint32_t off = (uint32_t)(j * 16 + b_kr) * B_PITCH +
                               (uint32_t)(wn + p * 16 + b_nc) * 2;
                ldsm4t(aBh + off, bh[p]);
            }
#pragma unroll
            for (int t = 0; t < 2; t++)
#pragma unroll
                for (int nt = 0; nt < 8; nt++) {
                    const uint32_t* bhp = &bh[nt >> 1][(nt & 1) * 2];
                    mma_f16(acc[t][nt], ah[t], bhp);
                    mma_f16(acc[t][nt], al[t], bhp);
                }
        }
        __syncthreads();
    }

    const int l4 = lane >> 2;
    const int l2 = (lane & 3) * 2;
#pragma unroll
    for (int t = 0; t < 2; t++) {
        const int m_lo = m0 + wm + t * 16 + l4;
        const float bi_lo = bias[m_lo];
        const float bi_hi = bias[m_lo + 8];
        float* c_lo = C + ((size_t)b * M + m_lo) * N + n0 + wn + l2;
        float* c_hi = c_lo + (size_t)8 * N;
#pragma unroll
        for (int nt = 0; nt < 8; nt++) {
            float2 v0 = {acc[t][nt][0] + bi_lo, acc[t][nt][1] + bi_lo};
            float2 v1 = {acc[t][nt][2] + bi_hi, acc[t][nt][3] + bi_hi};
            *(float2*)(c_lo + nt * 8) = v0;
            *(float2*)(c_hi + nt * 8) = v1;
        }
    }
}

// ---------------------------------------------------------------------------
__global__ void wsplit_kernel(const float* __restrict__ w,
                              __half* __restrict__ hi,
                              __half* __restrict__ lo, int n)
{
    int i = blockIdx.x * 256 + threadIdx.x;
    if (i < n) {
        float v = w[i];
        __half h = __float2half_rn(v);
        hi[i] = h;
        lo[i] = __float2half_rn(v - __half2float(h));
    }
}

// ---------------------------------------------------------------------------
// dwpw (R10 version, unchanged)
// ---------------------------------------------------------------------------
#define OFF_SIN   0
#define OFF_D3    17408
#define OFF_D5    41984
#define OFF_W5P   66560
#define OFF_W3P   71360
#define OFF_PWP   73088
#define OFF_PWB   82304
#define OFF_DB5   82688
#define OFF_DB3   82880
#define OFF_STASH 83072
#define DW_SMEM   91264

__global__ __launch_bounds__(256, 2)
void dwpw_kernel(const float* __restrict__ qkv,
                 const float* __restrict__ dw3_w, const float* __restrict__ dw3_b,
                 const float* __restrict__ pw3_w, const float* __restrict__ pw3_b,
                 const float* __restrict__ dw5_w, const float* __restrict__ dw5_b,
                 const float* __restrict__ pw5_w, const float* __restrict__ pw5_b,
                 float* __restrict__ s3q, float* __restrict__ s5q,
                 float* __restrict__ vkg)
{
    extern __shared__ __align__(16) char sm[];
    float* sin_  = (float*)(sm + OFF_SIN);
    float* d3s   = (float*)(sm + OFF_D3);
    float* d5s   = (float*)(sm + OFF_D5);
    ull*   kvq   = (ull*)(sm + OFF_D3);
    float* red   = (float*)(sm + OFF_PWP);
    float* stash = (float*)(sm + OFF_STASH);
    ull*   w5p   = (ull*)(sm + OFF_W5P);
    ull*   w3p   = (ull*)(sm + OFF_W3P);
    ull*   pwp   = (ull*)(sm + OFF_PWP);
    ull*   pwb   = (ull*)(sm + OFF_PWB);
    ull*   db5   = (ull*)(sm + OFF_DB5);
    ull*   db3   = (ull*)(sm + OFF_DB3);

    const int ytile = blockIdx.x;
    const int g     = blockIdx.y;
    const int b     = blockIdx.z;
    const int tid   = threadIdx.x;
    const int y0    = ytile * 4;

    for (int i = tid; i < 600; i += 256) {
        float w = dw5_w[(g * 24 + i / 25) * 25 + i % 25];
        w5p[i] = pk2(w, w);
    }
    for (int i = tid; i < 216; i += 256) {
        float w = dw3_w[(g * 24 + i / 9) * 9 + i % 9];
        w3p[i] = pk2(w, w);
    }
    for (int i = tid; i < 576; i += 256) {
        float a = pw3_w[g * 576 + i];
        float c = pw5_w[g * 576 + i];
        pwp[i] = pk2(a, a);
        pwp[576 + i] = pk2(c, c);
    }
    if (tid < 24) {
        float b3 = pw3_b[g * 24 + tid], b5 = pw5_b[g * 24 + tid];
        pwb[tid] = pk2(b3, b3);
        pwb[24 + tid] = pk2(b5, b5);
        float d3b = dw3_b[g * 24 + tid], d5b = dw5_b[g * 24 + tid];
        db3[tid] = pk2(d3b, d3b);
        db5[tid] = pk2(d5b, d5b);
    }

    const int c  = tid >> 5;
    const int t  = tid & 31;
    const int py = t >> 3;
    const int xo = (t & 7) * 8;

    for (int grp = 0; grp < 3; grp++) {
        __syncthreads();
        const int icb = grp * 8;
        const float* src = qkv + ((size_t)b * C3 + g * 24 + icb) * NPIX;
        for (int i = tid; i < 8 * 8 * 68; i += 256) {
            int xx = i % 68;
            int r  = (i / 68) & 7;
            int cc = i / (68 * 8);
            int yy = y0 - 2 + r;
            int xg = xx - 2;
            float v = 0.f;
            if ((unsigned)yy < 64u && (unsigned)xg < 64u)
                v = src[(size_t)cc * NPIX + yy * WIDTH + xg];
            sin_[(cc * 8 + r) * 68 + xx] = v;
        }
        __syncthreads();

        const int ch = icb + c;
        ull acc5[4], acc3[4];
        {
            ull b5v = db5[ch], b3v = db3[ch];
#pragma unroll
            for (int j = 0; j < 4; j++) { acc5[j] = b5v; acc3[j] = b3v; }
        }
#pragma unroll
        for (int dy = 0; dy < 5; dy++) {
            const ull* row = (const ull*)&sin_[(c * 8 + py + dy) * 68 + xo];
            ull r0 = row[0], r1 = row[1], r2 = row[2],
                r3 = row[3], r4 = row[4], r5 = row[5];
            ull m0 = pk2(f2hi(r0), f2lo(r1));
            ull m1 = pk2(f2hi(r1), f2lo(r2));
            ull m2 = pk2(f2hi(r2), f2lo(r3));
            ull m3 = pk2(f2hi(r3), f2lo(r4));
            ull m4 = pk2(f2hi(r4), f2lo(r5));
            const ull* w5r = &w5p[ch * 25 + dy * 5];
            ull w0 = w5r[0], w1 = w5r[1], w2 = w5r[2], w3v = w5r[3], w4 = w5r[4];

            ffma2(acc5[0], w0, r0); ffma2(acc5[0], w1, m0); ffma2(acc5[0], w2, r1);
            ffma2(acc5[0], w3v, m1); ffma2(acc5[0], w4, r2);
            ffma2(acc5[1], w0, r1); ffma2(acc5[1], w1, m1); ffma2(acc5[1], w2, r2);
            ffma2(acc5[1], w3v, m2); ffma2(acc5[1], w4, r3);
            ffma2(acc5[2], w0, r2); ffma2(acc5[2], w1, m2); ffma2(acc5[2], w2, r3);
            ffma2(acc5[2], w3v, m3); ffma2(acc5[2], w4, r4);
            ffma2(acc5[3], w0, r3); ffma2(acc5[3], w1, m3); ffma2(acc5[3], w2, r4);
            ffma2(acc5[3], w3v, m4); ffma2(acc5[3], w4, r5);

            if (dy >= 1 && dy <= 3) {
                const ull* w3r = &w3p[ch * 9 + (dy - 1) * 3];
                ull u0 = w3r[0], u1 = w3r[1], u2 = w3r[2];
                ffma2(acc3[0], u0, m0); ffma2(acc3[0], u1, r1); ffma2(acc3[0], u2, m1);
                ffma2(acc3[1], u0, m1); ffma2(acc3[1], u1, r2); ffma2(acc3[1], u2, m2);
                ffma2(acc3[2], u0, m2); ffma2(acc3[2], u1, r3); ffma2(acc3[2], u2, m3);
                ffma2(acc3[3], u0, m3); ffma2(acc3[3], u1, r4); ffma2(acc3[3], u2, m4);
            }
        }
        const int ppb = py * 32 + (xo >> 1);
#pragma unroll
        for (int j = 0; j < 4; j++) {
            *(ull*)&d3s[ch * 256 + (ppb + j) * 2] = acc3[j];
            *(ull*)&d5s[ch * 256 + (ppb + j) * 2] = acc5[j];
        }

        if (grp == 1) {
            for (int i = tid; i < 8 * 256; i += 256) {
                int cc = i >> 8, px = i & 255;
                stash[i] = sin_[(cc * 8 + 2 + (px >> 6)) * 68 + 2 + (px & 63)];
            }
        }

        if (grp == 2) {
            const int px = tid;
            const int vy = px >> 6;
            const int vx = px & 63;
            float kk[8], vv[8];
#pragma unroll
            for (int e = 0; e < 8; e++)
                kk[e] = fmaxf(stash[e * 256 + px], 0.f);
#pragma unroll
            for (int d = 0; d < 8; d++)
                vv[d] = sin_[(d * 8 + 2 + vy) * 68 + 2 + vx];

            float vacc[9][8];
#pragma unroll
            for (int d = 0; d < 8; d++)
#pragma unroll
                for (int e = 0; e < 8; e++)
                    vacc[d][e] = vv[d] * kk[e];
#pragma unroll
            for (int e = 0; e < 8; e++) vacc[8][e] = kk[e];

#pragma unroll
            for (int d = 0; d < 9; d++)
#pragma unroll
                for (int e = 0; e < 8; e++) {
                    float v = vacc[d][e];
                    v += __shfl_xor_sync(0xffffffffu, v, 16);
                    v += __shfl_xor_sync(0xffffffffu, v, 8);
                    v += __shfl_xor_sync(0xffffffffu, v, 4);
                    v += __shfl_xor_sync(0xffffffffu, v, 2);
                    v += __shfl_xor_sync(0xffffffffu, v, 1);
                    vacc[d][e] = v;
                }
            __syncthreads();
            const int w    = tid >> 5;
            const int lane = tid & 31;
            if (lane == 0) {
#pragma unroll
                for (int d = 0; d < 9; d++)
#pragma unroll
                    for (int e = 0; e < 8; e++)
                        stash[w * 72 + d * 8 + e] = vacc[d][e];
            }
            __syncthreads();
            if (tid < 72) {
                float s = 0.f;
#pragma unroll
                for (int j = 0; j < 8; j++) s += stash[j * 72 + tid];
                atomicAdd(&vkg[((size_t)b * 96 + g) * 72 + tid], s);
            }
        }
    }
    __syncthreads();

    const int conv = tid >> 7;
    const int tt   = tid & 127;
    const int og   = tt >> 5;
    const int pg   = tt & 31;
    const float* dsrc = conv ? d5s : d3s;
    const ull* wp = &pwp[conv * 576];
    const ull* bb = &pwb[conv * 24];
    float* qout = conv ? s5q : s3q;

    ull acc[6][4];
#pragma unroll
    for (int j = 0; j < 6; j++) {
        ull bv = bb[og * 6 + j];
#pragma unroll
        for (int i = 0; i < 4; i++) acc[j][i] = bv;
    }

#pragma unroll
    for (int ic = 0; ic < 24; ic++) {
        const ulonglong2 dA = *(const ulonglong2*)&dsrc[ic * 256 + pg * 8];
        const ulonglong2 dB = *(const ulonglong2*)&dsrc[ic * 256 + pg * 8 + 4];
        ull dv[4] = {dA.x, dA.y, dB.x, dB.y};
#pragma unroll
        for (int j = 0; j < 6; j++) {
            ull wv = wp[(og * 6 + j) * 24 + ic];
#pragma unroll
            for (int i = 0; i < 4; i++)
                ffma2(acc[j][i], wv, dv[i]);
        }
    }
    __syncthreads();

    {
        const int pair0 = pg * 4;
        const int by = y0 + (pair0 >> 5);
        const int bx = (pair0 & 31) * 2;
        const size_t qbase = (((size_t)b * 32 + g) * 8) * NPIX + by * WIDTH + bx;
#pragma unroll
        for (int j = 0; j < 6; j++) {
            const int o = og * 6 + j;
            if (o < 8) {
#pragma unroll
                for (int i = 0; i < 4; i++)
                    *(float2*)&qout[qbase + (size_t)o * NPIX + i * 2] =
                        make_float2(f2lo(acc[j][i]), f2hi(acc[j][i]));
            } else {
#pragma unroll
                for (int i = 0; i < 4; i++)
                    kvq[(conv * 16 + (o - 8)) * 128 + pair0 + i] = acc[j][i];
            }
        }
    }
    __syncthreads();

    {
        const int w    = tid >> 5;
        const int lane = tid & 31;
        const int cv   = w >> 2;
        const int sub  = w & 3;
        const int pair = sub * 32 + lane;

        ull kvv[16];
#pragma unroll
        for (int ch = 0; ch < 16; ch++)
            kvv[ch] = kvq[(cv * 16 + ch) * 128 + pair];

        float acc2[9][8];
#pragma unroll
        for (int d = 0; d < 9; d++)
#pragma unroll
            for (int e = 0; e < 8; e++) acc2[d][e] = 0.f;

#pragma unroll
        for (int hx = 0; hx < 2; hx++) {
            float kk[8], vv[8];
#pragma unroll
            for (int e = 0; e < 8; e++)
                kk[e] = fmaxf(hx ? f2hi(kvv[e]) : f2lo(kvv[e]), 0.f);
#pragma unroll
            for (int d = 0; d < 8; d++)
                vv[d] = hx ? f2hi(kvv[8 + d]) : f2lo(kvv[8 + d]);
#pragma unroll
            for (int d = 0; d < 8; d++)
#pragma unroll
                for (int e = 0; e < 8; e++)
                    acc2[d][e] += vv[d] * kk[e];
#pragma unroll
            for (int e = 0; e < 8; e++)
                acc2[8][e] += kk[e];
        }

#pragma unroll
        for (int d = 0; d < 9; d++)
#pragma unroll
            for (int e = 0; e < 8; e++) {
                float v = acc2[d][e];
                v += __shfl_xor_sync(0xffffffffu, v, 16);
                v += __shfl_xor_sync(0xffffffffu, v, 8);
                v += __shfl_xor_sync(0xffffffffu, v, 4);
                acc2[d][e] = v;
            }
        if (lane < 4) {
            float* rp = &red[((cv * 16) + sub * 4 + lane) * 72];
#pragma unroll
            for (int d = 0; d < 9; d++)
#pragma unroll
                for (int e = 0; e < 8; e++)
                    rp[d * 8 + e] = acc2[d][e];
        }
    }
    __syncthreads();

    if (tid < 144) {
        const int cv  = tid / 72;
        const int idx = tid % 72;
        float s = 0.f;
#pragma unroll
        for (int j = 0; j < 16; j++)
            s += red[(cv * 16 + j) * 72 + idx];
        atomicAdd(&vkg[((size_t)b * 96 + 32 + cv * 32 + g) * 72 + idx], s);
    }
}

// ---------------------------------------------------------------------------
// attention normalize: 4 CTAs/SM, packed f32x2, z=2 x 4 iterations.
// ---------------------------------------------------------------------------
__global__ __launch_bounds__(256, 4)
void att_kernel(const float* __restrict__ qkv, const float* __restrict__ s3q,
                const float* __restrict__ s5q, const float* __restrict__ vk,
                __half* __restrict__ atth)
{
    const int hh = blockIdx.x;
    const int b  = blockIdx.y;
    const int n0 = blockIdx.z * (NPIX / 2);
    const int src_id = hh >> 5;
    const int g      = hh & 31;
    const float* base;
    if (src_id == 0)      base = qkv + ((size_t)b * C3 + g * 24) * NPIX;
    else if (src_id == 1) base = s3q + (((size_t)b * 32 + g) * 8) * NPIX;
    else                  base = s5q + (((size_t)b * 32 + g) * 8) * NPIX;

    __shared__ ull vsp[72];
    const int tid = threadIdx.x;
    if (tid < 72) {
        float v = vk[((size_t)b * 96 + hh) * 72 + tid];
        vsp[tid] = pk2(v, v);
    }
    __syncthreads();

    __half* oh = atth + ((size_t)b * C3 + hh * 8) * NPIX;

#pragma unroll
    for (int it = 0; it < 4; it++) {
        const int n = n0 + (tid + it * 256) * 2;
        ull qp[8];
#pragma unroll
        for (int e = 0; e < 8; e++) {
            ull raw = *(const ull*)(base + (size_t)e * NPIX + n);
            qp[e] = pk2(fmaxf(f2lo(raw), 0.f), fmaxf(f2hi(raw), 0.f));
        }
        ull den = pk2(1e-15f, 1e-15f);
#pragma unroll
        for (int e = 0; e < 8; e++) ffma2(den, vsp[64 + e], qp[e]);
        const float rd0 = __fdividef(1.f, f2lo(den));
        const float rd1 = __fdividef(1.f, f2hi(den));
#pragma unroll
        for (int d = 0; d < 8; d++) {
            ull num = 0ull;
#pragma unroll
            for (int e = 0; e < 8; e++) ffma2(num, vsp[d * 8 + e], qp[e]);
            __half2 hp;
            hp.x = __float2half_rn(f2lo(num) * rd0);
            hp.y = __float2half_rn(f2hi(num) * rd1);
            *(__half2*)(oh + (size_t)d * NPIX + n) = hp;
        }
    }
}

// ---------------------------------------------------------------------------
struct PipeArgs {
    const float *x, *qkv_b, *dw3_w, *dw3_b, *pw3_w, *pw3_b;
    const float *dw5_w, *dw5_b, *pw5_w, *pw5_b, *proj_b;
    __half *xth, *xtl, *ath, *wqh, *wql, *wph, *wpl;
    float *qkv, *s3q, *s5q, *vkb, *out;
};

static void enqueue_part(cudaStream_t st, const PipeArgs& a, int b0, int nb)
{
    const size_t offX = (size_t)b0 * 256 * NPIX;
    const size_t offQ = (size_t)b0 * C3 * NPIX;
    const size_t off3 = (size_t)b0 * 32 * 8 * NPIX;
    const size_t offV = (size_t)b0 * 96 * 72;

    wsplit_kernel<<<(nb * 256 * NPIX + 255) / 256, 256, 0, st>>>(
        a.x + offX, a.xth + offX, a.xtl + offX, nb * 256 * NPIX);

    gemm_f16<<<dim3(NPIX / 128, C3 / 128, nb), 256, 3 * STG2, st>>>(
        a.wqh, a.wql, a.xth + offX, a.xtl + offX, a.qkv_b, a.qkv + offQ,
        C3, NPIX, 256);

    dwpw_kernel<<<dim3(16, 32, nb), 256, DW_SMEM, st>>>(
        a.qkv + offQ, a.dw3_w, a.dw3_b, a.pw3_w, a.pw3_b,
        a.dw5_w, a.dw5_b, a.pw5_w, a.pw5_b,
        a.s3q + off3, a.s5q + off3, a.vkb + offV);

    att_kernel<<<dim3(96, nb, 2), 256, 0, st>>>(
        a.qkv + offQ, a.s3q + off3, a.s5q + off3, a.vkb + offV, a.ath + offQ);

    gemm_f16_2p<<<dim3(NPIX / 128, 256 / 128, nb), 256, 3 * P2_STG, st>>>(
        a.wph, a.wpl, a.ath + offQ, a.proj_b, a.out + (size_t)b0 * 256 * NPIX,
        256, NPIX, C3);
}

extern "C" void kernel_launch(void* const* d_in, const int* in_sizes, int n_in,
                              void* d_out, int out_size)
{
    PipeArgs a;
    a.x      = (const float*)d_in[0];
    const float* qkv_w = (const float*)d_in[1];
    a.qkv_b  = (const float*)d_in[2];
    a.dw3_w  = (const float*)d_in[3];
    a.dw3_b  = (const float*)d_in[4];
    a.pw3_w  = (const float*)d_in[5];
    a.pw3_b  = (const float*)d_in[6];
    a.dw5_w  = (const float*)d_in[7];
    a.dw5_b  = (const float*)d_in[8];
    a.pw5_w  = (const float*)d_in[9];
    a.pw5_b  = (const float*)d_in[10];
    const float* proj_w = (const float*)d_in[11];
    a.proj_b = (const float*)d_in[12];
    a.out    = (float*)d_out;

    void *p;
    cudaGetSymbolAddress(&p, g_qkv);  a.qkv = (float*)p;
    cudaGetSymbolAddress(&p, g_s3q);  a.s3q = (float*)p;
    cudaGetSymbolAddress(&p, g_s5q);  a.s5q = (float*)p;
    cudaGetSymbolAddress(&p, g_vk);   a.vkb = (float*)p;
    cudaGetSymbolAddress(&p, g_xt_h); a.xth = (__half*)p;
    cudaGetSymbolAddress(&p, g_xt_l); a.xtl = (__half*)p;
    cudaGetSymbolAddress(&p, g_at_h); a.ath = (__half*)p;
    cudaGetSymbolAddress(&p, g_wq_h); a.wqh = (__half*)p;
    cudaGetSymbolAddress(&p, g_wq_l); a.wql = (__half*)p;
    cudaGetSymbolAddress(&p, g_wp_h); a.wph = (__half*)p;
    cudaGetSymbolAddress(&p, g_wp_l); a.wpl = (__half*)p;

    static bool inited = false;
    static cudaStream_t s[3];
    static cudaEvent_t evW, evJ[3];
    if (!inited) {
        for (int i = 0; i < 3; i++) {
            cudaStreamCreateWithFlags(&s[i], cudaStreamNonBlocking);
            cudaEventCreateWithFlags(&evJ[i], cudaEventDisableTiming);
        }
        cudaEventCreateWithFlags(&evW, cudaEventDisableTiming);
        cudaFuncSetAttribute(gemm_f16,
            cudaFuncAttributeMaxDynamicSharedMemorySize, 3 * STG2);
        cudaFuncSetAttribute(gemm_f16_2p,
            cudaFuncAttributeMaxDynamicSharedMemorySize, 3 * P2_STG);
        cudaFuncSetAttribute(dwpw_kernel,
            cudaFuncAttributeMaxDynamicSharedMemorySize, DW_SMEM);
        inited = true;
    }

    // serial head on main stream: vk zero (all batches) + weight splits
    cudaMemsetAsync(a.vkb, 0, (size_t)BATCH * 96 * 72 * sizeof(float), 0);
    wsplit_kernel<<<(C3 * 256 + 255) / 256, 256>>>(qkv_w, a.wqh, a.wql, C3 * 256);
    wsplit_kernel<<<(256 * C3 + 255) / 256, 256>>>(proj_w, a.wph, a.wpl, 256 * C3);

    // fork to 4 pipelines: main stream + s[0..2]
    cudaEventRecord(evW, 0);
    for (int i = 0; i < 3; i++) cudaStreamWaitEvent(s[i], evW, 0);

    enqueue_part(0,    a, 0, 2);
    enqueue_part(s[0], a, 2, 2);
    enqueue_part(s[1], a, 4, 2);
    enqueue_part(s[2], a, 6, 2);

    // join
    for (int i = 0; i < 3; i++) {
        cudaEventRecord(evJ[i], s[i]);
        cudaStreamWaitEvent(0, evJ[i], 0);
    }
}

// round 13
// speedup vs baseline: 1.0704x; 1.0647x over previous
#include <cuda_runtime.h>
#include <cuda_fp16.h>
#include <cstdint>

// ---------------------------------------------------------------------------
// LiteMLA on sm_103a.  (R10 configuration, byte-identical restore)
// Four-stream batch-split pipeline (2 batches each) to overlap stage tails.
// qkv GEMM: fp16 hi/lo x hi/lo, 3 mma products, 3-stage cp.async ring.
// proj GEMM: weights hi/lo x att fp16, 2 products, 3-stage ring.
// dwpw: depthwise f32x2 -> register-tiled pointwise -> fused vk (all heads).
// ---------------------------------------------------------------------------

#define BATCH 8
#define C3 768
#define NPIX 4096
#define WIDTH 64

__device__ float g_qkv[(size_t)BATCH * C3 * NPIX];
__device__ float g_s3q[(size_t)BATCH * 32 * 8 * NPIX];
__device__ float g_s5q[(size_t)BATCH * 32 * 8 * NPIX];
__device__ float g_vk [(size_t)BATCH * 96 * 72];

__device__ __half g_xt_h [(size_t)BATCH * 256 * NPIX];
__device__ __half g_xt_l [(size_t)BATCH * 256 * NPIX];
__device__ __half g_at_h [(size_t)BATCH * C3 * NPIX];
__device__ __half g_wq_h [C3 * 256];
__device__ __half g_wq_l [C3 * 256];
__device__ __half g_wp_h [256 * C3];
__device__ __half g_wp_l [256 * C3];

// ---------------------------------------------------------------------------
typedef unsigned long long ull;

__device__ __forceinline__ uint32_t smem_u32(const void* p) {
    uint32_t a;
    asm("{ .reg .u64 t; cvta.to.shared.u64 t, %1; cvt.u32.u64 %0, t; }"
        : "=r"(a) : "l"(p));
    return a;
}
__device__ __forceinline__ ull pk2(float lo, float hi) {
    ull r;
    asm("mov.b64 %0, {%1, %2};" : "=l"(r)
        : "r"(__float_as_uint(lo)), "r"(__float_as_uint(hi)));
    return r;
}
__device__ __forceinline__ void ffma2(ull& d, ull a, ull b) {
    asm("fma.rn.f32x2 %0, %1, %2, %0;" : "+l"(d) : "l"(a), "l"(b));
}
__device__ __forceinline__ float f2lo(ull v) {
    return __uint_as_float((unsigned)(v & 0xffffffffull));
}
__device__ __forceinline__ float f2hi(ull v) {
    return __uint_as_float((unsigned)(v >> 32));
}

#define CP_ASYNC16(s, g) \
    asm volatile("cp.async.cg.shared.global [%0], [%1], 16;" :: "r"(s), "l"(g))
#define CP_COMMIT() asm volatile("cp.async.commit_group;" ::: "memory")
#define CP_WAIT(n)  asm volatile("cp.async.wait_group %0;" :: "n"(n) : "memory")

__device__ __forceinline__ void ldsm4(uint32_t addr, uint32_t* r) {
    asm volatile("ldmatrix.sync.aligned.m8n8.x4.shared.b16 {%0,%1,%2,%3}, [%4];"
                 : "=r"(r[0]), "=r"(r[1]), "=r"(r[2]), "=r"(r[3]) : "r"(addr));
}
__device__ __forceinline__ void ldsm4t(uint32_t addr, uint32_t* r) {
    asm volatile("ldmatrix.sync.aligned.m8n8.x4.trans.shared.b16 {%0,%1,%2,%3}, [%4];"
                 : "=r"(r[0]), "=r"(r[1]), "=r"(r[2]), "=r"(r[3]) : "r"(addr));
}
__device__ __forceinline__ void mma_f16(float* d, const uint32_t* a,
                                        const uint32_t* b) {
    asm volatile(
        "mma.sync.aligned.m16n8k16.row.col.f32.f16.f16.f32 "
        "{%0,%1,%2,%3}, {%4,%5,%6,%7}, {%8,%9}, {%0,%1,%2,%3};"
        : "+f"(d[0]), "+f"(d[1]), "+f"(d[2]), "+f"(d[3])
        : "r"(a[0]), "r"(a[1]), "r"(a[2]), "r"(a[3]), "r"(b[0]), "r"(b[1]));
}

#define A_PITCH 80
#define B_PITCH 272

// ---------------------------------------------------------------------------
// 3-product GEMM (qkv): C[b] = (Ah+Al)(M,K) @ (Bh+Bl)(b,K,N) + bias
// 3-stage cp.async ring, 2 CTAs/SM.
// ---------------------------------------------------------------------------
#define OFF_AL  10240
#define OFF_BH  20480
#define OFF_BL  29184
#define STG2    37888

__device__ __forceinline__ void stage_load(
    uint32_t sbase, const __half* gA_h, const __half* gA_l,
    const __half* gB_h, const __half* gB_l, int K, int N, int kc, int tid)
{
    const int op = tid >> 6;
    const int t  = tid & 63;
    if (op < 2) {
        const __half* g = ((op == 0) ? gA_h : gA_l) + kc * 32;
        const uint32_t sb = sbase + op * OFF_AL;
#pragma unroll
        for (int it = 0; it < 8; it++) {
            int chunk = t + it * 64;
            int row = chunk >> 2, c = chunk & 3;
            CP_ASYNC16(sb + row * A_PITCH + c * 16, g + (size_t)row * K + c * 8);
        }
    } else {
        const __half* g = ((op == 2) ? gB_h : gB_l) + (size_t)kc * 32 * N;
        const uint32_t sb = sbase + ((op == 2) ? OFF_BH : OFF_BL);
#pragma unroll
        for (int it = 0; it < 8; it++) {
            int chunk = t + it * 64;
            int row = chunk >> 4, c = chunk & 15;
            CP_ASYNC16(sb + row * B_PITCH + c * 16, g + (size_t)row * N + c * 8);
        }
    }
}

__global__ __launch_bounds__(256, 2)
void gemm_f16(const __half* __restrict__ Ah, const __half* __restrict__ Al,
              const __half* __restrict__ Bmh, const __half* __restrict__ Bml,
              const float* __restrict__ bias, float* __restrict__ C,
              int M, int N, int K)
{
    extern __shared__ __align__(16) char smem[];
    const uint32_t sm0 = smem_u32(smem);

    const int tid  = threadIdx.x;
    const int wid  = tid >> 5;
    const int lane = tid & 31;
    const int n0 = blockIdx.x * 128;
    const int m0 = blockIdx.y * 128;
    const int b  = blockIdx.z;

    const int wm = (wid >> 1) * 32;
    const int wn = (wid & 1) * 64;

    const __half* gA_h = Ah + (size_t)m0 * K;
    const __half* gA_l = Al + (size_t)m0 * K;
    const __half* gB_h = Bmh + (size_t)b * K * N + n0;
    const __half* gB_l = Bml + (size_t)b * K * N + n0;

    float acc[2][8][4];
#pragma unroll
    for (int t = 0; t < 2; t++)
#pragma unroll
        for (int nt = 0; nt < 8; nt++)
#pragma unroll
            for (int i = 0; i < 4; i++) acc[t][nt][i] = 0.f;

    const int nk = K / 32;

    stage_load(sm0, gA_h, gA_l, gB_h, gB_l, K, N, 0, tid);
    CP_COMMIT();
    if (nk > 1) {
        stage_load(sm0 + STG2, gA_h, gA_l, gB_h, gB_l, K, N, 1, tid);
        CP_COMMIT();
    }

    const int a_row = lane & 15;
    const int a_hi  = (lane >> 4) * 16;
    const int b_kr = (lane & 7) + ((lane >> 3) & 1) * 8;
    const int b_nc = (lane >> 4) * 8;

    for (int kc = 0; kc < nk; kc++) {
        if (kc + 2 < nk) {
            stage_load(sm0 + ((kc + 2) % 3) * STG2,
                       gA_h, gA_l, gB_h, gB_l, K, N, kc + 2, tid);
            CP_COMMIT();
        }
        if (kc + 2 < nk)      CP_WAIT(2);
        else if (kc + 1 < nk) CP_WAIT(1);
        else                  CP_WAIT(0);
        __syncthreads();

        const uint32_t sb  = sm0 + (kc % 3) * STG2;
        const uint32_t aAh = sb;
        const uint32_t aAl = sb + OFF_AL;
        const uint32_t aBh = sb + OFF_BH;
        const uint32_t aBl = sb + OFF_BL;

#pragma unroll
        for (int j = 0; j < 2; j++) {
            uint32_t ah[2][4], al[2][4];
#pragma unroll
            for (int t = 0; t < 2; t++) {
                uint32_t off = (uint32_t)(wm + t * 16 + a_row) * A_PITCH + j * 32 + a_hi;
                ldsm4(aAh + off, ah[t]);
                ldsm4(aAl + off, al[t]);
            }
            uint32_t bh[4][4], bl[4][4];
#pragma unroll
            for (int p = 0; p < 4; p++) {
                uint32_t off = (uint32_t)(j * 16 + b_kr) * B_PITCH +
                               (uint32_t)(wn + p * 16 + b_nc) * 2;
                ldsm4t(aBh + off, bh[p]);
                ldsm4t(aBl + off, bl[p]);
            }
#pragma unroll
            for (int t = 0; t < 2; t++)
#pragma unroll
                for (int nt = 0; nt < 8; nt++) {
                    const uint32_t* bhp = &bh[nt >> 1][(nt & 1) * 2];
                    const uint32_t* blp = &bl[nt >> 1][(nt & 1) * 2];
                    mma_f16(acc[t][nt], ah[t], bhp);
                    mma_f16(acc[t][nt], ah[t], blp);
                    mma_f16(acc[t][nt], al[t], bhp);
                }
        }
        __syncthreads();
    }

    const int l4 = lane >> 2;
    const int l2 = (lane & 3) * 2;
#pragma unroll
    for (int t = 0; t < 2; t++) {
        const int m_lo = m0 + wm + t * 16 + l4;
        const float bi_lo = bias[m_lo];
        const float bi_hi = bias[m_lo + 8];
        float* c_lo = C + ((size_t)b * M + m_lo) * N + n0 + wn + l2;
        float* c_hi = c_lo + (size_t)8 * N;
#pragma unroll
        for (int nt = 0; nt < 8; nt++) {
            float2 v0 = {acc[t][nt][0] + bi_lo, acc[t][nt][1] + bi_lo};
            float2 v1 = {acc[t][nt][2] + bi_hi, acc[t][nt][3] + bi_hi};
            *(float2*)(c_lo + nt * 8) = v0;
            *(float2*)(c_hi + nt * 8) = v1;
        }
    }
}

// ---------------------------------------------------------------------------
// 2-product GEMM (proj): 3-stage ring.
// ---------------------------------------------------------------------------
#define P2_AL   10240
#define P2_BH   20480
#define P2_STG  29184

__device__ __forceinline__ void stage_load_2p(
    uint32_t sbase, const __half* gA_h, const __half* gA_l,
    const __half* gB_h, int K, int N, int kc, int tid)
{
    if (tid < 128) {
        const int op = tid >> 6;
        const int t  = tid & 63;
        const __half* g = ((op == 0) ? gA_h : gA_l) + kc * 32;
        const uint32_t sb = sbase + op * P2_AL;
#pragma unroll
        for (int it = 0; it < 8; it++) {
            int chunk = t + it * 64;
            int row = chunk >> 2, c = chunk & 3;
            CP_ASYNC16(sb + row * A_PITCH + c * 16, g + (size_t)row * K + c * 8);
        }
    } else {
        const int t = tid - 128;
        const __half* g = gB_h + (size_t)kc * 32 * N;
        const uint32_t sb = sbase + P2_BH;
#pragma unroll
        for (int it = 0; it < 4; it++) {
            int chunk = t + it * 128;
            int row = chunk >> 4, c = chunk & 15;
            CP_ASYNC16(sb + row * B_PITCH + c * 16, g + (size_t)row * N + c * 8);
        }
    }
}

__global__ __launch_bounds__(256, 2)
void gemm_f16_2p(const __half* __restrict__ Ah, const __half* __restrict__ Al,
                 const __half* __restrict__ Bmh,
                 const float* __restrict__ bias, float* __restrict__ C,
                 int M, int N, int K)
{
    extern __shared__ __align__(16) char smem[];
    const uint32_t sm0 = smem_u32(smem);

    const int tid  = threadIdx.x;
    const int wid  = tid >> 5;
    const int lane = tid & 31;
    const int n0 = blockIdx.x * 128;
    const int m0 = blockIdx.y * 128;
    const int b  = blockIdx.z;

    const int wm = (wid >> 1) * 32;
    const int wn = (wid & 1) * 64;

    const __half* gA_h = Ah + (size_t)m0 * K;
    const __half* gA_l = Al + (size_t)m0 * K;
    const __half* gB_h = Bmh + (size_t)b * K * N + n0;

    float acc[2][8][4];
#pragma unroll
    for (int t = 0; t < 2; t++)
#pragma unroll
        for (int nt = 0; nt < 8; nt++)
#pragma unroll
            for (int i = 0; i < 4; i++) acc[t][nt][i] = 0.f;

    const int nk = K / 32;

    stage_load_2p(sm0, gA_h, gA_l, gB_h, K, N, 0, tid);
    CP_COMMIT();
    if (nk > 1) {
        stage_load_2p(sm0 + P2_STG, gA_h, gA_l, gB_h, K, N, 1, tid);
        CP_COMMIT();
    }

    const int a_row = lane & 15;
    const int a_hi  = (lane >> 4) * 16;
    const int b_kr = (lane & 7) + ((lane >> 3) & 1) * 8;
    const int b_nc = (lane >> 4) * 8;

    for (int kc = 0; kc < nk; kc++) {
        if (kc + 2 < nk) {
            stage_load_2p(sm0 + ((kc + 2) % 3) * P2_STG,
                          gA_h, gA_l, gB_h, K, N, kc + 2, tid);
            CP_COMMIT();
        }
        if (kc + 2 < nk)      CP_WAIT(2);
        else if (kc + 1 < nk) CP_WAIT(1);
        else                  CP_WAIT(0);
        __syncthreads();

        const uint32_t sb  = sm0 + (kc % 3) * P2_STG;
        const uint32_t aAh = sb;
        const uint32_t aAl = sb + P2_AL;
        const uint32_t aBh = sb + P2_BH;

#pragma unroll
        for (int j = 0; j < 2; j++) {
            uint32_t ah[2][4], al[2][4];
#pragma unroll
            for (int t = 0; t < 2; t++) {
                uint32_t off = (uint32_t)(wm + t * 16 + a_row) * A_PITCH + j * 32 + a_hi;
                ldsm4(aAh + off, ah[t]);
                ldsm4(aAl + off, al[t]);
            }
            uint32_t bh[4][4];
#pragma unroll
            for (int p = 0; p < 4; p++) {
                uint32_t off = (uint32_t)(j * 16 + b_kr) * B_PITCH +
                               (uint32_t)(wn + p * 16 + b_nc) * 2;
                ldsm4t(aBh + off, bh[p]);
            }
#pragma unroll
            for (int t = 0; t < 2; t++)
#pragma unroll
                for (int nt = 0; nt < 8; nt++) {
                    const uint32_t* bhp = &bh[nt >> 1][(nt & 1) * 2];
                    mma_f16(acc[t][nt], ah[t], bhp);
                    mma_f16(acc[t][nt], al[t], bhp);
                }
        }
        __syncthreads();
    }

    const int l4 = lane >> 2;
    const int l2 = (lane & 3) * 2;
#pragma unroll
    for (int t = 0; t < 2; t++) {
        const int m_lo = m0 + wm + t * 16 + l4;
        const float bi_lo = bias[m_lo];
        const float bi_hi = bias[m_lo + 8];
        float* c_lo = C + ((size_t)b * M + m_lo) * N + n0 + wn + l2;
        float* c_hi = c_lo + (size_t)8 * N;
#pragma unroll
        for (int nt = 0; nt < 8; nt++) {
            float2 v0 = {acc[t][nt][0] + bi_lo, acc[t][nt][1] + bi_lo};
            float2 v1 = {acc[t][nt][2] + bi_hi, acc[t][nt][3] + bi_hi};
            *(float2*)(c_lo + nt * 8) = v0;
            *(float2*)(c_hi + nt * 8) = v1;
        }
    }
}

// ---------------------------------------------------------------------------
__global__ void wsplit_kernel(const float* __restrict__ w,
                              __half* __restrict__ hi,
                              __half* __restrict__ lo, int n)
{
    int i = blockIdx.x * 256 + threadIdx.x;
    if (i < n) {
        float v = w[i];
        __half h = __float2half_rn(v);
        hi[i] = h;
        lo[i] = __float2half_rn(v - __half2float(h));
    }
}

// ---------------------------------------------------------------------------
// dwpw (R10 version, unchanged)
// ---------------------------------------------------------------------------
#define OFF_SIN   0
#define OFF_D3    17408
#define OFF_D5    41984
#define OFF_W5P   66560
#define OFF_W3P   71360
#define OFF_PWP   73088
#define OFF_PWB   82304
#define OFF_DB5   82688
#define OFF_DB3   82880
#define OFF_STASH 83072
#define DW_SMEM   91264

__global__ __launch_bounds__(256, 2)
void dwpw_kernel(const float* __restrict__ qkv,
                 const float* __restrict__ dw3_w, const float* __restrict__ dw3_b,
                 const float* __restrict__ pw3_w, const float* __restrict__ pw3_b,
                 const float* __restrict__ dw5_w, const float* __restrict__ dw5_b,
                 const float* __restrict__ pw5_w, const float* __restrict__ pw5_b,
                 float* __restrict__ s3q, float* __restrict__ s5q,
                 float* __restrict__ vkg)
{
    extern __shared__ __align__(16) char sm[];
    float* sin_  = (float*)(sm + OFF_SIN);
    float* d3s   = (float*)(sm + OFF_D3);
    float* d5s   = (float*)(sm + OFF_D5);
    ull*   kvq   = (ull*)(sm + OFF_D3);
    float* red   = (float*)(sm + OFF_PWP);
    float* stash = (float*)(sm + OFF_STASH);
    ull*   w5p   = (ull*)(sm + OFF_W5P);
    ull*   w3p   = (ull*)(sm + OFF_W3P);
    ull*   pwp   = (ull*)(sm + OFF_PWP);
    ull*   pwb   = (ull*)(sm + OFF_PWB);
    ull*   db5   = (ull*)(sm + OFF_DB5);
    ull*   db3   = (ull*)(sm + OFF_DB3);

    const int ytile = blockIdx.x;
    const int g     = blockIdx.y;
    const int b     = blockIdx.z;
    const int tid   = threadIdx.x;
    const int y0    = ytile * 4;

    for (int i = tid; i < 600; i += 256) {
        float w = dw5_w[(g * 24 + i / 25) * 25 + i % 25];
        w5p[i] = pk2(w, w);
    }
    for (int i = tid; i < 216; i += 256) {
        float w = dw3_w[(g * 24 + i / 9) * 9 + i % 9];
        w3p[i] = pk2(w, w);
    }
    for (int i = tid; i < 576; i += 256) {
        float a = pw3_w[g * 576 + i];
        float c = pw5_w[g * 576 + i];
        pwp[i] = pk2(a, a);
        pwp[576 + i] = pk2(c, c);
    }
    if (tid < 24) {
        float b3 = pw3_b[g * 24 + tid], b5 = pw5_b[g * 24 + tid];
        pwb[tid] = pk2(b3, b3);
        pwb[24 + tid] = pk2(b5, b5);
        float d3b = dw3_b[g * 24 + tid], d5b = dw5_b[g * 24 + tid];
        db3[tid] = pk2(d3b, d3b);
        db5[tid] = pk2(d5b, d5b);
    }

    const int c  = tid >> 5;
    const int t  = tid & 31;
    const int py = t >> 3;
    const int xo = (t & 7) * 8;

    for (int grp = 0; grp < 3; grp++) {
        __syncthreads();
        const int icb = grp * 8;
        const float* src = qkv + ((size_t)b * C3 + g * 24 + icb) * NPIX;
        for (int i = tid; i < 8 * 8 * 68; i += 256) {
            int xx = i % 68;
            int r  = (i / 68) & 7;
            int cc = i / (68 * 8);
            int yy = y0 - 2 + r;
            int xg = xx - 2;
            float v = 0.f;
            if ((unsigned)yy < 64u && (unsigned)xg < 64u)
                v = src[(size_t)cc * NPIX + yy * WIDTH + xg];
            sin_[(cc * 8 + r) * 68 + xx] = v;
        }
        __syncthreads();

        const int ch = icb + c;
        ull acc5[4], acc3[4];
        {
            ull b5v = db5[ch], b3v = db3[ch];
#pragma unroll
            for (int j = 0; j < 4; j++) { acc5[j] = b5v; acc3[j] = b3v; }
        }
#pragma unroll
        for (int dy = 0; dy < 5; dy++) {
            const ull* row = (const ull*)&sin_[(c * 8 + py + dy) * 68 + xo];
            ull r0 = row[0], r1 = row[1], r2 = row[2],
                r3 = row[3], r4 = row[4], r5 = row[5];
            ull m0 = pk2(f2hi(r0), f2lo(r1));
            ull m1 = pk2(f2hi(r1), f2lo(r2));
            ull m2 = pk2(f2hi(r2), f2lo(r3));
            ull m3 = pk2(f2hi(r3), f2lo(r4));
            ull m4 = pk2(f2hi(r4), f2lo(r5));
            const ull* w5r = &w5p[ch * 25 + dy * 5];
            ull w0 = w5r[0], w1 = w5r[1], w2 = w5r[2], w3v = w5r[3], w4 = w5r[4];

            ffma2(acc5[0], w0, r0); ffma2(acc5[0], w1, m0); ffma2(acc5[0], w2, r1);
            ffma2(acc5[0], w3v, m1); ffma2(acc5[0], w4, r2);
            ffma2(acc5[1], w0, r1); ffma2(acc5[1], w1, m1); ffma2(acc5[1], w2, r2);
            ffma2(acc5[1], w3v, m2); ffma2(acc5[1], w4, r3);
            ffma2(acc5[2], w0, r2); ffma2(acc5[2], w1, m2); ffma2(acc5[2], w2, r3);
            ffma2(acc5[2], w3v, m3); ffma2(acc5[2], w4, r4);
            ffma2(acc5[3], w0, r3); ffma2(acc5[3], w1, m3); ffma2(acc5[3], w2, r4);
            ffma2(acc5[3], w3v, m4); ffma2(acc5[3], w4, r5);

            if (dy >= 1 && dy <= 3) {
                const ull* w3r = &w3p[ch * 9 + (dy - 1) * 3];
                ull u0 = w3r[0], u1 = w3r[1], u2 = w3r[2];
                ffma2(acc3[0], u0, m0); ffma2(acc3[0], u1, r1); ffma2(acc3[0], u2, m1);
                ffma2(acc3[1], u0, m1); ffma2(acc3[1], u1, r2); ffma2(acc3[1], u2, m2);
                ffma2(acc3[2], u0, m2); ffma2(acc3[2], u1, r3); ffma2(acc3[2], u2, m3);
                ffma2(acc3[3], u0, m3); ffma2(acc3[3], u1, r4); ffma2(acc3[3], u2, m4);
            }
        }
        const int ppb = py * 32 + (xo >> 1);
#pragma unroll
        for (int j = 0; j < 4; j++) {
            *(ull*)&d3s[ch * 256 + (ppb + j) * 2] = acc3[j];
            *(ull*)&d5s[ch * 256 + (ppb + j) * 2] = acc5[j];
        }

        if (grp == 1) {
            for (int i = tid; i < 8 * 256; i += 256) {
                int cc = i >> 8, px = i & 255;
                stash[i] = sin_[(cc * 8 + 2 + (px >> 6)) * 68 + 2 + (px & 63)];
            }
        }

        if (grp == 2) {
            const int px = tid;
            const int vy = px >> 6;
            const int vx = px & 63;
            float kk[8], vv[8];
#pragma unroll
            for (int e = 0; e < 8; e++)
                kk[e] = fmaxf(stash[e * 256 + px], 0.f);
#pragma unroll
            for (int d = 0; d < 8; d++)
                vv[d] = sin_[(d * 8 + 2 + vy) * 68 + 2 + vx];

            float vacc[9][8];
#pragma unroll
            for (int d = 0; d < 8; d++)
#pragma unroll
                for (int e = 0; e < 8; e++)
                    vacc[d][e] = vv[d] * kk[e];
#pragma unroll
            for (int e = 0; e < 8; e++) vacc[8][e] = kk[e];

#pragma unroll
            for (int d = 0; d < 9; d++)
#pragma unroll
                for (int e = 0; e < 8; e++) {
                    float v = vacc[d][e];
                    v += __shfl_xor_sync(0xffffffffu, v, 16);
                    v += __shfl_xor_sync(0xffffffffu, v, 8);
                    v += __shfl_xor_sync(0xffffffffu, v, 4);
                    v += __shfl_xor_sync(0xffffffffu, v, 2);
                    v += __shfl_xor_sync(0xffffffffu, v, 1);
                    vacc[d][e] = v;
                }
            __syncthreads();
            const int w    = tid >> 5;
            const int lane = tid & 31;
            if (lane == 0) {
#pragma unroll
                for (int d = 0; d < 9; d++)
#pragma unroll
                    for (int e = 0; e < 8; e++)
                        stash[w * 72 + d * 8 + e] = vacc[d][e];
            }
            __syncthreads();
            if (tid < 72) {
                float s = 0.f;
#pragma unroll
                for (int j = 0; j < 8; j++) s += stash[j * 72 + tid];
                atomicAdd(&vkg[((size_t)b * 96 + g) * 72 + tid], s);
            }
        }
    }
    __syncthreads();

    const int conv = tid >> 7;
    const int tt   = tid & 127;
    const int og   = tt >> 5;
    const int pg   = tt & 31;
    const float* dsrc = conv ? d5s : d3s;
    const ull* wp = &pwp[conv * 576];
    const ull* bb = &pwb[conv * 24];
    float* qout = conv ? s5q : s3q;

    ull acc[6][4];
#pragma unroll
    for (int j = 0; j < 6; j++) {
        ull bv = bb[og * 6 + j];
#pragma unroll
        for (int i = 0; i < 4; i++) acc[j][i] = bv;
    }

#pragma unroll
    for (int ic = 0; ic < 24; ic++) {
        const ulonglong2 dA = *(const ulonglong2*)&dsrc[ic * 256 + pg * 8];
        const ulonglong2 dB = *(const ulonglong2*)&dsrc[ic * 256 + pg * 8 + 4];
        ull dv[4] = {dA.x, dA.y, dB.x, dB.y};
#pragma unroll
        for (int j = 0; j < 6; j++) {
            ull wv = wp[(og * 6 + j) * 24 + ic];
#pragma unroll
            for (int i = 0; i < 4; i++)
                ffma2(acc[j][i], wv, dv[i]);
        }
    }
    __syncthreads();

    {
        const int pair0 = pg * 4;
        const int by = y0 + (pair0 >> 5);
        const int bx = (pair0 & 31) * 2;
        const size_t qbase = (((size_t)b * 32 + g) * 8) * NPIX + by * WIDTH + bx;
#pragma unroll
        for (int j = 0; j < 6; j++) {
            const int o = og * 6 + j;
            if (o < 8) {
#pragma unroll
                for (int i = 0; i < 4; i++)
                    *(float2*)&qout[qbase + (size_t)o * NPIX + i * 2] =
                        make_float2(f2lo(acc[j][i]), f2hi(acc[j][i]));
            } else {
#pragma unroll
                for (int i = 0; i < 4; i++)
                    kvq[(conv * 16 + (o - 8)) * 128 + pair0 + i] = acc[j][i];
            }
        }
    }
    __syncthreads();

    {
        const int w    = tid >> 5;
        const int lane = tid & 31;
        const int cv   = w >> 2;
        const int sub  = w & 3;
        const int pair = sub * 32 + lane;

        ull kvv[16];
#pragma unroll
        for (int ch = 0; ch < 16; ch++)
            kvv[ch] = kvq[(cv * 16 + ch) * 128 + pair];

        float acc2[9][8];
#pragma unroll
        for (int d = 0; d < 9; d++)
#pragma unroll
            for (int e = 0; e < 8; e++) acc2[d][e] = 0.f;

#pragma unroll
        for (int hx = 0; hx < 2; hx++) {
            float kk[8], vv[8];
#pragma unroll
            for (int e = 0; e < 8; e++)
                kk[e] = fmaxf(hx ? f2hi(kvv[e]) : f2lo(kvv[e]), 0.f);
#pragma unroll
            for (int d = 0; d < 8; d++)
                vv[d] = hx ? f2hi(kvv[8 + d]) : f2lo(kvv[8 + d]);
#pragma unroll
            for (int d = 0; d < 8; d++)
#pragma unroll
                for (int e = 0; e < 8; e++)
                    acc2[d][e] += vv[d] * kk[e];
#pragma unroll
            for (int e = 0; e < 8; e++)
                acc2[8][e] += kk[e];
        }

#pragma unroll
        for (int d = 0; d < 9; d++)
#pragma unroll
            for (int e = 0; e < 8; e++) {
                float v = acc2[d][e];
                v += __shfl_xor_sync(0xffffffffu, v, 16);
                v += __shfl_xor_sync(0xffffffffu, v, 8);
                v += __shfl_xor_sync(0xffffffffu, v, 4);
                acc2[d][e] = v;
            }
        if (lane < 4) {
            float* rp = &red[((cv * 16) + sub * 4 + lane) * 72];
#pragma unroll
            for (int d = 0; d < 9; d++)
#pragma unroll
                for (int e = 0; e < 8; e++)
                    rp[d * 8 + e] = acc2[d][e];
        }
    }
    __syncthreads();

    if (tid < 144) {
        const int cv  = tid / 72;
        const int idx = tid % 72;
        float s = 0.f;
#pragma unroll
        for (int j = 0; j < 16; j++)
            s += red[(cv * 16 + j) * 72 + idx];
        atomicAdd(&vkg[((size_t)b * 96 + 32 + cv * 32 + g) * 72 + idx], s);
    }
}

// ---------------------------------------------------------------------------
// attention normalize: 4 CTAs/SM, packed f32x2, z-split 4 (R10 version).
// ---------------------------------------------------------------------------
__global__ __launch_bounds__(256, 4)
void att_kernel(const float* __restrict__ qkv, const float* __restrict__ s3q,
                const float* __restrict__ s5q, const float* __restrict__ vk,
                __half* __restrict__ atth)
{
    const int hh = blockIdx.x;
    const int b  = blockIdx.y;
    const int n0 = blockIdx.z * (NPIX / 4);
    const int src_id = hh >> 5;
    const int g      = hh & 31;
    const float* base;
    if (src_id == 0)      base = qkv + ((size_t)b * C3 + g * 24) * NPIX;
    else if (src_id == 1) base = s3q + (((size_t)b * 32 + g) * 8) * NPIX;
    else                  base = s5q + (((size_t)b * 32 + g) * 8) * NPIX;

    __shared__ ull vsp[72];
    const int tid = threadIdx.x;
    if (tid < 72) {
        float v = vk[((size_t)b * 96 + hh) * 72 + tid];
        vsp[tid] = pk2(v, v);
    }
    __syncthreads();

    __half* oh = atth + ((size_t)b * C3 + hh * 8) * NPIX;

#pragma unroll
    for (int it = 0; it < 2; it++) {
        const int n = n0 + (tid + it * 256) * 2;
        ull qp[8];
#pragma unroll
        for (int e = 0; e < 8; e++) {
            ull raw = *(const ull*)(base + (size_t)e * NPIX + n);
            qp[e] = pk2(fmaxf(f2lo(raw), 0.f), fmaxf(f2hi(raw), 0.f));
        }
        ull den = pk2(1e-15f, 1e-15f);
#pragma unroll
        for (int e = 0; e < 8; e++) ffma2(den, vsp[64 + e], qp[e]);
        const float rd0 = __fdividef(1.f, f2lo(den));
        const float rd1 = __fdividef(1.f, f2hi(den));
#pragma unroll
        for (int d = 0; d < 8; d++) {
            ull num = 0ull;
#pragma unroll
            for (int e = 0; e < 8; e++) ffma2(num, vsp[d * 8 + e], qp[e]);
            __half2 hp;
            hp.x = __float2half_rn(f2lo(num) * rd0);
            hp.y = __float2half_rn(f2hi(num) * rd1);
            *(__half2*)(oh + (size_t)d * NPIX + n) = hp;
        }
    }
}

// ---------------------------------------------------------------------------
struct PipeArgs {
    const float *x, *qkv_b, *dw3_w, *dw3_b, *pw3_w, *pw3_b;
    const float *dw5_w, *dw5_b, *pw5_w, *pw5_b, *proj_b;
    __half *xth, *xtl, *ath, *wqh, *wql, *wph, *wpl;
    float *qkv, *s3q, *s5q, *vkb, *out;
};

static void enqueue_part(cudaStream_t st, const PipeArgs& a, int b0, int nb)
{
    const size_t offX = (size_t)b0 * 256 * NPIX;
    const size_t offQ = (size_t)b0 * C3 * NPIX;
    const size_t off3 = (size_t)b0 * 32 * 8 * NPIX;
    const size_t offV = (size_t)b0 * 96 * 72;

    wsplit_kernel<<<(nb * 256 * NPIX + 255) / 256, 256, 0, st>>>(
        a.x + offX, a.xth + offX, a.xtl + offX, nb * 256 * NPIX);

    gemm_f16<<<dim3(NPIX / 128, C3 / 128, nb), 256, 3 * STG2, st>>>(
        a.wqh, a.wql, a.xth + offX, a.xtl + offX, a.qkv_b, a.qkv + offQ,
        C3, NPIX, 256);

    dwpw_kernel<<<dim3(16, 32, nb), 256, DW_SMEM, st>>>(
        a.qkv + offQ, a.dw3_w, a.dw3_b, a.pw3_w, a.pw3_b,
        a.dw5_w, a.dw5_b, a.pw5_w, a.pw5_b,
        a.s3q + off3, a.s5q + off3, a.vkb + offV);

    att_kernel<<<dim3(96, nb, 4), 256, 0, st>>>(
        a.qkv + offQ, a.s3q + off3, a.s5q + off3, a.vkb + offV, a.ath + offQ);

    gemm_f16_2p<<<dim3(NPIX / 128, 256 / 128, nb), 256, 3 * P2_STG, st>>>(
        a.wph, a.wpl, a.ath + offQ, a.proj_b, a.out + (size_t)b0 * 256 * NPIX,
        256, NPIX, C3);
}

extern "C" void kernel_launch(void* const* d_in, const int* in_sizes, int n_in,
                              void* d_out, int out_size)
{
    PipeArgs a;
    a.x      = (const float*)d_in[0];
    const float* qkv_w = (const float*)d_in[1];
    a.qkv_b  = (const float*)d_in[2];
    a.dw3_w  = (const float*)d_in[3];
    a.dw3_b  = (const float*)d_in[4];
    a.pw3_w  = (const float*)d_in[5];
    a.pw3_b  = (const float*)d_in[6];
    a.dw5_w  = (const float*)d_in[7];
    a.dw5_b  = (const float*)d_in[8];
    a.pw5_w  = (const float*)d_in[9];
    a.pw5_b  = (const float*)d_in[10];
    const float* proj_w = (const float*)d_in[11];
    a.proj_b = (const float*)d_in[12];
    a.out    = (float*)d_out;

    void *p;
    cudaGetSymbolAddress(&p, g_qkv);  a.qkv = (float*)p;
    cudaGetSymbolAddress(&p, g_s3q);  a.s3q = (float*)p;
    cudaGetSymbolAddress(&p, g_s5q);  a.s5q = (float*)p;
    cudaGetSymbolAddress(&p, g_vk);   a.vkb = (float*)p;
    cudaGetSymbolAddress(&p, g_xt_h); a.xth = (__half*)p;
    cudaGetSymbolAddress(&p, g_xt_l); a.xtl = (__half*)p;
    cudaGetSymbolAddress(&p, g_at_h); a.ath = (__half*)p;
    cudaGetSymbolAddress(&p, g_wq_h); a.wqh = (__half*)p;
    cudaGetSymbolAddress(&p, g_wq_l); a.wql = (__half*)p;
    cudaGetSymbolAddress(&p, g_wp_h); a.wph = (__half*)p;
    cudaGetSymbolAddress(&p, g_wp_l); a.wpl = (__half*)p;

    static bool inited = false;
    static cudaStream_t s[3];
    static cudaEvent_t evW, evJ[3];
    if (!inited) {
        for (int i = 0; i < 3; i++) {
            cudaStreamCreateWithFlags(&s[i], cudaStreamNonBlocking);
            cudaEventCreateWithFlags(&evJ[i], cudaEventDisableTiming);
        }
        cudaEventCreateWithFlags(&evW, cudaEventDisableTiming);
        cudaFuncSetAttribute(gemm_f16,
            cudaFuncAttributeMaxDynamicSharedMemorySize, 3 * STG2);
        cudaFuncSetAttribute(gemm_f16_2p,
            cudaFuncAttributeMaxDynamicSharedMemorySize, 3 * P2_STG);
        cudaFuncSetAttribute(dwpw_kernel,
            cudaFuncAttributeMaxDynamicSharedMemorySize, DW_SMEM);
        inited = true;
    }

    // serial head on main stream: vk zero (all batches) + weight splits
    cudaMemsetAsync(a.vkb, 0, (size_t)BATCH * 96 * 72 * sizeof(float), 0);
    wsplit_kernel<<<(C3 * 256 + 255) / 256, 256>>>(qkv_w, a.wqh, a.wql, C3 * 256);
    wsplit_kernel<<<(256 * C3 + 255) / 256, 256>>>(proj_w, a.wph, a.wpl, 256 * C3);

    // fork to 4 pipelines: main stream + s[0..2]
    cudaEventRecord(evW, 0);
    for (int i = 0; i < 3; i++) cudaStreamWaitEvent(s[i], evW, 0);

    enqueue_part(0,    a, 0, 2);
    enqueue_part(s[0], a, 2, 2);
    enqueue_part(s[1], a, 4, 2);
    enqueue_part(s[2], a, 6, 2);

    // join
    for (int i = 0; i < 3; i++) {
        cudaEventRecord(evJ[i], s[i]);
        cudaStreamWaitEvent(0, evJ[i], 0);
    }
}

// round 14
// speedup vs baseline: 1.1002x; 1.0278x over previous
#include <cuda_runtime.h>
#include <cuda_fp16.h>
#include <cstdint>

// ---------------------------------------------------------------------------
// LiteMLA on sm_103a.  (R10 kernels; early-fork launch + vectorized wsplit)
// Four-stream batch-split pipeline (2 batches each) to overlap stage tails.
// qkv GEMM: fp16 hi/lo x hi/lo, 3 mma products, 3-stage cp.async ring.
// proj GEMM: weights hi/lo x att fp16, 2 products, 3-stage ring.
// dwpw: depthwise f32x2 -> register-tiled pointwise -> fused vk (all heads).
// ---------------------------------------------------------------------------

#define BATCH 8
#define C3 768
#define NPIX 4096
#define WIDTH 64

__device__ float g_qkv[(size_t)BATCH * C3 * NPIX];
__device__ float g_s3q[(size_t)BATCH * 32 * 8 * NPIX];
__device__ float g_s5q[(size_t)BATCH * 32 * 8 * NPIX];
__device__ float g_vk [(size_t)BATCH * 96 * 72];

__device__ __half g_xt_h [(size_t)BATCH * 256 * NPIX];
__device__ __half g_xt_l [(size_t)BATCH * 256 * NPIX];
__device__ __half g_at_h [(size_t)BATCH * C3 * NPIX];
__device__ __half g_wq_h [C3 * 256];
__device__ __half g_wq_l [C3 * 256];
__device__ __half g_wp_h [256 * C3];
__device__ __half g_wp_l [256 * C3];

// ---------------------------------------------------------------------------
typedef unsigned long long ull;

__device__ __forceinline__ uint32_t smem_u32(const void* p) {
    uint32_t a;
    asm("{ .reg .u64 t; cvta.to.shared.u64 t, %1; cvt.u32.u64 %0, t; }"
        : "=r"(a) : "l"(p));
    return a;
}
__device__ __forceinline__ ull pk2(float lo, float hi) {
    ull r;
    asm("mov.b64 %0, {%1, %2};" : "=l"(r)
        : "r"(__float_as_uint(lo)), "r"(__float_as_uint(hi)));
    return r;
}
__device__ __forceinline__ void ffma2(ull& d, ull a, ull b) {
    asm("fma.rn.f32x2 %0, %1, %2, %0;" : "+l"(d) : "l"(a), "l"(b));
}
__device__ __forceinline__ float f2lo(ull v) {
    return __uint_as_float((unsigned)(v & 0xffffffffull));
}
__device__ __forceinline__ float f2hi(ull v) {
    return __uint_as_float((unsigned)(v >> 32));
}

#define CP_ASYNC16(s, g) \
    asm volatile("cp.async.cg.shared.global [%0], [%1], 16;" :: "r"(s), "l"(g))
#define CP_COMMIT() asm volatile("cp.async.commit_group;" ::: "memory")
#define CP_WAIT(n)  asm volatile("cp.async.wait_group %0;" :: "n"(n) : "memory")

__device__ __forceinline__ void ldsm4(uint32_t addr, uint32_t* r) {
    asm volatile("ldmatrix.sync.aligned.m8n8.x4.shared.b16 {%0,%1,%2,%3}, [%4];"
                 : "=r"(r[0]), "=r"(r[1]), "=r"(r[2]), "=r"(r[3]) : "r"(addr));
}
__device__ __forceinline__ void ldsm4t(uint32_t addr, uint32_t* r) {
    asm volatile("ldmatrix.sync.aligned.m8n8.x4.trans.shared.b16 {%0,%1,%2,%3}, [%4];"
                 : "=r"(r[0]), "=r"(r[1]), "=r"(r[2]), "=r"(r[3]) : "r"(addr));
}
__device__ __forceinline__ void mma_f16(float* d, const uint32_t* a,
                                        const uint32_t* b) {
    asm volatile(
        "mma.sync.aligned.m16n8k16.row.col.f32.f16.f16.f32 "
        "{%0,%1,%2,%3}, {%4,%5,%6,%7}, {%8,%9}, {%0,%1,%2,%3};"
        : "+f"(d[0]), "+f"(d[1]), "+f"(d[2]), "+f"(d[3])
        : "r"(a[0]), "r"(a[1]), "r"(a[2]), "r"(a[3]), "r"(b[0]), "r"(b[1]));
}

#define A_PITCH 80
#define B_PITCH 272

// ---------------------------------------------------------------------------
// 3-product GEMM (qkv): C[b] = (Ah+Al)(M,K) @ (Bh+Bl)(b,K,N) + bias
// 3-stage cp.async ring, 2 CTAs/SM.  (R10 version, unchanged)
// ---------------------------------------------------------------------------
#define OFF_AL  10240
#define OFF_BH  20480
#define OFF_BL  29184
#define STG2    37888

__device__ __forceinline__ void stage_load(
    uint32_t sbase, const __half* gA_h, const __half* gA_l,
    const __half* gB_h, const __half* gB_l, int K, int N, int kc, int tid)
{
    const int op = tid >> 6;
    const int t  = tid & 63;
    if (op < 2) {
        const __half* g = ((op == 0) ? gA_h : gA_l) + kc * 32;
        const uint32_t sb = sbase + op * OFF_AL;
#pragma unroll
        for (int it = 0; it < 8; it++) {
            int chunk = t + it * 64;
            int row = chunk >> 2, c = chunk & 3;
            CP_ASYNC16(sb + row * A_PITCH + c * 16, g + (size_t)row * K + c * 8);
        }
    } else {
        const __half* g = ((op == 2) ? gB_h : gB_l) + (size_t)kc * 32 * N;
        const uint32_t sb = sbase + ((op == 2) ? OFF_BH : OFF_BL);
#pragma unroll
        for (int it = 0; it < 8; it++) {
            int chunk = t + it * 64;
            int row = chunk >> 4, c = chunk & 15;
            CP_ASYNC16(sb + row * B_PITCH + c * 16, g + (size_t)row * N + c * 8);
        }
    }
}

__global__ __launch_bounds__(256, 2)
void gemm_f16(const __half* __restrict__ Ah, const __half* __restrict__ Al,
              const __half* __restrict__ Bmh, const __half* __restrict__ Bml,
              const float* __restrict__ bias, float* __restrict__ C,
              int M, int N, int K)
{
    extern __shared__ __align__(16) char smem[];
    const uint32_t sm0 = smem_u32(smem);

    const int tid  = threadIdx.x;
    const int wid  = tid >> 5;
    const int lane = tid & 31;
    const int n0 = blockIdx.x * 128;
    const int m0 = blockIdx.y * 128;
    const int b  = blockIdx.z;

    const int wm = (wid >> 1) * 32;
    const int wn = (wid & 1) * 64;

    const __half* gA_h = Ah + (size_t)m0 * K;
    const __half* gA_l = Al + (size_t)m0 * K;
    const __half* gB_h = Bmh + (size_t)b * K * N + n0;
    const __half* gB_l = Bml + (size_t)b * K * N + n0;

    float acc[2][8][4];
#pragma unroll
    for (int t = 0; t < 2; t++)
#pragma unroll
        for (int nt = 0; nt < 8; nt++)
#pragma unroll
            for (int i = 0; i < 4; i++) acc[t][nt][i] = 0.f;

    const int nk = K / 32;

    stage_load(sm0, gA_h, gA_l, gB_h, gB_l, K, N, 0, tid);
    CP_COMMIT();
    if (nk > 1) {
        stage_load(sm0 + STG2, gA_h, gA_l, gB_h, gB_l, K, N, 1, tid);
        CP_COMMIT();
    }

    const int a_row = lane & 15;
    const int a_hi  = (lane >> 4) * 16;
    const int b_kr = (lane & 7) + ((lane >> 3) & 1) * 8;
    const int b_nc = (lane >> 4) * 8;

    for (int kc = 0; kc < nk; kc++) {
        if (kc + 2 < nk) {
            stage_load(sm0 + ((kc + 2) % 3) * STG2,
                       gA_h, gA_l, gB_h, gB_l, K, N, kc + 2, tid);
            CP_COMMIT();
        }
        if (kc + 2 < nk)      CP_WAIT(2);
        else if (kc + 1 < nk) CP_WAIT(1);
        else                  CP_WAIT(0);
        __syncthreads();

        const uint32_t sb  = sm0 + (kc % 3) * STG2;
        const uint32_t aAh = sb;
        const uint32_t aAl = sb + OFF_AL;
        const uint32_t aBh = sb + OFF_BH;
        const uint32_t aBl = sb + OFF_BL;

#pragma unroll
        for (int j = 0; j < 2; j++) {
            uint32_t ah[2][4], al[2][4];
#pragma unroll
            for (int t = 0; t < 2; t++) {
                uint32_t off = (uint32_t)(wm + t * 16 + a_row) * A_PITCH + j * 32 + a_hi;
                ldsm4(aAh + off, ah[t]);
                ldsm4(aAl + off, al[t]);
            }
            uint32_t bh[4][4], bl[4][4];
#pragma unroll
            for (int p = 0; p < 4; p++) {
                uint32_t off = (uint32_t)(j * 16 + b_kr) * B_PITCH +
                               (uint32_t)(wn + p * 16 + b_nc) * 2;
                ldsm4t(aBh + off, bh[p]);
                ldsm4t(aBl + off, bl[p]);
            }
#pragma unroll
            for (int t = 0; t < 2; t++)
#pragma unroll
                for (int nt = 0; nt < 8; nt++) {
                    const uint32_t* bhp = &bh[nt >> 1][(nt & 1) * 2];
                    const uint32_t* blp = &bl[nt >> 1][(nt & 1) * 2];
                    mma_f16(acc[t][nt], ah[t], bhp);
                    mma_f16(acc[t][nt], ah[t], blp);
                    mma_f16(acc[t][nt], al[t], bhp);
                }
        }
        __syncthreads();
    }

    const int l4 = lane >> 2;
    const int l2 = (lane & 3) * 2;
#pragma unroll
    for (int t = 0; t < 2; t++) {
        const int m_lo = m0 + wm + t * 16 + l4;
        const float bi_lo = bias[m_lo];
        const float bi_hi = bias[m_lo + 8];
        float* c_lo = C + ((size_t)b * M + m_lo) * N + n0 + wn + l2;
        float* c_hi = c_lo + (size_t)8 * N;
#pragma unroll
        for (int nt = 0; nt < 8; nt++) {
            float2 v0 = {acc[t][nt][0] + bi_lo, acc[t][nt][1] + bi_lo};
            float2 v1 = {acc[t][nt][2] + bi_hi, acc[t][nt][3] + bi_hi};
            *(float2*)(c_lo + nt * 8) = v0;
            *(float2*)(c_hi + nt * 8) = v1;
        }
    }
}

// ---------------------------------------------------------------------------
// 2-product GEMM (proj): 3-stage ring.  (R10 version, unchanged)
// ---------------------------------------------------------------------------
#define P2_AL   10240
#define P2_BH   20480
#define P2_STG  29184

__device__ __forceinline__ void stage_load_2p(
    uint32_t sbase, const __half* gA_h, const __half* gA_l,
    const __half* gB_h, int K, int N, int kc, int tid)
{
    if (tid < 128) {
        const int op = tid >> 6;
        const int t  = tid & 63;
        const __half* g = ((op == 0) ? gA_h : gA_l) + kc * 32;
        const uint32_t sb = sbase + op * P2_AL;
#pragma unroll
        for (int it = 0; it < 8; it++) {
            int chunk = t + it * 64;
            int row = chunk >> 2, c = chunk & 3;
            CP_ASYNC16(sb + row * A_PITCH + c * 16, g + (size_t)row * K + c * 8);
        }
    } else {
        const int t = tid - 128;
        const __half* g = gB_h + (size_t)kc * 32 * N;
        const uint32_t sb = sbase + P2_BH;
#pragma unroll
        for (int it = 0; it < 4; it++) {
            int chunk = t + it * 128;
            int row = chunk >> 4, c = chunk & 15;
            CP_ASYNC16(sb + row * B_PITCH + c * 16, g + (size_t)row * N + c * 8);
        }
    }
}

__global__ __launch_bounds__(256, 2)
void gemm_f16_2p(const __half* __restrict__ Ah, const __half* __restrict__ Al,
                 const __half* __restrict__ Bmh,
                 const float* __restrict__ bias, float* __restrict__ C,
                 int M, int N, int K)
{
    extern __shared__ __align__(16) char smem[];
    const uint32_t sm0 = smem_u32(smem);

    const int tid  = threadIdx.x;
    const int wid  = tid >> 5;
    const int lane = tid & 31;
    const int n0 = blockIdx.x * 128;
    const int m0 = blockIdx.y * 128;
    const int b  = blockIdx.z;

    const int wm = (wid >> 1) * 32;
    const int wn = (wid & 1) * 64;

    const __half* gA_h = Ah + (size_t)m0 * K;
    const __half* gA_l = Al + (size_t)m0 * K;
    const __half* gB_h = Bmh + (size_t)b * K * N + n0;

    float acc[2][8][4];
#pragma unroll
    for (int t = 0; t < 2; t++)
#pragma unroll
        for (int nt = 0; nt < 8; nt++)
#pragma unroll
            for (int i = 0; i < 4; i++) acc[t][nt][i] = 0.f;

    const int nk = K / 32;

    stage_load_2p(sm0, gA_h, gA_l, gB_h, K, N, 0, tid);
    CP_COMMIT();
    if (nk > 1) {
        stage_load_2p(sm0 + P2_STG, gA_h, gA_l, gB_h, K, N, 1, tid);
        CP_COMMIT();
    }

    const int a_row = lane & 15;
    const int a_hi  = (lane >> 4) * 16;
    const int b_kr = (lane & 7) + ((lane >> 3) & 1) * 8;
    const int b_nc = (lane >> 4) * 8;

    for (int kc = 0; kc < nk; kc++) {
        if (kc + 2 < nk) {
            stage_load_2p(sm0 + ((kc + 2) % 3) * P2_STG,
                          gA_h, gA_l, gB_h, K, N, kc + 2, tid);
            CP_COMMIT();
        }
        if (kc + 2 < nk)      CP_WAIT(2);
        else if (kc + 1 < nk) CP_WAIT(1);
        else                  CP_WAIT(0);
        __syncthreads();

        const uint32_t sb  = sm0 + (kc % 3) * P2_STG;
        const uint32_t aAh = sb;
        const uint32_t aAl = sb + P2_AL;
        const uint32_t aBh = sb + P2_BH;

#pragma unroll
        for (int j = 0; j < 2; j++) {
            uint32_t ah[2][4], al[2][4];
#pragma unroll
            for (int t = 0; t < 2; t++) {
                uint32_t off = (uint32_t)(wm + t * 16 + a_row) * A_PITCH + j * 32 + a_hi;
                ldsm4(aAh + off, ah[t]);
                ldsm4(aAl + off, al[t]);
            }
            uint32_t bh[4][4];
#pragma unroll
            for (int p = 0; p < 4; p++) {
                uint32_t off = (uint32_t)(j * 16 + b_kr) * B_PITCH +
                               (uint32_t)(wn + p * 16 + b_nc) * 2;
                ldsm4t(aBh + off, bh[p]);
            }
#pragma unroll
            for (int t = 0; t < 2; t++)
#pragma unroll
                for (int nt = 0; nt < 8; nt++) {
                    const uint32_t* bhp = &bh[nt >> 1][(nt & 1) * 2];
                    mma_f16(acc[t][nt], ah[t], bhp);
                    mma_f16(acc[t][nt], al[t], bhp);
                }
        }
        __syncthreads();
    }

    const int l4 = lane >> 2;
    const int l2 = (lane & 3) * 2;
#pragma unroll
    for (int t = 0; t < 2; t++) {
        const int m_lo = m0 + wm + t * 16 + l4;
        const float bi_lo = bias[m_lo];
        const float bi_hi = bias[m_lo + 8];
        float* c_lo = C + ((size_t)b * M + m_lo) * N + n0 + wn + l2;
        float* c_hi = c_lo + (size_t)8 * N;
#pragma unroll
        for (int nt = 0; nt < 8; nt++) {
            float2 v0 = {acc[t][nt][0] + bi_lo, acc[t][nt][1] + bi_lo};
            float2 v1 = {acc[t][nt][2] + bi_hi, acc[t][nt][3] + bi_hi};
            *(float2*)(c_lo + nt * 8) = v0;
            *(float2*)(c_hi + nt * 8) = v1;
        }
    }
}

// ---------------------------------------------------------------------------
// vectorized split: 4 elements/thread (float4 -> 2x half2 each for hi/lo)
// n must be a multiple of 4 (true for all call sites).
// ---------------------------------------------------------------------------
__global__ void wsplit_kernel(const float* __restrict__ w,
                              __half* __restrict__ hi,
                              __half* __restrict__ lo, int n)
{
    int i = blockIdx.x * 256 + threadIdx.x;
    int n4 = n >> 2;
    if (i < n4) {
        float4 v = ((const float4*)w)[i];
        __half h0 = __float2half_rn(v.x), h1 = __float2half_rn(v.y);
        __half h2 = __float2half_rn(v.z), h3 = __float2half_rn(v.w);
        __half2 hp0; hp0.x = h0; hp0.y = h1;
        __half2 hp1; hp1.x = h2; hp1.y = h3;
        ((__half2*)hi)[2 * i]     = hp0;
        ((__half2*)hi)[2 * i + 1] = hp1;
        __half2 lp0, lp1;
        lp0.x = __float2half_rn(v.x - __half2float(h0));
        lp0.y = __float2half_rn(v.y - __half2float(h1));
        lp1.x = __float2half_rn(v.z - __half2float(h2));
        lp1.y = __float2half_rn(v.w - __half2float(h3));
        ((__half2*)lo)[2 * i]     = lp0;
        ((__half2*)lo)[2 * i + 1] = lp1;
    }
}

// ---------------------------------------------------------------------------
// dwpw (R10 version, unchanged)
// ---------------------------------------------------------------------------
#define OFF_SIN   0
#define OFF_D3    17408
#define OFF_D5    41984
#define OFF_W5P   66560
#define OFF_W3P   71360
#define OFF_PWP   73088
#define OFF_PWB   82304
#define OFF_DB5   82688
#define OFF_DB3   82880
#define OFF_STASH 83072
#define DW_SMEM   91264

__global__ __launch_bounds__(256, 2)
void dwpw_kernel(const float* __restrict__ qkv,
                 const float* __restrict__ dw3_w, const float* __restrict__ dw3_b,
                 const float* __restrict__ pw3_w, const float* __restrict__ pw3_b,
                 const float* __restrict__ dw5_w, const float* __restrict__ dw5_b,
                 const float* __restrict__ pw5_w, const float* __restrict__ pw5_b,
                 float* __restrict__ s3q, float* __restrict__ s5q,
                 float* __restrict__ vkg)
{
    extern __shared__ __align__(16) char sm[];
    float* sin_  = (float*)(sm + OFF_SIN);
    float* d3s   = (float*)(sm + OFF_D3);
    float* d5s   = (float*)(sm + OFF_D5);
    ull*   kvq   = (ull*)(sm + OFF_D3);
    float* red   = (float*)(sm + OFF_PWP);
    float* stash = (float*)(sm + OFF_STASH);
    ull*   w5p   = (ull*)(sm + OFF_W5P);
    ull*   w3p   = (ull*)(sm + OFF_W3P);
    ull*   pwp   = (ull*)(sm + OFF_PWP);
    ull*   pwb   = (ull*)(sm + OFF_PWB);
    ull*   db5   = (ull*)(sm + OFF_DB5);
    ull*   db3   = (ull*)(sm + OFF_DB3);

    const int ytile = blockIdx.x;
    const int g     = blockIdx.y;
    const int b     = blockIdx.z;
    const int tid   = threadIdx.x;
    const int y0    = ytile * 4;

    for (int i = tid; i < 600; i += 256) {
        float w = dw5_w[(g * 24 + i / 25) * 25 + i % 25];
        w5p[i] = pk2(w, w);
    }
    for (int i = tid; i < 216; i += 256) {
        float w = dw3_w[(g * 24 + i / 9) * 9 + i % 9];
        w3p[i] = pk2(w, w);
    }
    for (int i = tid; i < 576; i += 256) {
        float a = pw3_w[g * 576 + i];
        float c = pw5_w[g * 576 + i];
        pwp[i] = pk2(a, a);
        pwp[576 + i] = pk2(c, c);
    }
    if (tid < 24) {
        float b3 = pw3_b[g * 24 + tid], b5 = pw5_b[g * 24 + tid];
        pwb[tid] = pk2(b3, b3);
        pwb[24 + tid] = pk2(b5, b5);
        float d3b = dw3_b[g * 24 + tid], d5b = dw5_b[g * 24 + tid];
        db3[tid] = pk2(d3b, d3b);
        db5[tid] = pk2(d5b, d5b);
    }

    const int c  = tid >> 5;
    const int t  = tid & 31;
    const int py = t >> 3;
    const int xo = (t & 7) * 8;

    for (int grp = 0; grp < 3; grp++) {
        __syncthreads();
        const int icb = grp * 8;
        const float* src = qkv + ((size_t)b * C3 + g * 24 + icb) * NPIX;
        for (int i = tid; i < 8 * 8 * 68; i += 256) {
            int xx = i % 68;
            int r  = (i / 68) & 7;
            int cc = i / (68 * 8);
            int yy = y0 - 2 + r;
            int xg = xx - 2;
            float v = 0.f;
            if ((unsigned)yy < 64u && (unsigned)xg < 64u)
                v = src[(size_t)cc * NPIX + yy * WIDTH + xg];
            sin_[(cc * 8 + r) * 68 + xx] = v;
        }
        __syncthreads();

        const int ch = icb + c;
        ull acc5[4], acc3[4];
        {
            ull b5v = db5[ch], b3v = db3[ch];
#pragma unroll
            for (int j = 0; j < 4; j++) { acc5[j] = b5v; acc3[j] = b3v; }
        }
#pragma unroll
        for (int dy = 0; dy < 5; dy++) {
            const ull* row = (const ull*)&sin_[(c * 8 + py + dy) * 68 + xo];
            ull r0 = row[0], r1 = row[1], r2 = row[2],
                r3 = row[3], r4 = row[4], r5 = row[5];
            ull m0 = pk2(f2hi(r0), f2lo(r1));
            ull m1 = pk2(f2hi(r1), f2lo(r2));
            ull m2 = pk2(f2hi(r2), f2lo(r3));
            ull m3 = pk2(f2hi(r3), f2lo(r4));
            ull m4 = pk2(f2hi(r4), f2lo(r5));
            const ull* w5r = &w5p[ch * 25 + dy * 5];
            ull w0 = w5r[0], w1 = w5r[1], w2 = w5r[2], w3v = w5r[3], w4 = w5r[4];

            ffma2(acc5[0], w0, r0); ffma2(acc5[0], w1, m0); ffma2(acc5[0], w2, r1);
            ffma2(acc5[0], w3v, m1); ffma2(acc5[0], w4, r2);
            ffma2(acc5[1], w0, r1); ffma2(acc5[1], w1, m1); ffma2(acc5[1], w2, r2);
            ffma2(acc5[1], w3v, m2); ffma2(acc5[1], w4, r3);
            ffma2(acc5[2], w0, r2); ffma2(acc5[2], w1, m2); ffma2(acc5[2], w2, r3);
            ffma2(acc5[2], w3v, m3); ffma2(acc5[2], w4, r4);
            ffma2(acc5[3], w0, r3); ffma2(acc5[3], w1, m3); ffma2(acc5[3], w2, r4);
            ffma2(acc5[3], w3v, m4); ffma2(acc5[3], w4, r5);

            if (dy >= 1 && dy <= 3) {
                const ull* w3r = &w3p[ch * 9 + (dy - 1) * 3];
                ull u0 = w3r[0], u1 = w3r[1], u2 = w3r[2];
                ffma2(acc3[0], u0, m0); ffma2(acc3[0], u1, r1); ffma2(acc3[0], u2, m1);
                ffma2(acc3[1], u0, m1); ffma2(acc3[1], u1, r2); ffma2(acc3[1], u2, m2);
                ffma2(acc3[2], u0, m2); ffma2(acc3[2], u1, r3); ffma2(acc3[2], u2, m3);
                ffma2(acc3[3], u0, m3); ffma2(acc3[3], u1, r4); ffma2(acc3[3], u2, m4);
            }
        }
        const int ppb = py * 32 + (xo >> 1);
#pragma unroll
        for (int j = 0; j < 4; j++) {
            *(ull*)&d3s[ch * 256 + (ppb + j) * 2] = acc3[j];
            *(ull*)&d5s[ch * 256 + (ppb + j) * 2] = acc5[j];
        }

        if (grp == 1) {
            for (int i = tid; i < 8 * 256; i += 256) {
                int cc = i >> 8, px = i & 255;
                stash[i] = sin_[(cc * 8 + 2 + (px >> 6)) * 68 + 2 + (px & 63)];
            }
        }

        if (grp == 2) {
            const int px = tid;
            const int vy = px >> 6;
            const int vx = px & 63;
            float kk[8], vv[8];
#pragma unroll
            for (int e = 0; e < 8; e++)
                kk[e] = fmaxf(stash[e * 256 + px], 0.f);
#pragma unroll
            for (int d = 0; d < 8; d++)
                vv[d] = sin_[(d * 8 + 2 + vy) * 68 + 2 + vx];

            float vacc[9][8];
#pragma unroll
            for (int d = 0; d < 8; d++)
#pragma unroll
                for (int e = 0; e < 8; e++)
                    vacc[d][e] = vv[d] * kk[e];
#pragma unroll
            for (int e = 0; e < 8; e++) vacc[8][e] = kk[e];

#pragma unroll
            for (int d = 0; d < 9; d++)
#pragma unroll
                for (int e = 0; e < 8; e++) {
                    float v = vacc[d][e];
                    v += __shfl_xor_sync(0xffffffffu, v, 16);
                    v += __shfl_xor_sync(0xffffffffu, v, 8);
                    v += __shfl_xor_sync(0xffffffffu, v, 4);
                    v += __shfl_xor_sync(0xffffffffu, v, 2);
                    v += __shfl_xor_sync(0xffffffffu, v, 1);
                    vacc[d][e] = v;
                }
            __syncthreads();
            const int w    = tid >> 5;
            const int lane = tid & 31;
            if (lane == 0) {
#pragma unroll
                for (int d = 0; d < 9; d++)
#pragma unroll
                    for (int e = 0; e < 8; e++)
                        stash[w * 72 + d * 8 + e] = vacc[d][e];
            }
            __syncthreads();
            if (tid < 72) {
                float s = 0.f;
#pragma unroll
                for (int j = 0; j < 8; j++) s += stash[j * 72 + tid];
                atomicAdd(&vkg[((size_t)b * 96 + g) * 72 + tid], s);
            }
        }
    }
    __syncthreads();

    const int conv = tid >> 7;
    const int tt   = tid & 127;
    const int og   = tt >> 5;
    const int pg   = tt & 31;
    const float* dsrc = conv ? d5s : d3s;
    const ull* wp = &pwp[conv * 576];
    const ull* bb = &pwb[conv * 24];
    float* qout = conv ? s5q : s3q;

    ull acc[6][4];
#pragma unroll
    for (int j = 0; j < 6; j++) {
        ull bv = bb[og * 6 + j];
#pragma unroll
        for (int i = 0; i < 4; i++) acc[j][i] = bv;
    }

#pragma unroll
    for (int ic = 0; ic < 24; ic++) {
        const ulonglong2 dA = *(const ulonglong2*)&dsrc[ic * 256 + pg * 8];
        const ulonglong2 dB = *(const ulonglong2*)&dsrc[ic * 256 + pg * 8 + 4];
        ull dv[4] = {dA.x, dA.y, dB.x, dB.y};
#pragma unroll
        for (int j = 0; j < 6; j++) {
            ull wv = wp[(og * 6 + j) * 24 + ic];
#pragma unroll
            for (int i = 0; i < 4; i++)
                ffma2(acc[j][i], wv, dv[i]);
        }
    }
    __syncthreads();

    {
        const int pair0 = pg * 4;
        const int by = y0 + (pair0 >> 5);
        const int bx = (pair0 & 31) * 2;
        const size_t qbase = (((size_t)b * 32 + g) * 8) * NPIX + by * WIDTH + bx;
#pragma unroll
        for (int j = 0; j < 6; j++) {
            const int o = og * 6 + j;
            if (o < 8) {
#pragma unroll
                for (int i = 0; i < 4; i++)
                    *(float2*)&qout[qbase + (size_t)o * NPIX + i * 2] =
                        make_float2(f2lo(acc[j][i]), f2hi(acc[j][i]));
            } else {
#pragma unroll
                for (int i = 0; i < 4; i++)
                    kvq[(conv * 16 + (o - 8)) * 128 + pair0 + i] = acc[j][i];
            }
        }
    }
    __syncthreads();

    {
        const int w    = tid >> 5;
        const int lane = tid & 31;
        const int cv   = w >> 2;
        const int sub  = w & 3;
        const int pair = sub * 32 + lane;

        ull kvv[16];
#pragma unroll
        for (int ch = 0; ch < 16; ch++)
            kvv[ch] = kvq[(cv * 16 + ch) * 128 + pair];

        float acc2[9][8];
#pragma unroll
        for (int d = 0; d < 9; d++)
#pragma unroll
            for (int e = 0; e < 8; e++) acc2[d][e] = 0.f;

#pragma unroll
        for (int hx = 0; hx < 2; hx++) {
            float kk[8], vv[8];
#pragma unroll
            for (int e = 0; e < 8; e++)
                kk[e] = fmaxf(hx ? f2hi(kvv[e]) : f2lo(kvv[e]), 0.f);
#pragma unroll
            for (int d = 0; d < 8; d++)
                vv[d] = hx ? f2hi(kvv[8 + d]) : f2lo(kvv[8 + d]);
#pragma unroll
            for (int d = 0; d < 8; d++)
#pragma unroll
                for (int e = 0; e < 8; e++)
                    acc2[d][e] += vv[d] * kk[e];
#pragma unroll
            for (int e = 0; e < 8; e++)
                acc2[8][e] += kk[e];
        }

#pragma unroll
        for (int d = 0; d < 9; d++)
#pragma unroll
            for (int e = 0; e < 8; e++) {
                float v = acc2[d][e];
                v += __shfl_xor_sync(0xffffffffu, v, 16);
                v += __shfl_xor_sync(0xffffffffu, v, 8);
                v += __shfl_xor_sync(0xffffffffu, v, 4);
                acc2[d][e] = v;
            }
        if (lane < 4) {
            float* rp = &red[((cv * 16) + sub * 4 + lane) * 72];
#pragma unroll
            for (int d = 0; d < 9; d++)
#pragma unroll
                for (int e = 0; e < 8; e++)
                    rp[d * 8 + e] = acc2[d][e];
        }
    }
    __syncthreads();

    if (tid < 144) {
        const int cv  = tid / 72;
        const int idx = tid % 72;
        float s = 0.f;
#pragma unroll
        for (int j = 0; j < 16; j++)
            s += red[(cv * 16 + j) * 72 + idx];
        atomicAdd(&vkg[((size_t)b * 96 + 32 + cv * 32 + g) * 72 + idx], s);
    }
}

// ---------------------------------------------------------------------------
// attention normalize: 4 CTAs/SM, packed f32x2, z-split 4 (R10 version).
// ---------------------------------------------------------------------------
__global__ __launch_bounds__(256, 4)
void att_kernel(const float* __restrict__ qkv, const float* __restrict__ s3q,
                const float* __restrict__ s5q, const float* __restrict__ vk,
                __half* __restrict__ atth)
{
    const int hh = blockIdx.x;
    const int b  = blockIdx.y;
    const int n0 = blockIdx.z * (NPIX / 4);
    const int src_id = hh >> 5;
    const int g      = hh & 31;
    const float* base;
    if (src_id == 0)      base = qkv + ((size_t)b * C3 + g * 24) * NPIX;
    else if (src_id == 1) base = s3q + (((size_t)b * 32 + g) * 8) * NPIX;
    else                  base = s5q + (((size_t)b * 32 + g) * 8) * NPIX;

    __shared__ ull vsp[72];
    const int tid = threadIdx.x;
    if (tid < 72) {
        float v = vk[((size_t)b * 96 + hh) * 72 + tid];
        vsp[tid] = pk2(v, v);
    }
    __syncthreads();

    __half* oh = atth + ((size_t)b * C3 + hh * 8) * NPIX;

#pragma unroll
    for (int it = 0; it < 2; it++) {
        const int n = n0 + (tid + it * 256) * 2;
        ull qp[8];
#pragma unroll
        for (int e = 0; e < 8; e++) {
            ull raw = *(const ull*)(base + (size_t)e * NPIX + n);
            qp[e] = pk2(fmaxf(f2lo(raw), 0.f), fmaxf(f2hi(raw), 0.f));
        }
        ull den = pk2(1e-15f, 1e-15f);
#pragma unroll
        for (int e = 0; e < 8; e++) ffma2(den, vsp[64 + e], qp[e]);
        const float rd0 = __fdividef(1.f, f2lo(den));
        const float rd1 = __fdividef(1.f, f2hi(den));
#pragma unroll
        for (int d = 0; d < 8; d++) {
            ull num = 0ull;
#pragma unroll
            for (int e = 0; e < 8; e++) ffma2(num, vsp[d * 8 + e], qp[e]);
            __half2 hp;
            hp.x = __float2half_rn(f2lo(num) * rd0);
            hp.y = __float2half_rn(f2hi(num) * rd1);
            *(__half2*)(oh + (size_t)d * NPIX + n) = hp;
        }
    }
}

// ---------------------------------------------------------------------------
struct PipeArgs {
    const float *x, *qkv_b, *dw3_w, *dw3_b, *pw3_w, *pw3_b;
    const float *dw5_w, *dw5_b, *pw5_w, *pw5_b, *proj_b;
    __half *xth, *xtl, *ath, *wqh, *wql, *wph, *wpl;
    float *qkv, *s3q, *s5q, *vkb, *out;
};

static void enqueue_part(cudaStream_t st, const PipeArgs& a, int b0, int nb,
                         cudaEvent_t evW)
{
    const size_t offX = (size_t)b0 * 256 * NPIX;
    const size_t offQ = (size_t)b0 * C3 * NPIX;
    const size_t off3 = (size_t)b0 * 32 * 8 * NPIX;
    const size_t offV = (size_t)b0 * 96 * 72;

    // x split has no weight dependency — issue before the weight barrier
    wsplit_kernel<<<(nb * 256 * NPIX / 4 + 255) / 256, 256, 0, st>>>(
        a.x + offX, a.xth + offX, a.xtl + offX, nb * 256 * NPIX);

    cudaStreamWaitEvent(st, evW, 0);   // weights ready before qkv GEMM

    gemm_f16<<<dim3(NPIX / 128, C3 / 128, nb), 256, 3 * STG2, st>>>(
        a.wqh, a.wql, a.xth + offX, a.xtl + offX, a.qkv_b, a.qkv + offQ,
        C3, NPIX, 256);

    dwpw_kernel<<<dim3(16, 32, nb), 256, DW_SMEM, st>>>(
        a.qkv + offQ, a.dw3_w, a.dw3_b, a.pw3_w, a.pw3_b,
        a.dw5_w, a.dw5_b, a.pw5_w, a.pw5_b,
        a.s3q + off3, a.s5q + off3, a.vkb + offV);

    att_kernel<<<dim3(96, nb, 4), 256, 0, st>>>(
        a.qkv + offQ, a.s3q + off3, a.s5q + off3, a.vkb + offV, a.ath + offQ);

    gemm_f16_2p<<<dim3(NPIX / 128, 256 / 128, nb), 256, 3 * P2_STG, st>>>(
        a.wph, a.wpl, a.ath + offQ, a.proj_b, a.out + (size_t)b0 * 256 * NPIX,
        256, NPIX, C3);
}

extern "C" void kernel_launch(void* const* d_in, const int* in_sizes, int n_in,
                              void* d_out, int out_size)
{
    PipeArgs a;
    a.x      = (const float*)d_in[0];
    const float* qkv_w = (const float*)d_in[1];
    a.qkv_b  = (const float*)d_in[2];
    a.dw3_w  = (const float*)d_in[3];
    a.dw3_b  = (const float*)d_in[4];
    a.pw3_w  = (const float*)d_in[5];
    a.pw3_b  = (const float*)d_in[6];
    a.dw5_w  = (const float*)d_in[7];
    a.dw5_b  = (const float*)d_in[8];
    a.pw5_w  = (const float*)d_in[9];
    a.pw5_b  = (const float*)d_in[10];
    const float* proj_w = (const float*)d_in[11];
    a.proj_b = (const float*)d_in[12];
    a.out    = (float*)d_out;

    void *p;
    cudaGetSymbolAddress(&p, g_qkv);  a.qkv = (float*)p;
    cudaGetSymbolAddress(&p, g_s3q);  a.s3q = (float*)p;
    cudaGetSymbolAddress(&p, g_s5q);  a.s5q = (float*)p;
    cudaGetSymbolAddress(&p, g_vk);   a.vkb = (float*)p;
    cudaGetSymbolAddress(&p, g_xt_h); a.xth = (__half*)p;
    cudaGetSymbolAddress(&p, g_xt_l); a.xtl = (__half*)p;
    cudaGetSymbolAddress(&p, g_at_h); a.ath = (__half*)p;
    cudaGetSymbolAddress(&p, g_wq_h); a.wqh = (__half*)p;
    cudaGetSymbolAddress(&p, g_wq_l); a.wql = (__half*)p;
    cudaGetSymbolAddress(&p, g_wp_h); a.wph = (__half*)p;
    cudaGetSymbolAddress(&p, g_wp_l); a.wpl = (__half*)p;

    static bool inited = false;
    static cudaStream_t s[3];
    static cudaEvent_t evW, evF, evJ[3];
    if (!inited) {
        for (int i = 0; i < 3; i++) {
            cudaStreamCreateWithFlags(&s[i], cudaStreamNonBlocking);
            cudaEventCreateWithFlags(&evJ[i], cudaEventDisableTiming);
        }
        cudaEventCreateWithFlags(&evW, cudaEventDisableTiming);
        cudaEventCreateWithFlags(&evF, cudaEventDisableTiming);
        cudaFuncSetAttribute(gemm_f16,
            cudaFuncAttributeMaxDynamicSharedMemorySize, 3 * STG2);
        cudaFuncSetAttribute(gemm_f16_2p,
            cudaFuncAttributeMaxDynamicSharedMemorySize, 3 * P2_STG);
        cudaFuncSetAttribute(dwpw_kernel,
            cudaFuncAttributeMaxDynamicSharedMemorySize, DW_SMEM);
        inited = true;
    }

    // main stream head: vk zero, then fork so side streams start x-splits
    cudaMemsetAsync(a.vkb, 0, (size_t)BATCH * 96 * 72 * sizeof(float), 0);
    cudaEventRecord(evF, 0);
    for (int i = 0; i < 3; i++) cudaStreamWaitEvent(s[i], evF, 0);

    // weight splits on the main stream (overlap side-stream x-splits)
    wsplit_kernel<<<(C3 * 256 / 4 + 255) / 256, 256>>>(
        qkv_w, a.wqh, a.wql, C3 * 256);
    wsplit_kernel<<<(256 * C3 / 4 + 255) / 256, 256>>>(
        proj_w, a.wph, a.wpl, 256 * C3);
    cudaEventRecord(evW, 0);

    enqueue_part(0,    a, 0, 2, evW);
    enqueue_part(s[0], a, 2, 2, evW);
    enqueue_part(s[1], a, 4, 2, evW);
    enqueue_part(s[2], a, 6, 2, evW);

    for (int i = 0; i < 3; i++) {
        cudaEventRecord(evJ[i], s[i]);
        cudaStreamWaitEvent(0, evJ[i], 0);
    }
}

// round 15
// speedup vs baseline: 1.1006x; 1.0004x over previous
#include <cuda_runtime.h>
#include <cuda_fp16.h>
#include <cstdint>

// ---------------------------------------------------------------------------
// LiteMLA on sm_103a.  (R14 kernels; att z-split 8)
// Four-stream batch-split pipeline (2 batches each) to overlap stage tails.
// qkv GEMM: fp16 hi/lo x hi/lo, 3 mma products, 3-stage cp.async ring.
// proj GEMM: weights hi/lo x att fp16, 2 products, 3-stage ring.
// dwpw: depthwise f32x2 -> register-tiled pointwise -> fused vk (all heads).
// ---------------------------------------------------------------------------

#define BATCH 8
#define C3 768
#define NPIX 4096
#define WIDTH 64

__device__ float g_qkv[(size_t)BATCH * C3 * NPIX];
__device__ float g_s3q[(size_t)BATCH * 32 * 8 * NPIX];
__device__ float g_s5q[(size_t)BATCH * 32 * 8 * NPIX];
__device__ float g_vk [(size_t)BATCH * 96 * 72];

__device__ __half g_xt_h [(size_t)BATCH * 256 * NPIX];
__device__ __half g_xt_l [(size_t)BATCH * 256 * NPIX];
__device__ __half g_at_h [(size_t)BATCH * C3 * NPIX];
__device__ __half g_wq_h [C3 * 256];
__device__ __half g_wq_l [C3 * 256];
__device__ __half g_wp_h [256 * C3];
__device__ __half g_wp_l [256 * C3];

// ---------------------------------------------------------------------------
typedef unsigned long long ull;

__device__ __forceinline__ uint32_t smem_u32(const void* p) {
    uint32_t a;
    asm("{ .reg .u64 t; cvta.to.shared.u64 t, %1; cvt.u32.u64 %0, t; }"
        : "=r"(a) : "l"(p));
    return a;
}
__device__ __forceinline__ ull pk2(float lo, float hi) {
    ull r;
    asm("mov.b64 %0, {%1, %2};" : "=l"(r)
        : "r"(__float_as_uint(lo)), "r"(__float_as_uint(hi)));
    return r;
}
__device__ __forceinline__ void ffma2(ull& d, ull a, ull b) {
    asm("fma.rn.f32x2 %0, %1, %2, %0;" : "+l"(d) : "l"(a), "l"(b));
}
__device__ __forceinline__ float f2lo(ull v) {
    return __uint_as_float((unsigned)(v & 0xffffffffull));
}
__device__ __forceinline__ float f2hi(ull v) {
    return __uint_as_float((unsigned)(v >> 32));
}

#define CP_ASYNC16(s, g) \
    asm volatile("cp.async.cg.shared.global [%0], [%1], 16;" :: "r"(s), "l"(g))
#define CP_COMMIT() asm volatile("cp.async.commit_group;" ::: "memory")
#define CP_WAIT(n)  asm volatile("cp.async.wait_group %0;" :: "n"(n) : "memory")

__device__ __forceinline__ void ldsm4(uint32_t addr, uint32_t* r) {
    asm volatile("ldmatrix.sync.aligned.m8n8.x4.shared.b16 {%0,%1,%2,%3}, [%4];"
                 : "=r"(r[0]), "=r"(r[1]), "=r"(r[2]), "=r"(r[3]) : "r"(addr));
}
__device__ __forceinline__ void ldsm4t(uint32_t addr, uint32_t* r) {
    asm volatile("ldmatrix.sync.aligned.m8n8.x4.trans.shared.b16 {%0,%1,%2,%3}, [%4];"
                 : "=r"(r[0]), "=r"(r[1]), "=r"(r[2]), "=r"(r[3]) : "r"(addr));
}
__device__ __forceinline__ void mma_f16(float* d, const uint32_t* a,
                                        const uint32_t* b) {
    asm volatile(
        "mma.sync.aligned.m16n8k16.row.col.f32.f16.f16.f32 "
        "{%0,%1,%2,%3}, {%4,%5,%6,%7}, {%8,%9}, {%0,%1,%2,%3};"
        : "+f"(d[0]), "+f"(d[1]), "+f"(d[2]), "+f"(d[3])
        : "r"(a[0]), "r"(a[1]), "r"(a[2]), "r"(a[3]), "r"(b[0]), "r"(b[1]));
}

#define A_PITCH 80
#define B_PITCH 272

// ---------------------------------------------------------------------------
// 3-product GEMM (qkv): C[b] = (Ah+Al)(M,K) @ (Bh+Bl)(b,K,N) + bias
// 3-stage cp.async ring, 2 CTAs/SM.  (unchanged)
// ---------------------------------------------------------------------------
#define OFF_AL  10240
#define OFF_BH  20480
#define OFF_BL  29184
#define STG2    37888

__device__ __forceinline__ void stage_load(
    uint32_t sbase, const __half* gA_h, const __half* gA_l,
    const __half* gB_h, const __half* gB_l, int K, int N, int kc, int tid)
{
    const int op = tid >> 6;
    const int t  = tid & 63;
    if (op < 2) {
        const __half* g = ((op == 0) ? gA_h : gA_l) + kc * 32;
        const uint32_t sb = sbase + op * OFF_AL;
#pragma unroll
        for (int it = 0; it < 8; it++) {
            int chunk = t + it * 64;
            int row = chunk >> 2, c = chunk & 3;
            CP_ASYNC16(sb + row * A_PITCH + c * 16, g + (size_t)row * K + c * 8);
        }
    } else {
        const __half* g = ((op == 2) ? gB_h : gB_l) + (size_t)kc * 32 * N;
        const uint32_t sb = sbase + ((op == 2) ? OFF_BH : OFF_BL);
#pragma unroll
        for (int it = 0; it < 8; it++) {
            int chunk = t + it * 64;
            int row = chunk >> 4, c = chunk & 15;
            CP_ASYNC16(sb + row * B_PITCH + c * 16, g + (size_t)row * N + c * 8);
        }
    }
}

__global__ __launch_bounds__(256, 2)
void gemm_f16(const __half* __restrict__ Ah, const __half* __restrict__ Al,
              const __half* __restrict__ Bmh, const __half* __restrict__ Bml,
              const float* __restrict__ bias, float* __restrict__ C,
              int M, int N, int K)
{
    extern __shared__ __align__(16) char smem[];
    const uint32_t sm0 = smem_u32(smem);

    const int tid  = threadIdx.x;
    const int wid  = tid >> 5;
    const int lane = tid & 31;
    const int n0 = blockIdx.x * 128;
    const int m0 = blockIdx.y * 128;
    const int b  = blockIdx.z;

    const int wm = (wid >> 1) * 32;
    const int wn = (wid & 1) * 64;

    const __half* gA_h = Ah + (size_t)m0 * K;
    const __half* gA_l = Al + (size_t)m0 * K;
    const __half* gB_h = Bmh + (size_t)b * K * N + n0;
    const __half* gB_l = Bml + (size_t)b * K * N + n0;

    float acc[2][8][4];
#pragma unroll
    for (int t = 0; t < 2; t++)
#pragma unroll
        for (int nt = 0; nt < 8; nt++)
#pragma unroll
            for (int i = 0; i < 4; i++) acc[t][nt][i] = 0.f;

    const int nk = K / 32;

    stage_load(sm0, gA_h, gA_l, gB_h, gB_l, K, N, 0, tid);
    CP_COMMIT();
    if (nk > 1) {
        stage_load(sm0 + STG2, gA_h, gA_l, gB_h, gB_l, K, N, 1, tid);
        CP_COMMIT();
    }

    const int a_row = lane & 15;
    const int a_hi  = (lane >> 4) * 16;
    const int b_kr = (lane & 7) + ((lane >> 3) & 1) * 8;
    const int b_nc = (lane >> 4) * 8;

    for (int kc = 0; kc < nk; kc++) {
        if (kc + 2 < nk) {
            stage_load(sm0 + ((kc + 2) % 3) * STG2,
                       gA_h, gA_l, gB_h, gB_l, K, N, kc + 2, tid);
            CP_COMMIT();
        }
        if (kc + 2 < nk)      CP_WAIT(2);
        else if (kc + 1 < nk) CP_WAIT(1);
        else                  CP_WAIT(0);
        __syncthreads();

        const uint32_t sb  = sm0 + (kc % 3) * STG2;
        const uint32_t aAh = sb;
        const uint32_t aAl = sb + OFF_AL;
        const uint32_t aBh = sb + OFF_BH;
        const uint32_t aBl = sb + OFF_BL;

#pragma unroll
        for (int j = 0; j < 2; j++) {
            uint32_t ah[2][4], al[2][4];
#pragma unroll
            for (int t = 0; t < 2; t++) {
                uint32_t off = (uint32_t)(wm + t * 16 + a_row) * A_PITCH + j * 32 + a_hi;
                ldsm4(aAh + off, ah[t]);
                ldsm4(aAl + off, al[t]);
            }
            uint32_t bh[4][4], bl[4][4];
#pragma unroll
            for (int p = 0; p < 4; p++) {
                uint32_t off = (uint32_t)(j * 16 + b_kr) * B_PITCH +
                               (uint32_t)(wn + p * 16 + b_nc) * 2;
                ldsm4t(aBh + off, bh[p]);
                ldsm4t(aBl + off, bl[p]);
            }
#pragma unroll
            for (int t = 0; t < 2; t++)
#pragma unroll
                for (int nt = 0; nt < 8; nt++) {
                    const uint32_t* bhp = &bh[nt >> 1][(nt & 1) * 2];
                    const uint32_t* blp = &bl[nt >> 1][(nt & 1) * 2];
                    mma_f16(acc[t][nt], ah[t], bhp);
                    mma_f16(acc[t][nt], ah[t], blp);
                    mma_f16(acc[t][nt], al[t], bhp);
                }
        }
        __syncthreads();
    }

    const int l4 = lane >> 2;
    const int l2 = (lane & 3) * 2;
#pragma unroll
    for (int t = 0; t < 2; t++) {
        const int m_lo = m0 + wm + t * 16 + l4;
        const float bi_lo = bias[m_lo];
        const float bi_hi = bias[m_lo + 8];
        float* c_lo = C + ((size_t)b * M + m_lo) * N + n0 + wn + l2;
        float* c_hi = c_lo + (size_t)8 * N;
#pragma unroll
        for (int nt = 0; nt < 8; nt++) {
            float2 v0 = {acc[t][nt][0] + bi_lo, acc[t][nt][1] + bi_lo};
            float2 v1 = {acc[t][nt][2] + bi_hi, acc[t][nt][3] + bi_hi};
            *(float2*)(c_lo + nt * 8) = v0;
            *(float2*)(c_hi + nt * 8) = v1;
        }
    }
}

// ---------------------------------------------------------------------------
// 2-product GEMM (proj): 3-stage ring.  (unchanged)
// ---------------------------------------------------------------------------
#define P2_AL   10240
#define P2_BH   20480
#define P2_STG  29184

__device__ __forceinline__ void stage_load_2p(
    uint32_t sbase, const __half* gA_h, const __half* gA_l,
    const __half* gB_h, int K, int N, int kc, int tid)
{
    if (tid < 128) {
        const int op = tid >> 6;
        const int t  = tid & 63;
        const __half* g = ((op == 0) ? gA_h : gA_l) + kc * 32;
        const uint32_t sb = sbase + op * P2_AL;
#pragma unroll
        for (int it = 0; it < 8; it++) {
            int chunk = t + it * 64;
            int row = chunk >> 2, c = chunk & 3;
            CP_ASYNC16(sb + row * A_PITCH + c * 16, g + (size_t)row * K + c * 8);
        }
    } else {
        const int t = tid - 128;
        const __half* g = gB_h + (size_t)kc * 32 * N;
        const uint32_t sb = sbase + P2_BH;
#pragma unroll
        for (int it = 0; it < 4; it++) {
            int chunk = t + it * 128;
            int row = chunk >> 4, c = chunk & 15;
            CP_ASYNC16(sb + row * B_PITCH + c * 16, g + (size_t)row * N + c * 8);
        }
    }
}

__global__ __launch_bounds__(256, 2)
void gemm_f16_2p(const __half* __restrict__ Ah, const __half* __restrict__ Al,
                 const __half* __restrict__ Bmh,
                 const float* __restrict__ bias, float* __restrict__ C,
                 int M, int N, int K)
{
    extern __shared__ __align__(16) char smem[];
    const uint32_t sm0 = smem_u32(smem);

    const int tid  = threadIdx.x;
    const int wid  = tid >> 5;
    const int lane = tid & 31;
    const int n0 = blockIdx.x * 128;
    const int m0 = blockIdx.y * 128;
    const int b  = blockIdx.z;

    const int wm = (wid >> 1) * 32;
    const int wn = (wid & 1) * 64;

    const __half* gA_h = Ah + (size_t)m0 * K;
    const __half* gA_l = Al + (size_t)m0 * K;
    const __half* gB_h = Bmh + (size_t)b * K * N + n0;

    float acc[2][8][4];
#pragma unroll
    for (int t = 0; t < 2; t++)
#pragma unroll
        for (int nt = 0; nt < 8; nt++)
#pragma unroll
            for (int i = 0; i < 4; i++) acc[t][nt][i] = 0.f;

    const int nk = K / 32;

    stage_load_2p(sm0, gA_h, gA_l, gB_h, K, N, 0, tid);
    CP_COMMIT();
    if (nk > 1) {
        stage_load_2p(sm0 + P2_STG, gA_h, gA_l, gB_h, K, N, 1, tid);
        CP_COMMIT();
    }

    const int a_row = lane & 15;
    const int a_hi  = (lane >> 4) * 16;
    const int b_kr = (lane & 7) + ((lane >> 3) & 1) * 8;
    const int b_nc = (lane >> 4) * 8;

    for (int kc = 0; kc < nk; kc++) {
        if (kc + 2 < nk) {
            stage_load_2p(sm0 + ((kc + 2) % 3) * P2_STG,
                          gA_h, gA_l, gB_h, K, N, kc + 2, tid);
            CP_COMMIT();
        }
        if (kc + 2 < nk)      CP_WAIT(2);
        else if (kc + 1 < nk) CP_WAIT(1);
        else                  CP_WAIT(0);
        __syncthreads();

        const uint32_t sb  = sm0 + (kc % 3) * P2_STG;
        const uint32_t aAh = sb;
        const uint32_t aAl = sb + P2_AL;
        const uint32_t aBh = sb + P2_BH;

#pragma unroll
        for (int j = 0; j < 2; j++) {
            uint32_t ah[2][4], al[2][4];
#pragma unroll
            for (int t = 0; t < 2; t++) {
                uint32_t off = (uint32_t)(wm + t * 16 + a_row) * A_PITCH + j * 32 + a_hi;
                ldsm4(aAh + off, ah[t]);
                ldsm4(aAl + off, al[t]);
            }
            uint32_t bh[4][4];
#pragma unroll
            for (int p = 0; p < 4; p++) {
                uint32_t off = (uint32_t)(j * 16 + b_kr) * B_PITCH +
                               (uint32_t)(wn + p * 16 + b_nc) * 2;
                ldsm4t(aBh + off, bh[p]);
            }
#pragma unroll
            for (int t = 0; t < 2; t++)
#pragma unroll
                for (int nt = 0; nt < 8; nt++) {
                    const uint32_t* bhp = &bh[nt >> 1][(nt & 1) * 2];
                    mma_f16(acc[t][nt], ah[t], bhp);
                    mma_f16(acc[t][nt], al[t], bhp);
                }
        }
        __syncthreads();
    }

    const int l4 = lane >> 2;
    const int l2 = (lane & 3) * 2;
#pragma unroll
    for (int t = 0; t < 2; t++) {
        const int m_lo = m0 + wm + t * 16 + l4;
        const float bi_lo = bias[m_lo];
        const float bi_hi = bias[m_lo + 8];
        float* c_lo = C + ((size_t)b * M + m_lo) * N + n0 + wn + l2;
        float* c_hi = c_lo + (size_t)8 * N;
#pragma unroll
        for (int nt = 0; nt < 8; nt++) {
            float2 v0 = {acc[t][nt][0] + bi_lo, acc[t][nt][1] + bi_lo};
            float2 v1 = {acc[t][nt][2] + bi_hi, acc[t][nt][3] + bi_hi};
            *(float2*)(c_lo + nt * 8) = v0;
            *(float2*)(c_hi + nt * 8) = v1;
        }
    }
}

// ---------------------------------------------------------------------------
// vectorized split: 4 elements/thread.  (unchanged)
// ---------------------------------------------------------------------------
__global__ void wsplit_kernel(const float* __restrict__ w,
                              __half* __restrict__ hi,
                              __half* __restrict__ lo, int n)
{
    int i = blockIdx.x * 256 + threadIdx.x;
    int n4 = n >> 2;
    if (i < n4) {
        float4 v = ((const float4*)w)[i];
        __half h0 = __float2half_rn(v.x), h1 = __float2half_rn(v.y);
        __half h2 = __float2half_rn(v.z), h3 = __float2half_rn(v.w);
        __half2 hp0; hp0.x = h0; hp0.y = h1;
        __half2 hp1; hp1.x = h2; hp1.y = h3;
        ((__half2*)hi)[2 * i]     = hp0;
        ((__half2*)hi)[2 * i + 1] = hp1;
        __half2 lp0, lp1;
        lp0.x = __float2half_rn(v.x - __half2float(h0));
        lp0.y = __float2half_rn(v.y - __half2float(h1));
        lp1.x = __float2half_rn(v.z - __half2float(h2));
        lp1.y = __float2half_rn(v.w - __half2float(h3));
        ((__half2*)lo)[2 * i]     = lp0;
        ((__half2*)lo)[2 * i + 1] = lp1;
    }
}

// ---------------------------------------------------------------------------
// dwpw (unchanged)
// ---------------------------------------------------------------------------
#define OFF_SIN   0
#define OFF_D3    17408
#define OFF_D5    41984
#define OFF_W5P   66560
#define OFF_W3P   71360
#define OFF_PWP   73088
#define OFF_PWB   82304
#define OFF_DB5   82688
#define OFF_DB3   82880
#define OFF_STASH 83072
#define DW_SMEM   91264

__global__ __launch_bounds__(256, 2)
void dwpw_kernel(const float* __restrict__ qkv,
                 const float* __restrict__ dw3_w, const float* __restrict__ dw3_b,
                 const float* __restrict__ pw3_w, const float* __restrict__ pw3_b,
                 const float* __restrict__ dw5_w, const float* __restrict__ dw5_b,
                 const float* __restrict__ pw5_w, const float* __restrict__ pw5_b,
                 float* __restrict__ s3q, float* __restrict__ s5q,
                 float* __restrict__ vkg)
{
    extern __shared__ __align__(16) char sm[];
    float* sin_  = (float*)(sm + OFF_SIN);
    float* d3s   = (float*)(sm + OFF_D3);
    float* d5s   = (float*)(sm + OFF_D5);
    ull*   kvq   = (ull*)(sm + OFF_D3);
    float* red   = (float*)(sm + OFF_PWP);
    float* stash = (float*)(sm + OFF_STASH);
    ull*   w5p   = (ull*)(sm + OFF_W5P);
    ull*   w3p   = (ull*)(sm + OFF_W3P);
    ull*   pwp   = (ull*)(sm + OFF_PWP);
    ull*   pwb   = (ull*)(sm + OFF_PWB);
    ull*   db5   = (ull*)(sm + OFF_DB5);
    ull*   db3   = (ull*)(sm + OFF_DB3);

    const int ytile = blockIdx.x;
    const int g     = blockIdx.y;
    const int b     = blockIdx.z;
    const int tid   = threadIdx.x;
    const int y0    = ytile * 4;

    for (int i = tid; i < 600; i += 256) {
        float w = dw5_w[(g * 24 + i / 25) * 25 + i % 25];
        w5p[i] = pk2(w, w);
    }
    for (int i = tid; i < 216; i += 256) {
        float w = dw3_w[(g * 24 + i / 9) * 9 + i % 9];
        w3p[i] = pk2(w, w);
    }
    for (int i = tid; i < 576; i += 256) {
        float a = pw3_w[g * 576 + i];
        float c = pw5_w[g * 576 + i];
        pwp[i] = pk2(a, a);
        pwp[576 + i] = pk2(c, c);
    }
    if (tid < 24) {
        float b3 = pw3_b[g * 24 + tid], b5 = pw5_b[g * 24 + tid];
        pwb[tid] = pk2(b3, b3);
        pwb[24 + tid] = pk2(b5, b5);
        float d3b = dw3_b[g * 24 + tid], d5b = dw5_b[g * 24 + tid];
        db3[tid] = pk2(d3b, d3b);
        db5[tid] = pk2(d5b, d5b);
    }

    const int c  = tid >> 5;
    const int t  = tid & 31;
    const int py = t >> 3;
    const int xo = (t & 7) * 8;

    for (int grp = 0; grp < 3; grp++) {
        __syncthreads();
        const int icb = grp * 8;
        const float* src = qkv + ((size_t)b * C3 + g * 24 + icb) * NPIX;
        for (int i = tid; i < 8 * 8 * 68; i += 256) {
            int xx = i % 68;
            int r  = (i / 68) & 7;
            int cc = i / (68 * 8);
            int yy = y0 - 2 + r;
            int xg = xx - 2;
            float v = 0.f;
            if ((unsigned)yy < 64u && (unsigned)xg < 64u)
                v = src[(size_t)cc * NPIX + yy * WIDTH + xg];
            sin_[(cc * 8 + r) * 68 + xx] = v;
        }
        __syncthreads();

        const int ch = icb + c;
        ull acc5[4], acc3[4];
        {
            ull b5v = db5[ch], b3v = db3[ch];
#pragma unroll
            for (int j = 0; j < 4; j++) { acc5[j] = b5v; acc3[j] = b3v; }
        }
#pragma unroll
        for (int dy = 0; dy < 5; dy++) {
            const ull* row = (const ull*)&sin_[(c * 8 + py + dy) * 68 + xo];
            ull r0 = row[0], r1 = row[1], r2 = row[2],
                r3 = row[3], r4 = row[4], r5 = row[5];
            ull m0 = pk2(f2hi(r0), f2lo(r1));
            ull m1 = pk2(f2hi(r1), f2lo(r2));
            ull m2 = pk2(f2hi(r2), f2lo(r3));
            ull m3 = pk2(f2hi(r3), f2lo(r4));
            ull m4 = pk2(f2hi(r4), f2lo(r5));
            const ull* w5r = &w5p[ch * 25 + dy * 5];
            ull w0 = w5r[0], w1 = w5r[1], w2 = w5r[2], w3v = w5r[3], w4 = w5r[4];

            ffma2(acc5[0], w0, r0); ffma2(acc5[0], w1, m0); ffma2(acc5[0], w2, r1);
            ffma2(acc5[0], w3v, m1); ffma2(acc5[0], w4, r2);
            ffma2(acc5[1], w0, r1); ffma2(acc5[1], w1, m1); ffma2(acc5[1], w2, r2);
            ffma2(acc5[1], w3v, m2); ffma2(acc5[1], w4, r3);
            ffma2(acc5[2], w0, r2); ffma2(acc5[2], w1, m2); ffma2(acc5[2], w2, r3);
            ffma2(acc5[2], w3v, m3); ffma2(acc5[2], w4, r4);
            ffma2(acc5[3], w0, r3); ffma2(acc5[3], w1, m3); ffma2(acc5[3], w2, r4);
            ffma2(acc5[3], w3v, m4); ffma2(acc5[3], w4, r5);

            if (dy >= 1 && dy <= 3) {
                const ull* w3r = &w3p[ch * 9 + (dy - 1) * 3];
                ull u0 = w3r[0], u1 = w3r[1], u2 = w3r[2];
                ffma2(acc3[0], u0, m0); ffma2(acc3[0], u1, r1); ffma2(acc3[0], u2, m1);
                ffma2(acc3[1], u0, m1); ffma2(acc3[1], u1, r2); ffma2(acc3[1], u2, m2);
                ffma2(acc3[2], u0, m2); ffma2(acc3[2], u1, r3); ffma2(acc3[2], u2, m3);
                ffma2(acc3[3], u0, m3); ffma2(acc3[3], u1, r4); ffma2(acc3[3], u2, m4);
            }
        }
        const int ppb = py * 32 + (xo >> 1);
#pragma unroll
        for (int j = 0; j < 4; j++) {
            *(ull*)&d3s[ch * 256 + (ppb + j) * 2] = acc3[j];
            *(ull*)&d5s[ch * 256 + (ppb + j) * 2] = acc5[j];
        }

        if (grp == 1) {
            for (int i = tid; i < 8 * 256; i += 256) {
                int cc = i >> 8, px = i & 255;
                stash[i] = sin_[(cc * 8 + 2 + (px >> 6)) * 68 + 2 + (px & 63)];
            }
        }

        if (grp == 2) {
            const int px = tid;
            const int vy = px >> 6;
            const int vx = px & 63;
            float kk[8], vv[8];
#pragma unroll
            for (int e = 0; e < 8; e++)
                kk[e] = fmaxf(stash[e * 256 + px], 0.f);
#pragma unroll
            for (int d = 0; d < 8; d++)
                vv[d] = sin_[(d * 8 + 2 + vy) * 68 + 2 + vx];

            float vacc[9][8];
#pragma unroll
            for (int d = 0; d < 8; d++)
#pragma unroll
                for (int e = 0; e < 8; e++)
                    vacc[d][e] = vv[d] * kk[e];
#pragma unroll
            for (int e = 0; e < 8; e++) vacc[8][e] = kk[e];

#pragma unroll
            for (int d = 0; d < 9; d++)
#pragma unroll
                for (int e = 0; e < 8; e++) {
                    float v = vacc[d][e];
                    v += __shfl_xor_sync(0xffffffffu, v, 16);
                    v += __shfl_xor_sync(0xffffffffu, v, 8);
                    v += __shfl_xor_sync(0xffffffffu, v, 4);
                    v += __shfl_xor_sync(0xffffffffu, v, 2);
                    v += __shfl_xor_sync(0xffffffffu, v, 1);
                    vacc[d][e] = v;
                }
            __syncthreads();
            const int w    = tid >> 5;
            const int lane = tid & 31;
            if (lane == 0) {
#pragma unroll
                for (int d = 0; d < 9; d++)
#pragma unroll
                    for (int e = 0; e < 8; e++)
                        stash[w * 72 + d * 8 + e] = vacc[d][e];
            }
            __syncthreads();
            if (tid < 72) {
                float s = 0.f;
#pragma unroll
                for (int j = 0; j < 8; j++) s += stash[j * 72 + tid];
                atomicAdd(&vkg[((size_t)b * 96 + g) * 72 + tid], s);
            }
        }
    }
    __syncthreads();

    const int conv = tid >> 7;
    const int tt   = tid & 127;
    const int og   = tt >> 5;
    const int pg   = tt & 31;
    const float* dsrc = conv ? d5s : d3s;
    const ull* wp = &pwp[conv * 576];
    const ull* bb = &pwb[conv * 24];
    float* qout = conv ? s5q : s3q;

    ull acc[6][4];
#pragma unroll
    for (int j = 0; j < 6; j++) {
        ull bv = bb[og * 6 + j];
#pragma unroll
        for (int i = 0; i < 4; i++) acc[j][i] = bv;
    }

#pragma unroll
    for (int ic = 0; ic < 24; ic++) {
        const ulonglong2 dA = *(const ulonglong2*)&dsrc[ic * 256 + pg * 8];
        const ulonglong2 dB = *(const ulonglong2*)&dsrc[ic * 256 + pg * 8 + 4];
        ull dv[4] = {dA.x, dA.y, dB.x, dB.y};
#pragma unroll
        for (int j = 0; j < 6; j++) {
            ull wv = wp[(og * 6 + j) * 24 + ic];
#pragma unroll
            for (int i = 0; i < 4; i++)
                ffma2(acc[j][i], wv, dv[i]);
        }
    }
    __syncthreads();

    {
        const int pair0 = pg * 4;
        const int by = y0 + (pair0 >> 5);
        const int bx = (pair0 & 31) * 2;
        const size_t qbase = (((size_t)b * 32 + g) * 8) * NPIX + by * WIDTH + bx;
#pragma unroll
        for (int j = 0; j < 6; j++) {
            const int o = og * 6 + j;
            if (o < 8) {
#pragma unroll
                for (int i = 0; i < 4; i++)
                    *(float2*)&qout[qbase + (size_t)o * NPIX + i * 2] =
                        make_float2(f2lo(acc[j][i]), f2hi(acc[j][i]));
            } else {
#pragma unroll
                for (int i = 0; i < 4; i++)
                    kvq[(conv * 16 + (o - 8)) * 128 + pair0 + i] = acc[j][i];
            }
        }
    }
    __syncthreads();

    {
        const int w    = tid >> 5;
        const int lane = tid & 31;
        const int cv   = w >> 2;
        const int sub  = w & 3;
        const int pair = sub * 32 + lane;

        ull kvv[16];
#pragma unroll
        for (int ch = 0; ch < 16; ch++)
            kvv[ch] = kvq[(cv * 16 + ch) * 128 + pair];

        float acc2[9][8];
#pragma unroll
        for (int d = 0; d < 9; d++)
#pragma unroll
            for (int e = 0; e < 8; e++) acc2[d][e] = 0.f;

#pragma unroll
        for (int hx = 0; hx < 2; hx++) {
            float kk[8], vv[8];
#pragma unroll
            for (int e = 0; e < 8; e++)
                kk[e] = fmaxf(hx ? f2hi(kvv[e]) : f2lo(kvv[e]), 0.f);
#pragma unroll
            for (int d = 0; d < 8; d++)
                vv[d] = hx ? f2hi(kvv[8 + d]) : f2lo(kvv[8 + d]);
#pragma unroll
            for (int d = 0; d < 8; d++)
#pragma unroll
                for (int e = 0; e < 8; e++)
                    acc2[d][e] += vv[d] * kk[e];
#pragma unroll
            for (int e = 0; e < 8; e++)
                acc2[8][e] += kk[e];
        }

#pragma unroll
        for (int d = 0; d < 9; d++)
#pragma unroll
            for (int e = 0; e < 8; e++) {
                float v = acc2[d][e];
                v += __shfl_xor_sync(0xffffffffu, v, 16);
                v += __shfl_xor_sync(0xffffffffu, v, 8);
                v += __shfl_xor_sync(0xffffffffu, v, 4);
                acc2[d][e] = v;
            }
        if (lane < 4) {
            float* rp = &red[((cv * 16) + sub * 4 + lane) * 72];
#pragma unroll
            for (int d = 0; d < 9; d++)
#pragma unroll
                for (int e = 0; e < 8; e++)
                    rp[d * 8 + e] = acc2[d][e];
        }
    }
    __syncthreads();

    if (tid < 144) {
        const int cv  = tid / 72;
        const int idx = tid % 72;
        float s = 0.f;
#pragma unroll
        for (int j = 0; j < 16; j++)
            s += red[(cv * 16 + j) * 72 + idx];
        atomicAdd(&vkg[((size_t)b * 96 + 32 + cv * 32 + g) * 72 + idx], s);
    }
}

// ---------------------------------------------------------------------------
// attention normalize: 4 CTAs/SM, packed f32x2, z-split 8 (1 iter/thread).
// ---------------------------------------------------------------------------
__global__ __launch_bounds__(256, 4)
void att_kernel(const float* __restrict__ qkv, const float* __restrict__ s3q,
                const float* __restrict__ s5q, const float* __restrict__ vk,
                __half* __restrict__ atth)
{
    const int hh = blockIdx.x;
    const int b  = blockIdx.y;
    const int n0 = blockIdx.z * (NPIX / 8);
    const int src_id = hh >> 5;
    const int g      = hh & 31;
    const float* base;
    if (src_id == 0)      base = qkv + ((size_t)b * C3 + g * 24) * NPIX;
    else if (src_id == 1) base = s3q + (((size_t)b * 32 + g) * 8) * NPIX;
    else                  base = s5q + (((size_t)b * 32 + g) * 8) * NPIX;

    __shared__ ull vsp[72];
    const int tid = threadIdx.x;
    if (tid < 72) {
        float v = vk[((size_t)b * 96 + hh) * 72 + tid];
        vsp[tid] = pk2(v, v);
    }
    __syncthreads();

    __half* oh = atth + ((size_t)b * C3 + hh * 8) * NPIX;

    {
        const int n = n0 + tid * 2;
        ull qp[8];
#pragma unroll
        for (int e = 0; e < 8; e++) {
            ull raw = *(const ull*)(base + (size_t)e * NPIX + n);
            qp[e] = pk2(fmaxf(f2lo(raw), 0.f), fmaxf(f2hi(raw), 0.f));
        }
        ull den = pk2(1e-15f, 1e-15f);
#pragma unroll
        for (int e = 0; e < 8; e++) ffma2(den, vsp[64 + e], qp[e]);
        const float rd0 = __fdividef(1.f, f2lo(den));
        const float rd1 = __fdividef(1.f, f2hi(den));
#pragma unroll
        for (int d = 0; d < 8; d++) {
            ull num = 0ull;
#pragma unroll
            for (int e = 0; e < 8; e++) ffma2(num, vsp[d * 8 + e], qp[e]);
            __half2 hp;
            hp.x = __float2half_rn(f2lo(num) * rd0);
            hp.y = __float2half_rn(f2hi(num) * rd1);
            *(__half2*)(oh + (size_t)d * NPIX + n) = hp;
        }
    }
}

// ---------------------------------------------------------------------------
struct PipeArgs {
    const float *x, *qkv_b, *dw3_w, *dw3_b, *pw3_w, *pw3_b;
    const float *dw5_w, *dw5_b, *pw5_w, *pw5_b, *proj_b;
    __half *xth, *xtl, *ath, *wqh, *wql, *wph, *wpl;
    float *qkv, *s3q, *s5q, *vkb, *out;
};

static void enqueue_part(cudaStream_t st, const PipeArgs& a, int b0, int nb,
                         cudaEvent_t evW)
{
    const size_t offX = (size_t)b0 * 256 * NPIX;
    const size_t offQ = (size_t)b0 * C3 * NPIX;
    const size_t off3 = (size_t)b0 * 32 * 8 * NPIX;
    const size_t offV = (size_t)b0 * 96 * 72;

    // x split has no weight dependency — issue before the weight barrier
    wsplit_kernel<<<(nb * 256 * NPIX / 4 + 255) / 256, 256, 0, st>>>(
        a.x + offX, a.xth + offX, a.xtl + offX, nb * 256 * NPIX);

    cudaStreamWaitEvent(st, evW, 0);   // weights ready before qkv GEMM

    gemm_f16<<<dim3(NPIX / 128, C3 / 128, nb), 256, 3 * STG2, st>>>(
        a.wqh, a.wql, a.xth + offX, a.xtl + offX, a.qkv_b, a.qkv + offQ,
        C3, NPIX, 256);

    dwpw_kernel<<<dim3(16, 32, nb), 256, DW_SMEM, st>>>(
        a.qkv + offQ, a.dw3_w, a.dw3_b, a.pw3_w, a.pw3_b,
        a.dw5_w, a.dw5_b, a.pw5_w, a.pw5_b,
        a.s3q + off3, a.s5q + off3, a.vkb + offV);

    att_kernel<<<dim3(96, nb, 8), 256, 0, st>>>(
        a.qkv + offQ, a.s3q + off3, a.s5q + off3, a.vkb + offV, a.ath + offQ);

    gemm_f16_2p<<<dim3(NPIX / 128, 256 / 128, nb), 256, 3 * P2_STG, st>>>(
        a.wph, a.wpl, a.ath + offQ, a.proj_b, a.out + (size_t)b0 * 256 * NPIX,
        256, NPIX, C3);
}

extern "C" void kernel_launch(void* const* d_in, const int* in_sizes, int n_in,
                              void* d_out, int out_size)
{
    PipeArgs a;
    a.x      = (const float*)d_in[0];
    const float* qkv_w = (const float*)d_in[1];
    a.qkv_b  = (const float*)d_in[2];
    a.dw3_w  = (const float*)d_in[3];
    a.dw3_b  = (const float*)d_in[4];
    a.pw3_w  = (const float*)d_in[5];
    a.pw3_b  = (const float*)d_in[6];
    a.dw5_w  = (const float*)d_in[7];
    a.dw5_b  = (const float*)d_in[8];
    a.pw5_w  = (const float*)d_in[9];
    a.pw5_b  = (const float*)d_in[10];
    const float* proj_w = (const float*)d_in[11];
    a.proj_b = (const float*)d_in[12];
    a.out    = (float*)d_out;

    void *p;
    cudaGetSymbolAddress(&p, g_qkv);  a.qkv = (float*)p;
    cudaGetSymbolAddress(&p, g_s3q);  a.s3q = (float*)p;
    cudaGetSymbolAddress(&p, g_s5q);  a.s5q = (float*)p;
    cudaGetSymbolAddress(&p, g_vk);   a.vkb = (float*)p;
    cudaGetSymbolAddress(&p, g_xt_h); a.xth = (__half*)p;
    cudaGetSymbolAddress(&p, g_xt_l); a.xtl = (__half*)p;
    cudaGetSymbolAddress(&p, g_at_h); a.ath = (__half*)p;
    cudaGetSymbolAddress(&p, g_wq_h); a.wqh = (__half*)p;
    cudaGetSymbolAddress(&p, g_wq_l); a.wql = (__half*)p;
    cudaGetSymbolAddress(&p, g_wp_h); a.wph = (__half*)p;
    cudaGetSymbolAddress(&p, g_wp_l); a.wpl = (__half*)p;

    static bool inited = false;
    static cudaStream_t s[3];
    static cudaEvent_t evW, evF, evJ[3];
    if (!inited) {
        for (int i = 0; i < 3; i++) {
            cudaStreamCreateWithFlags(&s[i], cudaStreamNonBlocking);
            cudaEventCreateWithFlags(&evJ[i], cudaEventDisableTiming);
        }
        cudaEventCreateWithFlags(&evW, cudaEventDisableTiming);
        cudaEventCreateWithFlags(&evF, cudaEventDisableTiming);
        cudaFuncSetAttribute(gemm_f16,
            cudaFuncAttributeMaxDynamicSharedMemorySize, 3 * STG2);
        cudaFuncSetAttribute(gemm_f16_2p,
            cudaFuncAttributeMaxDynamicSharedMemorySize, 3 * P2_STG);
        cudaFuncSetAttribute(dwpw_kernel,
            cudaFuncAttributeMaxDynamicSharedMemorySize, DW_SMEM);
        inited = true;
    }

    // main stream head: vk zero, then fork so side streams start x-splits
    cudaMemsetAsync(a.vkb, 0, (size_t)BATCH * 96 * 72 * sizeof(float), 0);
    cudaEventRecord(evF, 0);
    for (int i = 0; i < 3; i++) cudaStreamWaitEvent(s[i], evF, 0);

    // weight splits on the main stream (overlap side-stream x-splits)
    wsplit_kernel<<<(C3 * 256 / 4 + 255) / 256, 256>>>(
        qkv_w, a.wqh, a.wql, C3 * 256);
    wsplit_kernel<<<(256 * C3 / 4 + 255) / 256, 256>>>(
        proj_w, a.wph, a.wpl, 256 * C3);
    cudaEventRecord(evW, 0);

    enqueue_part(0,    a, 0, 2, evW);
    enqueue_part(s[0], a, 2, 2, evW);
    enqueue_part(s[1], a, 4, 2, evW);
    enqueue_part(s[2], a, 6, 2, evW);

    for (int i = 0; i < 3; i++) {
        cudaEventRecord(evJ[i], s[i]);
        cudaStreamWaitEvent(0, evJ[i], 0);
    }
}

// round 16
// speedup vs baseline: 1.1057x; 1.0046x over previous
#include <cuda_runtime.h>
#include <cuda_fp16.h>
#include <cstdint>

// ---------------------------------------------------------------------------
// LiteMLA on sm_103a.  (validated best config; fused weight-split head)
// Four-stream batch-split pipeline (2 batches each) to overlap stage tails.
// qkv GEMM: fp16 hi/lo x hi/lo, 3 mma products, 3-stage cp.async ring.
// proj GEMM: weights hi/lo x att fp16, 2 products, 3-stage ring.
// dwpw: depthwise f32x2 -> register-tiled pointwise -> fused vk (all heads).
// ---------------------------------------------------------------------------

#define BATCH 8
#define C3 768
#define NPIX 4096
#define WIDTH 64

__device__ float g_qkv[(size_t)BATCH * C3 * NPIX];
__device__ float g_s3q[(size_t)BATCH * 32 * 8 * NPIX];
__device__ float g_s5q[(size_t)BATCH * 32 * 8 * NPIX];
__device__ float g_vk [(size_t)BATCH * 96 * 72];

__device__ __half g_xt_h [(size_t)BATCH * 256 * NPIX];
__device__ __half g_xt_l [(size_t)BATCH * 256 * NPIX];
__device__ __half g_at_h [(size_t)BATCH * C3 * NPIX];
__device__ __half g_wq_h [C3 * 256];
__device__ __half g_wq_l [C3 * 256];
__device__ __half g_wp_h [256 * C3];
__device__ __half g_wp_l [256 * C3];

// ---------------------------------------------------------------------------
typedef unsigned long long ull;

__device__ __forceinline__ uint32_t smem_u32(const void* p) {
    uint32_t a;
    asm("{ .reg .u64 t; cvta.to.shared.u64 t, %1; cvt.u32.u64 %0, t; }"
        : "=r"(a) : "l"(p));
    return a;
}
__device__ __forceinline__ ull pk2(float lo, float hi) {
    ull r;
    asm("mov.b64 %0, {%1, %2};" : "=l"(r)
        : "r"(__float_as_uint(lo)), "r"(__float_as_uint(hi)));
    return r;
}
__device__ __forceinline__ void ffma2(ull& d, ull a, ull b) {
    asm("fma.rn.f32x2 %0, %1, %2, %0;" : "+l"(d) : "l"(a), "l"(b));
}
__device__ __forceinline__ float f2lo(ull v) {
    return __uint_as_float((unsigned)(v & 0xffffffffull));
}
__device__ __forceinline__ float f2hi(ull v) {
    return __uint_as_float((unsigned)(v >> 32));
}

#define CP_ASYNC16(s, g) \
    asm volatile("cp.async.cg.shared.global [%0], [%1], 16;" :: "r"(s), "l"(g))
#define CP_COMMIT() asm volatile("cp.async.commit_group;" ::: "memory")
#define CP_WAIT(n)  asm volatile("cp.async.wait_group %0;" :: "n"(n) : "memory")

__device__ __forceinline__ void ldsm4(uint32_t addr, uint32_t* r) {
    asm volatile("ldmatrix.sync.aligned.m8n8.x4.shared.b16 {%0,%1,%2,%3}, [%4];"
                 : "=r"(r[0]), "=r"(r[1]), "=r"(r[2]), "=r"(r[3]) : "r"(addr));
}
__device__ __forceinline__ void ldsm4t(uint32_t addr, uint32_t* r) {
    asm volatile("ldmatrix.sync.aligned.m8n8.x4.trans.shared.b16 {%0,%1,%2,%3}, [%4];"
                 : "=r"(r[0]), "=r"(r[1]), "=r"(r[2]), "=r"(r[3]) : "r"(addr));
}
__device__ __forceinline__ void mma_f16(float* d, const uint32_t* a,
                                        const uint32_t* b) {
    asm volatile(
        "mma.sync.aligned.m16n8k16.row.col.f32.f16.f16.f32 "
        "{%0,%1,%2,%3}, {%4,%5,%6,%7}, {%8,%9}, {%0,%1,%2,%3};"
        : "+f"(d[0]), "+f"(d[1]), "+f"(d[2]), "+f"(d[3])
        : "r"(a[0]), "r"(a[1]), "r"(a[2]), "r"(a[3]), "r"(b[0]), "r"(b[1]));
}

#define A_PITCH 80
#define B_PITCH 272

// ---------------------------------------------------------------------------
// 3-product GEMM (qkv): C[b] = (Ah+Al)(M,K) @ (Bh+Bl)(b,K,N) + bias
// 3-stage cp.async ring, 2 CTAs/SM.  (unchanged)
// ---------------------------------------------------------------------------
#define OFF_AL  10240
#define OFF_BH  20480
#define OFF_BL  29184
#define STG2    37888

__device__ __forceinline__ void stage_load(
    uint32_t sbase, const __half* gA_h, const __half* gA_l,
    const __half* gB_h, const __half* gB_l, int K, int N, int kc, int tid)
{
    const int op = tid >> 6;
    const int t  = tid & 63;
    if (op < 2) {
        const __half* g = ((op == 0) ? gA_h : gA_l) + kc * 32;
        const uint32_t sb = sbase + op * OFF_AL;
#pragma unroll
        for (int it = 0; it < 8; it++) {
            int chunk = t + it * 64;
            int row = chunk >> 2, c = chunk & 3;
            CP_ASYNC16(sb + row * A_PITCH + c * 16, g + (size_t)row * K + c * 8);
        }
    } else {
        const __half* g = ((op == 2) ? gB_h : gB_l) + (size_t)kc * 32 * N;
        const uint32_t sb = sbase + ((op == 2) ? OFF_BH : OFF_BL);
#pragma unroll
        for (int it = 0; it < 8; it++) {
            int chunk = t + it * 64;
            int row = chunk >> 4, c = chunk & 15;
            CP_ASYNC16(sb + row * B_PITCH + c * 16, g + (size_t)row * N + c * 8);
        }
    }
}

__global__ __launch_bounds__(256, 2)
void gemm_f16(const __half* __restrict__ Ah, const __half* __restrict__ Al,
              const __half* __restrict__ Bmh, const __half* __restrict__ Bml,
              const float* __restrict__ bias, float* __restrict__ C,
              int M, int N, int K)
{
    extern __shared__ __align__(16) char smem[];
    const uint32_t sm0 = smem_u32(smem);

    const int tid  = threadIdx.x;
    const int wid  = tid >> 5;
    const int lane = tid & 31;
    const int n0 = blockIdx.x * 128;
    const int m0 = blockIdx.y * 128;
    const int b  = blockIdx.z;

    const int wm = (wid >> 1) * 32;
    const int wn = (wid & 1) * 64;

    const __half* gA_h = Ah + (size_t)m0 * K;
    const __half* gA_l = Al + (size_t)m0 * K;
    const __half* gB_h = Bmh + (size_t)b * K * N + n0;
    const __half* gB_l = Bml + (size_t)b * K * N + n0;

    float acc[2][8][4];
#pragma unroll
    for (int t = 0; t < 2; t++)
#pragma unroll
        for (int nt = 0; nt < 8; nt++)
#pragma unroll
            for (int i = 0; i < 4; i++) acc[t][nt][i] = 0.f;

    const int nk = K / 32;

    stage_load(sm0, gA_h, gA_l, gB_h, gB_l, K, N, 0, tid);
    CP_COMMIT();
    if (nk > 1) {
        stage_load(sm0 + STG2, gA_h, gA_l, gB_h, gB_l, K, N, 1, tid);
        CP_COMMIT();
    }

    const int a_row = lane & 15;
    const int a_hi  = (lane >> 4) * 16;
    const int b_kr = (lane & 7) + ((lane >> 3) & 1) * 8;
    const int b_nc = (lane >> 4) * 8;

    for (int kc = 0; kc < nk; kc++) {
        if (kc + 2 < nk) {
            stage_load(sm0 + ((kc + 2) % 3) * STG2,
                       gA_h, gA_l, gB_h, gB_l, K, N, kc + 2, tid);
            CP_COMMIT();
        }
        if (kc + 2 < nk)      CP_WAIT(2);
        else if (kc + 1 < nk) CP_WAIT(1);
        else                  CP_WAIT(0);
        __syncthreads();

        const uint32_t sb  = sm0 + (kc % 3) * STG2;
        const uint32_t aAh = sb;
        const uint32_t aAl = sb + OFF_AL;
        const uint32_t aBh = sb + OFF_BH;
        const uint32_t aBl = sb + OFF_BL;

#pragma unroll
        for (int j = 0; j < 2; j++) {
            uint32_t ah[2][4], al[2][4];
#pragma unroll
            for (int t = 0; t < 2; t++) {
                uint32_t off = (uint32_t)(wm + t * 16 + a_row) * A_PITCH + j * 32 + a_hi;
                ldsm4(aAh + off, ah[t]);
                ldsm4(aAl + off, al[t]);
            }
            uint32_t bh[4][4], bl[4][4];
#pragma unroll
            for (int p = 0; p < 4; p++) {
                uint32_t off = (uint32_t)(j * 16 + b_kr) * B_PITCH +
                               (uint32_t)(wn + p * 16 + b_nc) * 2;
                ldsm4t(aBh + off, bh[p]);
                ldsm4t(aBl + off, bl[p]);
            }
#pragma unroll
            for (int t = 0; t < 2; t++)
#pragma unroll
                for (int nt = 0; nt < 8; nt++) {
                    const uint32_t* bhp = &bh[nt >> 1][(nt & 1) * 2];
                    const uint32_t* blp = &bl[nt >> 1][(nt & 1) * 2];
                    mma_f16(acc[t][nt], ah[t], bhp);
                    mma_f16(acc[t][nt], ah[t], blp);
                    mma_f16(acc[t][nt], al[t], bhp);
                }
        }
        __syncthreads();
    }

    const int l4 = lane >> 2;
    const int l2 = (lane & 3) * 2;
#pragma unroll
    for (int t = 0; t < 2; t++) {
        const int m_lo = m0 + wm + t * 16 + l4;
        const float bi_lo = bias[m_lo];
        const float bi_hi = bias[m_lo + 8];
        float* c_lo = C + ((size_t)b * M + m_lo) * N + n0 + wn + l2;
        float* c_hi = c_lo + (size_t)8 * N;
#pragma unroll
        for (int nt = 0; nt < 8; nt++) {
            float2 v0 = {acc[t][nt][0] + bi_lo, acc[t][nt][1] + bi_lo};
            float2 v1 = {acc[t][nt][2] + bi_hi, acc[t][nt][3] + bi_hi};
            *(float2*)(c_lo + nt * 8) = v0;
            *(float2*)(c_hi + nt * 8) = v1;
        }
    }
}

// ---------------------------------------------------------------------------
// 2-product GEMM (proj): 3-stage ring.  (unchanged)
// ---------------------------------------------------------------------------
#define P2_AL   10240
#define P2_BH   20480
#define P2_STG  29184

__device__ __forceinline__ void stage_load_2p(
    uint32_t sbase, const __half* gA_h, const __half* gA_l,
    const __half* gB_h, int K, int N, int kc, int tid)
{
    if (tid < 128) {
        const int op = tid >> 6;
        const int t  = tid & 63;
        const __half* g = ((op == 0) ? gA_h : gA_l) + kc * 32;
        const uint32_t sb = sbase + op * P2_AL;
#pragma unroll
        for (int it = 0; it < 8; it++) {
            int chunk = t + it * 64;
            int row = chunk >> 2, c = chunk & 3;
            CP_ASYNC16(sb + row * A_PITCH + c * 16, g + (size_t)row * K + c * 8);
        }
    } else {
        const int t = tid - 128;
        const __half* g = gB_h + (size_t)kc * 32 * N;
        const uint32_t sb = sbase + P2_BH;
#pragma unroll
        for (int it = 0; it < 4; it++) {
            int chunk = t + it * 128;
            int row = chunk >> 4, c = chunk & 15;
            CP_ASYNC16(sb + row * B_PITCH + c * 16, g + (size_t)row * N + c * 8);
        }
    }
}

__global__ __launch_bounds__(256, 2)
void gemm_f16_2p(const __half* __restrict__ Ah, const __half* __restrict__ Al,
                 const __half* __restrict__ Bmh,
                 const float* __restrict__ bias, float* __restrict__ C,
                 int M, int N, int K)
{
    extern __shared__ __align__(16) char smem[];
    const uint32_t sm0 = smem_u32(smem);

    const int tid  = threadIdx.x;
    const int wid  = tid >> 5;
    const int lane = tid & 31;
    const int n0 = blockIdx.x * 128;
    const int m0 = blockIdx.y * 128;
    const int b  = blockIdx.z;

    const int wm = (wid >> 1) * 32;
    const int wn = (wid & 1) * 64;

    const __half* gA_h = Ah + (size_t)m0 * K;
    const __half* gA_l = Al + (size_t)m0 * K;
    const __half* gB_h = Bmh + (size_t)b * K * N + n0;

    float acc[2][8][4];
#pragma unroll
    for (int t = 0; t < 2; t++)
#pragma unroll
        for (int nt = 0; nt < 8; nt++)
#pragma unroll
            for (int i = 0; i < 4; i++) acc[t][nt][i] = 0.f;

    const int nk = K / 32;

    stage_load_2p(sm0, gA_h, gA_l, gB_h, K, N, 0, tid);
    CP_COMMIT();
    if (nk > 1) {
        stage_load_2p(sm0 + P2_STG, gA_h, gA_l, gB_h, K, N, 1, tid);
        CP_COMMIT();
    }

    const int a_row = lane & 15;
    const int a_hi  = (lane >> 4) * 16;
    const int b_kr = (lane & 7) + ((lane >> 3) & 1) * 8;
    const int b_nc = (lane >> 4) * 8;

    for (int kc = 0; kc < nk; kc++) {
        if (kc + 2 < nk) {
            stage_load_2p(sm0 + ((kc + 2) % 3) * P2_STG,
                          gA_h, gA_l, gB_h, K, N, kc + 2, tid);
            CP_COMMIT();
        }
        if (kc + 2 < nk)      CP_WAIT(2);
        else if (kc + 1 < nk) CP_WAIT(1);
        else                  CP_WAIT(0);
        __syncthreads();

        const uint32_t sb  = sm0 + (kc % 3) * P2_STG;
        const uint32_t aAh = sb;
        const uint32_t aAl = sb + P2_AL;
        const uint32_t aBh = sb + P2_BH;

#pragma unroll
        for (int j = 0; j < 2; j++) {
            uint32_t ah[2][4], al[2][4];
#pragma unroll
            for (int t = 0; t < 2; t++) {
                uint32_t off = (uint32_t)(wm + t * 16 + a_row) * A_PITCH + j * 32 + a_hi;
                ldsm4(aAh + off, ah[t]);
                ldsm4(aAl + off, al[t]);
            }
            uint32_t bh[4][4];
#pragma unroll
            for (int p = 0; p < 4; p++) {
                uint32_t off = (uint32_t)(j * 16 + b_kr) * B_PITCH +
                               (uint32_t)(wn + p * 16 + b_nc) * 2;
                ldsm4t(aBh + off, bh[p]);
            }
#pragma unroll
            for (int t = 0; t < 2; t++)
#pragma unroll
                for (int nt = 0; nt < 8; nt++) {
                    const uint32_t* bhp = &bh[nt >> 1][(nt & 1) * 2];
                    mma_f16(acc[t][nt], ah[t], bhp);
                    mma_f16(acc[t][nt], al[t], bhp);
                }
        }
        __syncthreads();
    }

    const int l4 = lane >> 2;
    const int l2 = (lane & 3) * 2;
#pragma unroll
    for (int t = 0; t < 2; t++) {
        const int m_lo = m0 + wm + t * 16 + l4;
        const float bi_lo = bias[m_lo];
        const float bi_hi = bias[m_lo + 8];
        float* c_lo = C + ((size_t)b * M + m_lo) * N + n0 + wn + l2;
        float* c_hi = c_lo + (size_t)8 * N;
#pragma unroll
        for (int nt = 0; nt < 8; nt++) {
            float2 v0 = {acc[t][nt][0] + bi_lo, acc[t][nt][1] + bi_lo};
            float2 v1 = {acc[t][nt][2] + bi_hi, acc[t][nt][3] + bi_hi};
            *(float2*)(c_lo + nt * 8) = v0;
            *(float2*)(c_hi + nt * 8) = v1;
        }
    }
}

// ---------------------------------------------------------------------------
// vectorized split: 4 elements/thread.  (unchanged)
// ---------------------------------------------------------------------------
__global__ void wsplit_kernel(const float* __restrict__ w,
                              __half* __restrict__ hi,
                              __half* __restrict__ lo, int n)
{
    int i = blockIdx.x * 256 + threadIdx.x;
    int n4 = n >> 2;
    if (i < n4) {
        float4 v = ((const float4*)w)[i];
        __half h0 = __float2half_rn(v.x), h1 = __float2half_rn(v.y);
        __half h2 = __float2half_rn(v.z), h3 = __float2half_rn(v.w);
        __half2 hp0; hp0.x = h0; hp0.y = h1;
        __half2 hp1; hp1.x = h2; hp1.y = h3;
        ((__half2*)hi)[2 * i]     = hp0;
        ((__half2*)hi)[2 * i + 1] = hp1;
        __half2 lp0, lp1;
        lp0.x = __float2half_rn(v.x - __half2float(h0));
        lp0.y = __float2half_rn(v.y - __half2float(h1));
        lp1.x = __float2half_rn(v.z - __half2float(h2));
        lp1.y = __float2half_rn(v.w - __half2float(h3));
        ((__half2*)lo)[2 * i]     = lp0;
        ((__half2*)lo)[2 * i + 1] = lp1;
    }
}

// fused double split: blocks [0,192) -> wa (C3*256), blocks [192,384) -> wb
__global__ void wsplit2_kernel(const float* __restrict__ wa,
                               __half* __restrict__ ha, __half* __restrict__ la,
                               const float* __restrict__ wb,
                               __half* __restrict__ hb, __half* __restrict__ lb)
{
    const int half = (blockIdx.x >= 192);
    const int i = (blockIdx.x - half * 192) * 256 + threadIdx.x;
    const float* w = half ? wb : wa;
    __half* hi = half ? hb : ha;
    __half* lo = half ? lb : la;
    // each tensor: C3*256 = 196608 elems = 49152 float4 = 192 blocks x 256
    float4 v = ((const float4*)w)[i];
    __half h0 = __float2half_rn(v.x), h1 = __float2half_rn(v.y);
    __half h2 = __float2half_rn(v.z), h3 = __float2half_rn(v.w);
    __half2 hp0; hp0.x = h0; hp0.y = h1;
    __half2 hp1; hp1.x = h2; hp1.y = h3;
    ((__half2*)hi)[2 * i]     = hp0;
    ((__half2*)hi)[2 * i + 1] = hp1;
    __half2 lp0, lp1;
    lp0.x = __float2half_rn(v.x - __half2float(h0));
    lp0.y = __float2half_rn(v.y - __half2float(h1));
    lp1.x = __float2half_rn(v.z - __half2float(h2));
    lp1.y = __float2half_rn(v.w - __half2float(h3));
    ((__half2*)lo)[2 * i]     = lp0;
    ((__half2*)lo)[2 * i + 1] = lp1;
}

// ---------------------------------------------------------------------------
// dwpw (unchanged)
// ---------------------------------------------------------------------------
#define OFF_SIN   0
#define OFF_D3    17408
#define OFF_D5    41984
#define OFF_W5P   66560
#define OFF_W3P   71360
#define OFF_PWP   73088
#define OFF_PWB   82304
#define OFF_DB5   82688
#define OFF_DB3   82880
#define OFF_STASH 83072
#define DW_SMEM   91264

__global__ __launch_bounds__(256, 2)
void dwpw_kernel(const float* __restrict__ qkv,
                 const float* __restrict__ dw3_w, const float* __restrict__ dw3_b,
                 const float* __restrict__ pw3_w, const float* __restrict__ pw3_b,
                 const float* __restrict__ dw5_w, const float* __restrict__ dw5_b,
                 const float* __restrict__ pw5_w, const float* __restrict__ pw5_b,
                 float* __restrict__ s3q, float* __restrict__ s5q,
                 float* __restrict__ vkg)
{
    extern __shared__ __align__(16) char sm[];
    float* sin_  = (float*)(sm + OFF_SIN);
    float* d3s   = (float*)(sm + OFF_D3);
    float* d5s   = (float*)(sm + OFF_D5);
    ull*   kvq   = (ull*)(sm + OFF_D3);
    float* red   = (float*)(sm + OFF_PWP);
    float* stash = (float*)(sm + OFF_STASH);
    ull*   w5p   = (ull*)(sm + OFF_W5P);
    ull*   w3p   = (ull*)(sm + OFF_W3P);
    ull*   pwp   = (ull*)(sm + OFF_PWP);
    ull*   pwb   = (ull*)(sm + OFF_PWB);
    ull*   db5   = (ull*)(sm + OFF_DB5);
    ull*   db3   = (ull*)(sm + OFF_DB3);

    const int ytile = blockIdx.x;
    const int g     = blockIdx.y;
    const int b     = blockIdx.z;
    const int tid   = threadIdx.x;
    const int y0    = ytile * 4;

    for (int i = tid; i < 600; i += 256) {
        float w = dw5_w[(g * 24 + i / 25) * 25 + i % 25];
        w5p[i] = pk2(w, w);
    }
    for (int i = tid; i < 216; i += 256) {
        float w = dw3_w[(g * 24 + i / 9) * 9 + i % 9];
        w3p[i] = pk2(w, w);
    }
    for (int i = tid; i < 576; i += 256) {
        float a = pw3_w[g * 576 + i];
        float c = pw5_w[g * 576 + i];
        pwp[i] = pk2(a, a);
        pwp[576 + i] = pk2(c, c);
    }
    if (tid < 24) {
        float b3 = pw3_b[g * 24 + tid], b5 = pw5_b[g * 24 + tid];
        pwb[tid] = pk2(b3, b3);
        pwb[24 + tid] = pk2(b5, b5);
        float d3b = dw3_b[g * 24 + tid], d5b = dw5_b[g * 24 + tid];
        db3[tid] = pk2(d3b, d3b);
        db5[tid] = pk2(d5b, d5b);
    }

    const int c  = tid >> 5;
    const int t  = tid & 31;
    const int py = t >> 3;
    const int xo = (t & 7) * 8;

    for (int grp = 0; grp < 3; grp++) {
        __syncthreads();
        const int icb = grp * 8;
        const float* src = qkv + ((size_t)b * C3 + g * 24 + icb) * NPIX;
        for (int i = tid; i < 8 * 8 * 68; i += 256) {
            int xx = i % 68;
            int r  = (i / 68) & 7;
            int cc = i / (68 * 8);
            int yy = y0 - 2 + r;
            int xg = xx - 2;
            float v = 0.f;
            if ((unsigned)yy < 64u && (unsigned)xg < 64u)
                v = src[(size_t)cc * NPIX + yy * WIDTH + xg];
            sin_[(cc * 8 + r) * 68 + xx] = v;
        }
        __syncthreads();

        const int ch = icb + c;
        ull acc5[4], acc3[4];
        {
            ull b5v = db5[ch], b3v = db3[ch];
#pragma unroll
            for (int j = 0; j < 4; j++) { acc5[j] = b5v; acc3[j] = b3v; }
        }
#pragma unroll
        for (int dy = 0; dy < 5; dy++) {
            const ull* row = (const ull*)&sin_[(c * 8 + py + dy) * 68 + xo];
            ull r0 = row[0], r1 = row[1], r2 = row[2],
                r3 = row[3], r4 = row[4], r5 = row[5];
            ull m0 = pk2(f2hi(r0), f2lo(r1));
            ull m1 = pk2(f2hi(r1), f2lo(r2));
            ull m2 = pk2(f2hi(r2), f2lo(r3));
            ull m3 = pk2(f2hi(r3), f2lo(r4));
            ull m4 = pk2(f2hi(r4), f2lo(r5));
            const ull* w5r = &w5p[ch * 25 + dy * 5];
            ull w0 = w5r[0], w1 = w5r[1], w2 = w5r[2], w3v = w5r[3], w4 = w5r[4];

            ffma2(acc5[0], w0, r0); ffma2(acc5[0], w1, m0); ffma2(acc5[0], w2, r1);
            ffma2(acc5[0], w3v, m1); ffma2(acc5[0], w4, r2);
            ffma2(acc5[1], w0, r1); ffma2(acc5[1], w1, m1); ffma2(acc5[1], w2, r2);
            ffma2(acc5[1], w3v, m2); ffma2(acc5[1], w4, r3);
            ffma2(acc5[2], w0, r2); ffma2(acc5[2], w1, m2); ffma2(acc5[2], w2, r3);
            ffma2(acc5[2], w3v, m3); ffma2(acc5[2], w4, r4);
            ffma2(acc5[3], w0, r3); ffma2(acc5[3], w1, m3); ffma2(acc5[3], w2, r4);
            ffma2(acc5[3], w3v, m4); ffma2(acc5[3], w4, r5);

            if (dy >= 1 && dy <= 3) {
                const ull* w3r = &w3p[ch * 9 + (dy - 1) * 3];
                ull u0 = w3r[0], u1 = w3r[1], u2 = w3r[2];
                ffma2(acc3[0], u0, m0); ffma2(acc3[0], u1, r1); ffma2(acc3[0], u2, m1);
                ffma2(acc3[1], u0, m1); ffma2(acc3[1], u1, r2); ffma2(acc3[1], u2, m2);
                ffma2(acc3[2], u0, m2); ffma2(acc3[2], u1, r3); ffma2(acc3[2], u2, m3);
                ffma2(acc3[3], u0, m3); ffma2(acc3[3], u1, r4); ffma2(acc3[3], u2, m4);
            }
        }
        const int ppb = py * 32 + (xo >> 1);
#pragma unroll
        for (int j = 0; j < 4; j++) {
            *(ull*)&d3s[ch * 256 + (ppb + j) * 2] = acc3[j];
            *(ull*)&d5s[ch * 256 + (ppb + j) * 2] = acc5[j];
        }

        if (grp == 1) {
            for (int i = tid; i < 8 * 256; i += 256) {
                int cc = i >> 8, px = i & 255;
                stash[i] = sin_[(cc * 8 + 2 + (px >> 6)) * 68 + 2 + (px & 63)];
            }
        }

        if (grp == 2) {
            const int px = tid;
            const int vy = px >> 6;
            const int vx = px & 63;
            float kk[8], vv[8];
#pragma unroll
            for (int e = 0; e < 8; e++)
                kk[e] = fmaxf(stash[e * 256 + px], 0.f);
#pragma unroll
            for (int d = 0; d < 8; d++)
                vv[d] = sin_[(d * 8 + 2 + vy) * 68 + 2 + vx];

            float vacc[9][8];
#pragma unroll
            for (int d = 0; d < 8; d++)
#pragma unroll
                for (int e = 0; e < 8; e++)
                    vacc[d][e] = vv[d] * kk[e];
#pragma unroll
            for (int e = 0; e < 8; e++) vacc[8][e] = kk[e];

#pragma unroll
            for (int d = 0; d < 9; d++)
#pragma unroll
                for (int e = 0; e < 8; e++) {
                    float v = vacc[d][e];
                    v += __shfl_xor_sync(0xffffffffu, v, 16);
                    v += __shfl_xor_sync(0xffffffffu, v, 8);
                    v += __shfl_xor_sync(0xffffffffu, v, 4);
                    v += __shfl_xor_sync(0xffffffffu, v, 2);
                    v += __shfl_xor_sync(0xffffffffu, v, 1);
                    vacc[d][e] = v;
                }
            __syncthreads();
            const int w    = tid >> 5;
            const int lane = tid & 31;
            if (lane == 0) {
#pragma unroll
                for (int d = 0; d < 9; d++)
#pragma unroll
                    for (int e = 0; e < 8; e++)
                        stash[w * 72 + d * 8 + e] = vacc[d][e];
            }
            __syncthreads();
            if (tid < 72) {
                float s = 0.f;
#pragma unroll
                for (int j = 0; j < 8; j++) s += stash[j * 72 + tid];
                atomicAdd(&vkg[((size_t)b * 96 + g) * 72 + tid], s);
            }
        }
    }
    __syncthreads();

    const int conv = tid >> 7;
    const int tt   = tid & 127;
    const int og   = tt >> 5;
    const int pg   = tt & 31;
    const float* dsrc = conv ? d5s : d3s;
    const ull* wp = &pwp[conv * 576];
    const ull* bb = &pwb[conv * 24];
    float* qout = conv ? s5q : s3q;

    ull acc[6][4];
#pragma unroll
    for (int j = 0; j < 6; j++) {
        ull bv = bb[og * 6 + j];
#pragma unroll
        for (int i = 0; i < 4; i++) acc[j][i] = bv;
    }

#pragma unroll
    for (int ic = 0; ic < 24; ic++) {
        const ulonglong2 dA = *(const ulonglong2*)&dsrc[ic * 256 + pg * 8];
        const ulonglong2 dB = *(const ulonglong2*)&dsrc[ic * 256 + pg * 8 + 4];
        ull dv[4] = {dA.x, dA.y, dB.x, dB.y};
#pragma unroll
        for (int j = 0; j < 6; j++) {
            ull wv = wp[(og * 6 + j) * 24 + ic];
#pragma unroll
            for (int i = 0; i < 4; i++)
                ffma2(acc[j][i], wv, dv[i]);
        }
    }
    __syncthreads();

    {
        const int pair0 = pg * 4;
        const int by = y0 + (pair0 >> 5);
        const int bx = (pair0 & 31) * 2;
        const size_t qbase = (((size_t)b * 32 + g) * 8) * NPIX + by * WIDTH + bx;
#pragma unroll
        for (int j = 0; j < 6; j++) {
            const int o = og * 6 + j;
            if (o < 8) {
#pragma unroll
                for (int i = 0; i < 4; i++)
                    *(float2*)&qout[qbase + (size_t)o * NPIX + i * 2] =
                        make_float2(f2lo(acc[j][i]), f2hi(acc[j][i]));
            } else {
#pragma unroll
                for (int i = 0; i < 4; i++)
                    kvq[(conv * 16 + (o - 8)) * 128 + pair0 + i] = acc[j][i];
            }
        }
    }
    __syncthreads();

    {
        const int w    = tid >> 5;
        const int lane = tid & 31;
        const int cv   = w >> 2;
        const int sub  = w & 3;
        const int pair = sub * 32 + lane;

        ull kvv[16];
#pragma unroll
        for (int ch = 0; ch < 16; ch++)
            kvv[ch] = kvq[(cv * 16 + ch) * 128 + pair];

        float acc2[9][8];
#pragma unroll
        for (int d = 0; d < 9; d++)
#pragma unroll
            for (int e = 0; e < 8; e++) acc2[d][e] = 0.f;

#pragma unroll
        for (int hx = 0; hx < 2; hx++) {
            float kk[8], vv[8];
#pragma unroll
            for (int e = 0; e < 8; e++)
                kk[e] = fmaxf(hx ? f2hi(kvv[e]) : f2lo(kvv[e]), 0.f);
#pragma unroll
            for (int d = 0; d < 8; d++)
                vv[d] = hx ? f2hi(kvv[8 + d]) : f2lo(kvv[8 + d]);
#pragma unroll
            for (int d = 0; d < 8; d++)
#pragma unroll
                for (int e = 0; e < 8; e++)
                    acc2[d][e] += vv[d] * kk[e];
#pragma unroll
            for (int e = 0; e < 8; e++)
                acc2[8][e] += kk[e];
        }

#pragma unroll
        for (int d = 0; d < 9; d++)
#pragma unroll
            for (int e = 0; e < 8; e++) {
                float v = acc2[d][e];
                v += __shfl_xor_sync(0xffffffffu, v, 16);
                v += __shfl_xor_sync(0xffffffffu, v, 8);
                v += __shfl_xor_sync(0xffffffffu, v, 4);
                acc2[d][e] = v;
            }
        if (lane < 4) {
            float* rp = &red[((cv * 16) + sub * 4 + lane) * 72];
#pragma unroll
            for (int d = 0; d < 9; d++)
#pragma unroll
                for (int e = 0; e < 8; e++)
                    rp[d * 8 + e] = acc2[d][e];
        }
    }
    __syncthreads();

    if (tid < 144) {
        const int cv  = tid / 72;
        const int idx = tid % 72;
        float s = 0.f;
#pragma unroll
        for (int j = 0; j < 16; j++)
            s += red[(cv * 16 + j) * 72 + idx];
        atomicAdd(&vkg[((size_t)b * 96 + 32 + cv * 32 + g) * 72 + idx], s);
    }
}

// ---------------------------------------------------------------------------
// attention normalize: 4 CTAs/SM, packed f32x2, z-split 8 (1 iter/thread).
// ---------------------------------------------------------------------------
__global__ __launch_bounds__(256, 4)
void att_kernel(const float* __restrict__ qkv, const float* __restrict__ s3q,
                const float* __restrict__ s5q, const float* __restrict__ vk,
                __half* __restrict__ atth)
{
    const int hh = blockIdx.x;
    const int b  = blockIdx.y;
    const int n0 = blockIdx.z * (NPIX / 8);
    const int src_id = hh >> 5;
    const int g      = hh & 31;
    const float* base;
    if (src_id == 0)      base = qkv + ((size_t)b * C3 + g * 24) * NPIX;
    else if (src_id == 1) base = s3q + (((size_t)b * 32 + g) * 8) * NPIX;
    else                  base = s5q + (((size_t)b * 32 + g) * 8) * NPIX;

    __shared__ ull vsp[72];
    const int tid = threadIdx.x;
    if (tid < 72) {
        float v = vk[((size_t)b * 96 + hh) * 72 + tid];
        vsp[tid] = pk2(v, v);
    }
    __syncthreads();

    __half* oh = atth + ((size_t)b * C3 + hh * 8) * NPIX;

    {
        const int n = n0 + tid * 2;
        ull qp[8];
#pragma unroll
        for (int e = 0; e < 8; e++) {
            ull raw = *(const ull*)(base + (size_t)e * NPIX + n);
            qp[e] = pk2(fmaxf(f2lo(raw), 0.f), fmaxf(f2hi(raw), 0.f));
        }
        ull den = pk2(1e-15f, 1e-15f);
#pragma unroll
        for (int e = 0; e < 8; e++) ffma2(den, vsp[64 + e], qp[e]);
        const float rd0 = __fdividef(1.f, f2lo(den));
        const float rd1 = __fdividef(1.f, f2hi(den));
#pragma unroll
        for (int d = 0; d < 8; d++) {
            ull num = 0ull;
#pragma unroll
            for (int e = 0; e < 8; e++) ffma2(num, vsp[d * 8 + e], qp[e]);
            __half2 hp;
            hp.x = __float2half_rn(f2lo(num) * rd0);
            hp.y = __float2half_rn(f2hi(num) * rd1);
            *(__half2*)(oh + (size_t)d * NPIX + n) = hp;
        }
    }
}

// ---------------------------------------------------------------------------
struct PipeArgs {
    const float *x, *qkv_b, *dw3_w, *dw3_b, *pw3_w, *pw3_b;
    const float *dw5_w, *dw5_b, *pw5_w, *pw5_b, *proj_b;
    __half *xth, *xtl, *ath, *wqh, *wql, *wph, *wpl;
    float *qkv, *s3q, *s5q, *vkb, *out;
};

static void enqueue_part(cudaStream_t st, const PipeArgs& a, int b0, int nb,
                         cudaEvent_t evW)
{
    const size_t offX = (size_t)b0 * 256 * NPIX;
    const size_t offQ = (size_t)b0 * C3 * NPIX;
    const size_t off3 = (size_t)b0 * 32 * 8 * NPIX;
    const size_t offV = (size_t)b0 * 96 * 72;

    // x split has no weight dependency — issue before the weight barrier
    wsplit_kernel<<<(nb * 256 * NPIX / 4 + 255) / 256, 256, 0, st>>>(
        a.x + offX, a.xth + offX, a.xtl + offX, nb * 256 * NPIX);

    cudaStreamWaitEvent(st, evW, 0);   // weights ready before qkv GEMM

    gemm_f16<<<dim3(NPIX / 128, C3 / 128, nb), 256, 3 * STG2, st>>>(
        a.wqh, a.wql, a.xth + offX, a.xtl + offX, a.qkv_b, a.qkv + offQ,
        C3, NPIX, 256);

    dwpw_kernel<<<dim3(16, 32, nb), 256, DW_SMEM, st>>>(
        a.qkv + offQ, a.dw3_w, a.dw3_b, a.pw3_w, a.pw3_b,
        a.dw5_w, a.dw5_b, a.pw5_w, a.pw5_b,
        a.s3q + off3, a.s5q + off3, a.vkb + offV);

    att_kernel<<<dim3(96, nb, 8), 256, 0, st>>>(
        a.qkv + offQ, a.s3q + off3, a.s5q + off3, a.vkb + offV, a.ath + offQ);

    gemm_f16_2p<<<dim3(NPIX / 128, 256 / 128, nb), 256, 3 * P2_STG, st>>>(
        a.wph, a.wpl, a.ath + offQ, a.proj_b, a.out + (size_t)b0 * 256 * NPIX,
        256, NPIX, C3);
}

extern "C" void kernel_launch(void* const* d_in, const int* in_sizes, int n_in,
                              void* d_out, int out_size)
{
    PipeArgs a;
    a.x      = (const float*)d_in[0];
    const float* qkv_w = (const float*)d_in[1];
    a.qkv_b  = (const float*)d_in[2];
    a.dw3_w  = (const float*)d_in[3];
    a.dw3_b  = (const float*)d_in[4];
    a.pw3_w  = (const float*)d_in[5];
    a.pw3_b  = (const float*)d_in[6];
    a.dw5_w  = (const float*)d_in[7];
    a.dw5_b  = (const float*)d_in[8];
    a.pw5_w  = (const float*)d_in[9];
    a.pw5_b  = (const float*)d_in[10];
    const float* proj_w = (const float*)d_in[11];
    a.proj_b = (const float*)d_in[12];
    a.out    = (float*)d_out;

    void *p;
    cudaGetSymbolAddress(&p, g_qkv);  a.qkv = (float*)p;
    cudaGetSymbolAddress(&p, g_s3q);  a.s3q = (float*)p;
    cudaGetSymbolAddress(&p, g_s5q);  a.s5q = (float*)p;
    cudaGetSymbolAddress(&p, g_vk);   a.vkb = (float*)p;
    cudaGetSymbolAddress(&p, g_xt_h); a.xth = (__half*)p;
    cudaGetSymbolAddress(&p, g_xt_l); a.xtl = (__half*)p;
    cudaGetSymbolAddress(&p, g_at_h); a.ath = (__half*)p;
    cudaGetSymbolAddress(&p, g_wq_h); a.wqh = (__half*)p;
    cudaGetSymbolAddress(&p, g_wq_l); a.wql = (__half*)p;
    cudaGetSymbolAddress(&p, g_wp_h); a.wph = (__half*)p;
    cudaGetSymbolAddress(&p, g_wp_l); a.wpl = (__half*)p;

    static bool inited = false;
    static cudaStream_t s[3];
    static cudaEvent_t evW, evF, evJ[3];
    if (!inited) {
        for (int i = 0; i < 3; i++) {
            cudaStreamCreateWithFlags(&s[i], cudaStreamNonBlocking);
            cudaEventCreateWithFlags(&evJ[i], cudaEventDisableTiming);
        }
        cudaEventCreateWithFlags(&evW, cudaEventDisableTiming);
        cudaEventCreateWithFlags(&evF, cudaEventDisableTiming);
        cudaFuncSetAttribute(gemm_f16,
            cudaFuncAttributeMaxDynamicSharedMemorySize, 3 * STG2);
        cudaFuncSetAttribute(gemm_f16_2p,
            cudaFuncAttributeMaxDynamicSharedMemorySize, 3 * P2_STG);
        cudaFuncSetAttribute(dwpw_kernel,
            cudaFuncAttributeMaxDynamicSharedMemorySize, DW_SMEM);
        inited = true;
    }

    // main stream head: vk zero, then fork so side streams start x-splits
    cudaMemsetAsync(a.vkb, 0, (size_t)BATCH * 96 * 72 * sizeof(float), 0);
    cudaEventRecord(evF, 0);
    for (int i = 0; i < 3; i++) cudaStreamWaitEvent(s[i], evF, 0);

    // fused weight split on the main stream (one launch, both tensors)
    wsplit2_kernel<<<384, 256>>>(qkv_w, a.wqh, a.wql, proj_w, a.wph, a.wpl);
    cudaEventRecord(evW, 0);

    enqueue_part(0,    a, 0, 2, evW);
    enqueue_part(s[0], a, 2, 2, evW);
    enqueue_part(s[1], a, 4, 2, evW);
    enqueue_part(s[2], a, 6, 2, evW);

    for (int i = 0; i < 3; i++) {
        cudaEventRecord(evJ[i], s[i]);
        cudaStreamWaitEvent(0, evJ[i], 0);
    }
}

// round 17
// speedup vs baseline: 1.2201x; 1.1035x over previous
#include <cuda_runtime.h>
#include <cuda_fp16.h>
#include <cstdint>

// ---------------------------------------------------------------------------
// LiteMLA on sm_103a.  (R16 best config; vectorized dwpw tile loader)
// Four-stream batch-split pipeline (2 batches each) to overlap stage tails.
// qkv GEMM: fp16 hi/lo x hi/lo, 3 mma products, 3-stage cp.async ring.
// proj GEMM: weights hi/lo x att fp16, 2 products, 3-stage ring.
// dwpw: depthwise f32x2 -> register-tiled pointwise -> fused vk (all heads).
// ---------------------------------------------------------------------------

#define BATCH 8
#define C3 768
#define NPIX 4096
#define WIDTH 64

__device__ float g_qkv[(size_t)BATCH * C3 * NPIX];
__device__ float g_s3q[(size_t)BATCH * 32 * 8 * NPIX];
__device__ float g_s5q[(size_t)BATCH * 32 * 8 * NPIX];
__device__ float g_vk [(size_t)BATCH * 96 * 72];

__device__ __half g_xt_h [(size_t)BATCH * 256 * NPIX];
__device__ __half g_xt_l [(size_t)BATCH * 256 * NPIX];
__device__ __half g_at_h [(size_t)BATCH * C3 * NPIX];
__device__ __half g_wq_h [C3 * 256];
__device__ __half g_wq_l [C3 * 256];
__device__ __half g_wp_h [256 * C3];
__device__ __half g_wp_l [256 * C3];

// ---------------------------------------------------------------------------
typedef unsigned long long ull;

__device__ __forceinline__ uint32_t smem_u32(const void* p) {
    uint32_t a;
    asm("{ .reg .u64 t; cvta.to.shared.u64 t, %1; cvt.u32.u64 %0, t; }"
        : "=r"(a) : "l"(p));
    return a;
}
__device__ __forceinline__ ull pk2(float lo, float hi) {
    ull r;
    asm("mov.b64 %0, {%1, %2};" : "=l"(r)
        : "r"(__float_as_uint(lo)), "r"(__float_as_uint(hi)));
    return r;
}
__device__ __forceinline__ void ffma2(ull& d, ull a, ull b) {
    asm("fma.rn.f32x2 %0, %1, %2, %0;" : "+l"(d) : "l"(a), "l"(b));
}
__device__ __forceinline__ float f2lo(ull v) {
    return __uint_as_float((unsigned)(v & 0xffffffffull));
}
__device__ __forceinline__ float f2hi(ull v) {
    return __uint_as_float((unsigned)(v >> 32));
}

#define CP_ASYNC16(s, g) \
    asm volatile("cp.async.cg.shared.global [%0], [%1], 16;" :: "r"(s), "l"(g))
#define CP_COMMIT() asm volatile("cp.async.commit_group;" ::: "memory")
#define CP_WAIT(n)  asm volatile("cp.async.wait_group %0;" :: "n"(n) : "memory")

__device__ __forceinline__ void ldsm4(uint32_t addr, uint32_t* r) {
    asm volatile("ldmatrix.sync.aligned.m8n8.x4.shared.b16 {%0,%1,%2,%3}, [%4];"
                 : "=r"(r[0]), "=r"(r[1]), "=r"(r[2]), "=r"(r[3]) : "r"(addr));
}
__device__ __forceinline__ void ldsm4t(uint32_t addr, uint32_t* r) {
    asm volatile("ldmatrix.sync.aligned.m8n8.x4.trans.shared.b16 {%0,%1,%2,%3}, [%4];"
                 : "=r"(r[0]), "=r"(r[1]), "=r"(r[2]), "=r"(r[3]) : "r"(addr));
}
__device__ __forceinline__ void mma_f16(float* d, const uint32_t* a,
                                        const uint32_t* b) {
    asm volatile(
        "mma.sync.aligned.m16n8k16.row.col.f32.f16.f16.f32 "
        "{%0,%1,%2,%3}, {%4,%5,%6,%7}, {%8,%9}, {%0,%1,%2,%3};"
        : "+f"(d[0]), "+f"(d[1]), "+f"(d[2]), "+f"(d[3])
        : "r"(a[0]), "r"(a[1]), "r"(a[2]), "r"(a[3]), "r"(b[0]), "r"(b[1]));
}

#define A_PITCH 80
#define B_PITCH 272

// ---------------------------------------------------------------------------
// 3-product GEMM (qkv): C[b] = (Ah+Al)(M,K) @ (Bh+Bl)(b,K,N) + bias
// 3-stage cp.async ring, 2 CTAs/SM.  (unchanged)
// ---------------------------------------------------------------------------
#define OFF_AL  10240
#define OFF_BH  20480
#define OFF_BL  29184
#define STG2    37888

__device__ __forceinline__ void stage_load(
    uint32_t sbase, const __half* gA_h, const __half* gA_l,
    const __half* gB_h, const __half* gB_l, int K, int N, int kc, int tid)
{
    const int op = tid >> 6;
    const int t  = tid & 63;
    if (op < 2) {
        const __half* g = ((op == 0) ? gA_h : gA_l) + kc * 32;
        const uint32_t sb = sbase + op * OFF_AL;
#pragma unroll
        for (int it = 0; it < 8; it++) {
            int chunk = t + it * 64;
            int row = chunk >> 2, c = chunk & 3;
            CP_ASYNC16(sb + row * A_PITCH + c * 16, g + (size_t)row * K + c * 8);
        }
    } else {
        const __half* g = ((op == 2) ? gB_h : gB_l) + (size_t)kc * 32 * N;
        const uint32_t sb = sbase + ((op == 2) ? OFF_BH : OFF_BL);
#pragma unroll
        for (int it = 0; it < 8; it++) {
            int chunk = t + it * 64;
            int row = chunk >> 4, c = chunk & 15;
            CP_ASYNC16(sb + row * B_PITCH + c * 16, g + (size_t)row * N + c * 8);
        }
    }
}

__global__ __launch_bounds__(256, 2)
void gemm_f16(const __half* __restrict__ Ah, const __half* __restrict__ Al,
              const __half* __restrict__ Bmh, const __half* __restrict__ Bml,
              const float* __restrict__ bias, float* __restrict__ C,
              int M, int N, int K)
{
    extern __shared__ __align__(16) char smem[];
    const uint32_t sm0 = smem_u32(smem);

    const int tid  = threadIdx.x;
    const int wid  = tid >> 5;
    const int lane = tid & 31;
    const int n0 = blockIdx.x * 128;
    const int m0 = blockIdx.y * 128;
    const int b  = blockIdx.z;

    const int wm = (wid >> 1) * 32;
    const int wn = (wid & 1) * 64;

    const __half* gA_h = Ah + (size_t)m0 * K;
    const __half* gA_l = Al + (size_t)m0 * K;
    const __half* gB_h = Bmh + (size_t)b * K * N + n0;
    const __half* gB_l = Bml + (size_t)b * K * N + n0;

    float acc[2][8][4];
#pragma unroll
    for (int t = 0; t < 2; t++)
#pragma unroll
        for (int nt = 0; nt < 8; nt++)
#pragma unroll
            for (int i = 0; i < 4; i++) acc[t][nt][i] = 0.f;

    const int nk = K / 32;

    stage_load(sm0, gA_h, gA_l, gB_h, gB_l, K, N, 0, tid);
    CP_COMMIT();
    if (nk > 1) {
        stage_load(sm0 + STG2, gA_h, gA_l, gB_h, gB_l, K, N, 1, tid);
        CP_COMMIT();
    }

    const int a_row = lane & 15;
    const int a_hi  = (lane >> 4) * 16;
    const int b_kr = (lane & 7) + ((lane >> 3) & 1) * 8;
    const int b_nc = (lane >> 4) * 8;

    for (int kc = 0; kc < nk; kc++) {
        if (kc + 2 < nk) {
            stage_load(sm0 + ((kc + 2) % 3) * STG2,
                       gA_h, gA_l, gB_h, gB_l, K, N, kc + 2, tid);
            CP_COMMIT();
        }
        if (kc + 2 < nk)      CP_WAIT(2);
        else if (kc + 1 < nk) CP_WAIT(1);
        else                  CP_WAIT(0);
        __syncthreads();

        const uint32_t sb  = sm0 + (kc % 3) * STG2;
        const uint32_t aAh = sb;
        const uint32_t aAl = sb + OFF_AL;
        const uint32_t aBh = sb + OFF_BH;
        const uint32_t aBl = sb + OFF_BL;

#pragma unroll
        for (int j = 0; j < 2; j++) {
            uint32_t ah[2][4], al[2][4];
#pragma unroll
            for (int t = 0; t < 2; t++) {
                uint32_t off = (uint32_t)(wm + t * 16 + a_row) * A_PITCH + j * 32 + a_hi;
                ldsm4(aAh + off, ah[t]);
                ldsm4(aAl + off, al[t]);
            }
            uint32_t bh[4][4], bl[4][4];
#pragma unroll
            for (int p = 0; p < 4; p++) {
                uint32_t off = (uint32_t)(j * 16 + b_kr) * B_PITCH +
                               (uint32_t)(wn + p * 16 + b_nc) * 2;
                ldsm4t(aBh + off, bh[p]);
                ldsm4t(aBl + off, bl[p]);
            }
#pragma unroll
            for (int t = 0; t < 2; t++)
#pragma unroll
                for (int nt = 0; nt < 8; nt++) {
                    const uint32_t* bhp = &bh[nt >> 1][(nt & 1) * 2];
                    const uint32_t* blp = &bl[nt >> 1][(nt & 1) * 2];
                    mma_f16(acc[t][nt], ah[t], bhp);
                    mma_f16(acc[t][nt], ah[t], blp);
                    mma_f16(acc[t][nt], al[t], bhp);
                }
        }
        __syncthreads();
    }

    const int l4 = lane >> 2;
    const int l2 = (lane & 3) * 2;
#pragma unroll
    for (int t = 0; t < 2; t++) {
        const int m_lo = m0 + wm + t * 16 + l4;
        const float bi_lo = bias[m_lo];
        const float bi_hi = bias[m_lo + 8];
        float* c_lo = C + ((size_t)b * M + m_lo) * N + n0 + wn + l2;
        float* c_hi = c_lo + (size_t)8 * N;
#pragma unroll
        for (int nt = 0; nt < 8; nt++) {
            float2 v0 = {acc[t][nt][0] + bi_lo, acc[t][nt][1] + bi_lo};
            float2 v1 = {acc[t][nt][2] + bi_hi, acc[t][nt][3] + bi_hi};
            *(float2*)(c_lo + nt * 8) = v0;
            *(float2*)(c_hi + nt * 8) = v1;
        }
    }
}

// ---------------------------------------------------------------------------
// 2-product GEMM (proj): 3-stage ring.  (unchanged)
// ---------------------------------------------------------------------------
#define P2_AL   10240
#define P2_BH   20480
#define P2_STG  29184

__device__ __forceinline__ void stage_load_2p(
    uint32_t sbase, const __half* gA_h, const __half* gA_l,
    const __half* gB_h, int K, int N, int kc, int tid)
{
    if (tid < 128) {
        const int op = tid >> 6;
        const int t  = tid & 63;
        const __half* g = ((op == 0) ? gA_h : gA_l) + kc * 32;
        const uint32_t sb = sbase + op * P2_AL;
#pragma unroll
        for (int it = 0; it < 8; it++) {
            int chunk = t + it * 64;
            int row = chunk >> 2, c = chunk & 3;
            CP_ASYNC16(sb + row * A_PITCH + c * 16, g + (size_t)row * K + c * 8);
        }
    } else {
        const int t = tid - 128;
        const __half* g = gB_h + (size_t)kc * 32 * N;
        const uint32_t sb = sbase + P2_BH;
#pragma unroll
        for (int it = 0; it < 4; it++) {
            int chunk = t + it * 128;
            int row = chunk >> 4, c = chunk & 15;
            CP_ASYNC16(sb + row * B_PITCH + c * 16, g + (size_t)row * N + c * 8);
        }
    }
}

__global__ __launch_bounds__(256, 2)
void gemm_f16_2p(const __half* __restrict__ Ah, const __half* __restrict__ Al,
                 const __half* __restrict__ Bmh,
                 const float* __restrict__ bias, float* __restrict__ C,
                 int M, int N, int K)
{
    extern __shared__ __align__(16) char smem[];
    const uint32_t sm0 = smem_u32(smem);

    const int tid  = threadIdx.x;
    const int wid  = tid >> 5;
    const int lane = tid & 31;
    const int n0 = blockIdx.x * 128;
    const int m0 = blockIdx.y * 128;
    const int b  = blockIdx.z;

    const int wm = (wid >> 1) * 32;
    const int wn = (wid & 1) * 64;

    const __half* gA_h = Ah + (size_t)m0 * K;
    const __half* gA_l = Al + (size_t)m0 * K;
    const __half* gB_h = Bmh + (size_t)b * K * N + n0;

    float acc[2][8][4];
#pragma unroll
    for (int t = 0; t < 2; t++)
#pragma unroll
        for (int nt = 0; nt < 8; nt++)
#pragma unroll
            for (int i = 0; i < 4; i++) acc[t][nt][i] = 0.f;

    const int nk = K / 32;

    stage_load_2p(sm0, gA_h, gA_l, gB_h, K, N, 0, tid);
    CP_COMMIT();
    if (nk > 1) {
        stage_load_2p(sm0 + P2_STG, gA_h, gA_l, gB_h, K, N, 1, tid);
        CP_COMMIT();
    }

    const int a_row = lane & 15;
    const int a_hi  = (lane >> 4) * 16;
    const int b_kr = (lane & 7) + ((lane >> 3) & 1) * 8;
    const int b_nc = (lane >> 4) * 8;

    for (int kc = 0; kc < nk; kc++) {
        if (kc + 2 < nk) {
            stage_load_2p(sm0 + ((kc + 2) % 3) * P2_STG,
                          gA_h, gA_l, gB_h, K, N, kc + 2, tid);
            CP_COMMIT();
        }
        if (kc + 2 < nk)      CP_WAIT(2);
        else if (kc + 1 < nk) CP_WAIT(1);
        else                  CP_WAIT(0);
        __syncthreads();

        const uint32_t sb  = sm0 + (kc % 3) * P2_STG;
        const uint32_t aAh = sb;
        const uint32_t aAl = sb + P2_AL;
        const uint32_t aBh = sb + P2_BH;

#pragma unroll
        for (int j = 0; j < 2; j++) {
            uint32_t ah[2][4], al[2][4];
#pragma unroll
            for (int t = 0; t < 2; t++) {
                uint32_t off = (uint32_t)(wm + t * 16 + a_row) * A_PITCH + j * 32 + a_hi;
                ldsm4(aAh + off, ah[t]);
                ldsm4(aAl + off, al[t]);
            }
            uint32_t bh[4][4];
#pragma unroll
            for (int p = 0; p < 4; p++) {
                uint32_t off = (uint32_t)(j * 16 + b_kr) * B_PITCH +
                               (uint32_t)(wn + p * 16 + b_nc) * 2;
                ldsm4t(aBh + off, bh[p]);
            }
#pragma unroll
            for (int t = 0; t < 2; t++)
#pragma unroll
                for (int nt = 0; nt < 8; nt++) {
                    const uint32_t* bhp = &bh[nt >> 1][(nt & 1) * 2];
                    mma_f16(acc[t][nt], ah[t], bhp);
                    mma_f16(acc[t][nt], al[t], bhp);
                }
        }
        __syncthreads();
    }

    const int l4 = lane >> 2;
    const int l2 = (lane & 3) * 2;
#pragma unroll
    for (int t = 0; t < 2; t++) {
        const int m_lo = m0 + wm + t * 16 + l4;
        const float bi_lo = bias[m_lo];
        const float bi_hi = bias[m_lo + 8];
        float* c_lo = C + ((size_t)b * M + m_lo) * N + n0 + wn + l2;
        float* c_hi = c_lo + (size_t)8 * N;
#pragma unroll
        for (int nt = 0; nt < 8; nt++) {
            float2 v0 = {acc[t][nt][0] + bi_lo, acc[t][nt][1] + bi_lo};
            float2 v1 = {acc[t][nt][2] + bi_hi, acc[t][nt][3] + bi_hi};
            *(float2*)(c_lo + nt * 8) = v0;
            *(float2*)(c_hi + nt * 8) = v1;
        }
    }
}

// ---------------------------------------------------------------------------
// vectorized split: 4 elements/thread.  (unchanged)
// ---------------------------------------------------------------------------
__global__ void wsplit_kernel(const float* __restrict__ w,
                              __half* __restrict__ hi,
                              __half* __restrict__ lo, int n)
{
    int i = blockIdx.x * 256 + threadIdx.x;
    int n4 = n >> 2;
    if (i < n4) {
        float4 v = ((const float4*)w)[i];
        __half h0 = __float2half_rn(v.x), h1 = __float2half_rn(v.y);
        __half h2 = __float2half_rn(v.z), h3 = __float2half_rn(v.w);
        __half2 hp0; hp0.x = h0; hp0.y = h1;
        __half2 hp1; hp1.x = h2; hp1.y = h3;
        ((__half2*)hi)[2 * i]     = hp0;
        ((__half2*)hi)[2 * i + 1] = hp1;
        __half2 lp0, lp1;
        lp0.x = __float2half_rn(v.x - __half2float(h0));
        lp0.y = __float2half_rn(v.y - __half2float(h1));
        lp1.x = __float2half_rn(v.z - __half2float(h2));
        lp1.y = __float2half_rn(v.w - __half2float(h3));
        ((__half2*)lo)[2 * i]     = lp0;
        ((__half2*)lo)[2 * i + 1] = lp1;
    }
}

// fused double split: blocks [0,192) -> wa (C3*256), blocks [192,384) -> wb
__global__ void wsplit2_kernel(const float* __restrict__ wa,
                               __half* __restrict__ ha, __half* __restrict__ la,
                               const float* __restrict__ wb,
                               __half* __restrict__ hb, __half* __restrict__ lb)
{
    const int half = (blockIdx.x >= 192);
    const int i = (blockIdx.x - half * 192) * 256 + threadIdx.x;
    const float* w = half ? wb : wa;
    __half* hi = half ? hb : ha;
    __half* lo = half ? lb : la;
    float4 v = ((const float4*)w)[i];
    __half h0 = __float2half_rn(v.x), h1 = __float2half_rn(v.y);
    __half h2 = __float2half_rn(v.z), h3 = __float2half_rn(v.w);
    __half2 hp0; hp0.x = h0; hp0.y = h1;
    __half2 hp1; hp1.x = h2; hp1.y = h3;
    ((__half2*)hi)[2 * i]     = hp0;
    ((__half2*)hi)[2 * i + 1] = hp1;
    __half2 lp0, lp1;
    lp0.x = __float2half_rn(v.x - __half2float(h0));
    lp0.y = __float2half_rn(v.y - __half2float(h1));
    lp1.x = __float2half_rn(v.z - __half2float(h2));
    lp1.y = __float2half_rn(v.w - __half2float(h3));
    ((__half2*)lo)[2 * i]     = lp0;
    ((__half2*)lo)[2 * i + 1] = lp1;
}

// ---------------------------------------------------------------------------
// dwpw: vectorized tile loader (pads/invalid rows zeroed once; valid rows as
// 4x LDG.128 + 8x STS.64 per thread).  Rest unchanged.
// ---------------------------------------------------------------------------
#define OFF_SIN   0
#define OFF_D3    17408
#define OFF_D5    41984
#define OFF_W5P   66560
#define OFF_W3P   71360
#define OFF_PWP   73088
#define OFF_PWB   82304
#define OFF_DB5   82688
#define OFF_DB3   82880
#define OFF_STASH 83072
#define DW_SMEM   91264

__global__ __launch_bounds__(256, 2)
void dwpw_kernel(const float* __restrict__ qkv,
                 const float* __restrict__ dw3_w, const float* __restrict__ dw3_b,
                 const float* __restrict__ pw3_w, const float* __restrict__ pw3_b,
                 const float* __restrict__ dw5_w, const float* __restrict__ dw5_b,
                 const float* __restrict__ pw5_w, const float* __restrict__ pw5_b,
                 float* __restrict__ s3q, float* __restrict__ s5q,
                 float* __restrict__ vkg)
{
    extern __shared__ __align__(16) char sm[];
    float* sin_  = (float*)(sm + OFF_SIN);
    float* d3s   = (float*)(sm + OFF_D3);
    float* d5s   = (float*)(sm + OFF_D5);
    ull*   kvq   = (ull*)(sm + OFF_D3);
    float* red   = (float*)(sm + OFF_PWP);
    float* stash = (float*)(sm + OFF_STASH);
    ull*   w5p   = (ull*)(sm + OFF_W5P);
    ull*   w3p   = (ull*)(sm + OFF_W3P);
    ull*   pwp   = (ull*)(sm + OFF_PWP);
    ull*   pwb   = (ull*)(sm + OFF_PWB);
    ull*   db5   = (ull*)(sm + OFF_DB5);
    ull*   db3   = (ull*)(sm + OFF_DB3);

    const int ytile = blockIdx.x;
    const int g     = blockIdx.y;
    const int b     = blockIdx.z;
    const int tid   = threadIdx.x;
    const int y0    = ytile * 4;

    // zero the whole tile once: pads (xx<2 or >=66) and y-invalid rows stay 0
    for (int i = tid; i < 64 * 68; i += 256)
        sin_[i] = 0.f;

    for (int i = tid; i < 600; i += 256) {
        float w = dw5_w[(g * 24 + i / 25) * 25 + i % 25];
        w5p[i] = pk2(w, w);
    }
    for (int i = tid; i < 216; i += 256) {
        float w = dw3_w[(g * 24 + i / 9) * 9 + i % 9];
        w3p[i] = pk2(w, w);
    }
    for (int i = tid; i < 576; i += 256) {
        float a = pw3_w[g * 576 + i];
        float c = pw5_w[g * 576 + i];
        pwp[i] = pk2(a, a);
        pwp[576 + i] = pk2(c, c);
    }
    if (tid < 24) {
        float b3 = pw3_b[g * 24 + tid], b5 = pw5_b[g * 24 + tid];
        pwb[tid] = pk2(b3, b3);
        pwb[24 + tid] = pk2(b5, b5);
        float d3b = dw3_b[g * 24 + tid], d5b = dw5_b[g * 24 + tid];
        db3[tid] = pk2(d3b, d3b);
        db5[tid] = pk2(d5b, d5b);
    }

    // loader constants: thread = (row, quad). row=cc*8+r covers 8ch x 8rows.
    const int lrow = tid >> 2;            // 0..63
    const int lq   = tid & 3;             // 16-col quad
    const int lr   = lrow & 7;
    const int lcc  = lrow >> 3;
    const int lyy  = y0 - 2 + lr;
    const bool lvalid = ((unsigned)lyy < 64u);
    const float* lbase = qkv + ((size_t)b * C3 + g * 24 + lcc) * NPIX
                             + lyy * WIDTH + lq * 16;   // +icb*NPIX per grp
    float* sdst = &sin_[lrow * 68 + 2 + lq * 16];

    const int c  = tid >> 5;
    const int t  = tid & 31;
    const int py = t >> 3;
    const int xo = (t & 7) * 8;

    for (int grp = 0; grp < 3; grp++) {
        __syncthreads();
        const int icb = grp * 8;
        if (lvalid) {
            const float* src = lbase + (size_t)icb * NPIX;
#pragma unroll
            for (int j = 0; j < 4; j++) {
                float4 v = *(const float4*)(src + j * 4);
                *(float2*)(sdst + j * 4)     = make_float2(v.x, v.y);
                *(float2*)(sdst + j * 4 + 2) = make_float2(v.z, v.w);
            }
        }
        __syncthreads();

        const int ch = icb + c;
        ull acc5[4], acc3[4];
        {
            ull b5v = db5[ch], b3v = db3[ch];
#pragma unroll
            for (int j = 0; j < 4; j++) { acc5[j] = b5v; acc3[j] = b3v; }
        }
#pragma unroll
        for (int dy = 0; dy < 5; dy++) {
            const ull* row = (const ull*)&sin_[(c * 8 + py + dy) * 68 + xo];
            ull r0 = row[0], r1 = row[1], r2 = row[2],
                r3 = row[3], r4 = row[4], r5 = row[5];
            ull m0 = pk2(f2hi(r0), f2lo(r1));
            ull m1 = pk2(f2hi(r1), f2lo(r2));
            ull m2 = pk2(f2hi(r2), f2lo(r3));
            ull m3 = pk2(f2hi(r3), f2lo(r4));
            ull m4 = pk2(f2hi(r4), f2lo(r5));
            const ull* w5r = &w5p[ch * 25 + dy * 5];
            ull w0 = w5r[0], w1 = w5r[1], w2 = w5r[2], w3v = w5r[3], w4 = w5r[4];

            ffma2(acc5[0], w0, r0); ffma2(acc5[0], w1, m0); ffma2(acc5[0], w2, r1);
            ffma2(acc5[0], w3v, m1); ffma2(acc5[0], w4, r2);
            ffma2(acc5[1], w0, r1); ffma2(acc5[1], w1, m1); ffma2(acc5[1], w2, r2);
            ffma2(acc5[1], w3v, m2); ffma2(acc5[1], w4, r3);
            ffma2(acc5[2], w0, r2); ffma2(acc5[2], w1, m2); ffma2(acc5[2], w2, r3);
            ffma2(acc5[2], w3v, m3); ffma2(acc5[2], w4, r4);
            ffma2(acc5[3], w0, r3); ffma2(acc5[3], w1, m3); ffma2(acc5[3], w2, r4);
            ffma2(acc5[3], w3v, m4); ffma2(acc5[3], w4, r5);

            if (dy >= 1 && dy <= 3) {
                const ull* w3r = &w3p[ch * 9 + (dy - 1) * 3];
                ull u0 = w3r[0], u1 = w3r[1], u2 = w3r[2];
                ffma2(acc3[0], u0, m0); ffma2(acc3[0], u1, r1); ffma2(acc3[0], u2, m1);
                ffma2(acc3[1], u0, m1); ffma2(acc3[1], u1, r2); ffma2(acc3[1], u2, m2);
                ffma2(acc3[2], u0, m2); ffma2(acc3[2], u1, r3); ffma2(acc3[2], u2, m3);
                ffma2(acc3[3], u0, m3); ffma2(acc3[3], u1, r4); ffma2(acc3[3], u2, m4);
            }
        }
        const int ppb = py * 32 + (xo >> 1);
#pragma unroll
        for (int j = 0; j < 4; j++) {
            *(ull*)&d3s[ch * 256 + (ppb + j) * 2] = acc3[j];
            *(ull*)&d5s[ch * 256 + (ppb + j) * 2] = acc5[j];
        }

        if (grp == 1) {
            for (int i = tid; i < 8 * 256; i += 256) {
                int cc = i >> 8, px = i & 255;
                stash[i] = sin_[(cc * 8 + 2 + (px >> 6)) * 68 + 2 + (px & 63)];
            }
        }

        if (grp == 2) {
            const int px = tid;
            const int vy = px >> 6;
            const int vx = px & 63;
            float kk[8], vv[8];
#pragma unroll
            for (int e = 0; e < 8; e++)
                kk[e] = fmaxf(stash[e * 256 + px], 0.f);
#pragma unroll
            for (int d = 0; d < 8; d++)
                vv[d] = sin_[(d * 8 + 2 + vy) * 68 + 2 + vx];

            float vacc[9][8];
#pragma unroll
            for (int d = 0; d < 8; d++)
#pragma unroll
                for (int e = 0; e < 8; e++)
                    vacc[d][e] = vv[d] * kk[e];
#pragma unroll
            for (int e = 0; e < 8; e++) vacc[8][e] = kk[e];

#pragma unroll
            for (int d = 0; d < 9; d++)
#pragma unroll
                for (int e = 0; e < 8; e++) {
                    float v = vacc[d][e];
                    v += __shfl_xor_sync(0xffffffffu, v, 16);
                    v += __shfl_xor_sync(0xffffffffu, v, 8);
                    v += __shfl_xor_sync(0xffffffffu, v, 4);
                    v += __shfl_xor_sync(0xffffffffu, v, 2);
                    v += __shfl_xor_sync(0xffffffffu, v, 1);
                    vacc[d][e] = v;
                }
            __syncthreads();
            const int w    = tid >> 5;
            const int lane = tid & 31;
            if (lane == 0) {
#pragma unroll
                for (int d = 0; d < 9; d++)
#pragma unroll
                    for (int e = 0; e < 8; e++)
                        stash[w * 72 + d * 8 + e] = vacc[d][e];
            }
            __syncthreads();
            if (tid < 72) {
                float s = 0.f;
#pragma unroll
                for (int j = 0; j < 8; j++) s += stash[j * 72 + tid];
                atomicAdd(&vkg[((size_t)b * 96 + g) * 72 + tid], s);
            }
        }
    }
    __syncthreads();

    const int conv = tid >> 7;
    const int tt   = tid & 127;
    const int og   = tt >> 5;
    const int pg   = tt & 31;
    const float* dsrc = conv ? d5s : d3s;
    const ull* wp = &pwp[conv * 576];
    const ull* bb = &pwb[conv * 24];
    float* qout = conv ? s5q : s3q;

    ull acc[6][4];
#pragma unroll
    for (int j = 0; j < 6; j++) {
        ull bv = bb[og * 6 + j];
#pragma unroll
        for (int i = 0; i < 4; i++) acc[j][i] = bv;
    }

#pragma unroll
    for (int ic = 0; ic < 24; ic++) {
        const ulonglong2 dA = *(const ulonglong2*)&dsrc[ic * 256 + pg * 8];
        const ulonglong2 dB = *(const ulonglong2*)&dsrc[ic * 256 + pg * 8 + 4];
        ull dv[4] = {dA.x, dA.y, dB.x, dB.y};
#pragma unroll
        for (int j = 0; j < 6; j++) {
            ull wv = wp[(og * 6 + j) * 24 + ic];
#pragma unroll
            for (int i = 0; i < 4; i++)
                ffma2(acc[j][i], wv, dv[i]);
        }
    }
    __syncthreads();

    {
        const int pair0 = pg * 4;
        const int by = y0 + (pair0 >> 5);
        const int bx = (pair0 & 31) * 2;
        const size_t qbase = (((size_t)b * 32 + g) * 8) * NPIX + by * WIDTH + bx;
#pragma unroll
        for (int j = 0; j < 6; j++) {
            const int o = og * 6 + j;
            if (o < 8) {
#pragma unroll
                for (int i = 0; i < 4; i++)
                    *(float2*)&qout[qbase + (size_t)o * NPIX + i * 2] =
                        make_float2(f2lo(acc[j][i]), f2hi(acc[j][i]));
            } else {
#pragma unroll
                for (int i = 0; i < 4; i++)
                    kvq[(conv * 16 + (o - 8)) * 128 + pair0 + i] = acc[j][i];
            }
        }
    }
    __syncthreads();

    {
        const int w    = tid >> 5;
        const int lane = tid & 31;
        const int cv   = w >> 2;
        const int sub  = w & 3;
        const int pair = sub * 32 + lane;

        ull kvv[16];
#pragma unroll
        for (int ch = 0; ch < 16; ch++)
            kvv[ch] = kvq[(cv * 16 + ch) * 128 + pair];

        float acc2[9][8];
#pragma unroll
        for (int d = 0; d < 9; d++)
#pragma unroll
            for (int e = 0; e < 8; e++) acc2[d][e] = 0.f;

#pragma unroll
        for (int hx = 0; hx < 2; hx++) {
            float kk[8], vv[8];
#pragma unroll
            for (int e = 0; e < 8; e++)
                kk[e] = fmaxf(hx ? f2hi(kvv[e]) : f2lo(kvv[e]), 0.f);
#pragma unroll
            for (int d = 0; d < 8; d++)
                vv[d] = hx ? f2hi(kvv[8 + d]) : f2lo(kvv[8 + d]);
#pragma unroll
            for (int d = 0; d < 8; d++)
#pragma unroll
                for (int e = 0; e < 8; e++)
                    acc2[d][e] += vv[d] * kk[e];
#pragma unroll
            for (int e = 0; e < 8; e++)
                acc2[8][e] += kk[e];
        }

#pragma unroll
        for (int d = 0; d < 9; d++)
#pragma unroll
            for (int e = 0; e < 8; e++) {
                float v = acc2[d][e];
                v += __shfl_xor_sync(0xffffffffu, v, 16);
                v += __shfl_xor_sync(0xffffffffu, v, 8);
                v += __shfl_xor_sync(0xffffffffu, v, 4);
                acc2[d][e] = v;
            }
        if (lane < 4) {
            float* rp = &red[((cv * 16) + sub * 4 + lane) * 72];
#pragma unroll
            for (int d = 0; d < 9; d++)
#pragma unroll
                for (int e = 0; e < 8; e++)
                    rp[d * 8 + e] = acc2[d][e];
        }
    }
    __syncthreads();

    if (tid < 144) {
        const int cv  = tid / 72;
        const int idx = tid % 72;
        float s = 0.f;
#pragma unroll
        for (int j = 0; j < 16; j++)
            s += red[(cv * 16 + j) * 72 + idx];
        atomicAdd(&vkg[((size_t)b * 96 + 32 + cv * 32 + g) * 72 + idx], s);
    }
}

// ---------------------------------------------------------------------------
// attention normalize: 4 CTAs/SM, packed f32x2, z-split 8.  (unchanged)
// ---------------------------------------------------------------------------
__global__ __launch_bounds__(256, 4)
void att_kernel(const float* __restrict__ qkv, const float* __restrict__ s3q,
                const float* __restrict__ s5q, const float* __restrict__ vk,
                __half* __restrict__ atth)
{
    const int hh = blockIdx.x;
    const int b  = blockIdx.y;
    const int n0 = blockIdx.z * (NPIX / 8);
    const int src_id = hh >> 5;
    const int g      = hh & 31;
    const float* base;
    if (src_id == 0)      base = qkv + ((size_t)b * C3 + g * 24) * NPIX;
    else if (src_id == 1) base = s3q + (((size_t)b * 32 + g) * 8) * NPIX;
    else                  base = s5q + (((size_t)b * 32 + g) * 8) * NPIX;

    __shared__ ull vsp[72];
    const int tid = threadIdx.x;
    if (tid < 72) {
        float v = vk[((size_t)b * 96 + hh) * 72 + tid];
        vsp[tid] = pk2(v, v);
    }
    __syncthreads();

    __half* oh = atth + ((size_t)b * C3 + hh * 8) * NPIX;

    {
        const int n = n0 + tid * 2;
        ull qp[8];
#pragma unroll
        for (int e = 0; e < 8; e++) {
            ull raw = *(const ull*)(base + (size_t)e * NPIX + n);
            qp[e] = pk2(fmaxf(f2lo(raw), 0.f), fmaxf(f2hi(raw), 0.f));
        }
        ull den = pk2(1e-15f, 1e-15f);
#pragma unroll
        for (int e = 0; e < 8; e++) ffma2(den, vsp[64 + e], qp[e]);
        const float rd0 = __fdividef(1.f, f2lo(den));
        const float rd1 = __fdividef(1.f, f2hi(den));
#pragma unroll
        for (int d = 0; d < 8; d++) {
            ull num = 0ull;
#pragma unroll
            for (int e = 0; e < 8; e++) ffma2(num, vsp[d * 8 + e], qp[e]);
            __half2 hp;
            hp.x = __float2half_rn(f2lo(num) * rd0);
            hp.y = __float2half_rn(f2hi(num) * rd1);
            *(__half2*)(oh + (size_t)d * NPIX + n) = hp;
        }
    }
}

// ---------------------------------------------------------------------------
struct PipeArgs {
    const float *x, *qkv_b, *dw3_w, *dw3_b, *pw3_w, *pw3_b;
    const float *dw5_w, *dw5_b, *pw5_w, *pw5_b, *proj_b;
    __half *xth, *xtl, *ath, *wqh, *wql, *wph, *wpl;
    float *qkv, *s3q, *s5q, *vkb, *out;
};

static void enqueue_part(cudaStream_t st, const PipeArgs& a, int b0, int nb,
                         cudaEvent_t evW)
{
    const size_t offX = (size_t)b0 * 256 * NPIX;
    const size_t offQ = (size_t)b0 * C3 * NPIX;
    const size_t off3 = (size_t)b0 * 32 * 8 * NPIX;
    const size_t offV = (size_t)b0 * 96 * 72;

    wsplit_kernel<<<(nb * 256 * NPIX / 4 + 255) / 256, 256, 0, st>>>(
        a.x + offX, a.xth + offX, a.xtl + offX, nb * 256 * NPIX);

    cudaStreamWaitEvent(st, evW, 0);

    gemm_f16<<<dim3(NPIX / 128, C3 / 128, nb), 256, 3 * STG2, st>>>(
        a.wqh, a.wql, a.xth + offX, a.xtl + offX, a.qkv_b, a.qkv + offQ,
        C3, NPIX, 256);

    dwpw_kernel<<<dim3(16, 32, nb), 256, DW_SMEM, st>>>(
        a.qkv + offQ, a.dw3_w, a.dw3_b, a.pw3_w, a.pw3_b,
        a.dw5_w, a.dw5_b, a.pw5_w, a.pw5_b,
        a.s3q + off3, a.s5q + off3, a.vkb + offV);

    att_kernel<<<dim3(96, nb, 8), 256, 0, st>>>(
        a.qkv + offQ, a.s3q + off3, a.s5q + off3, a.vkb + offV, a.ath + offQ);

    gemm_f16_2p<<<dim3(NPIX / 128, 256 / 128, nb), 256, 3 * P2_STG, st>>>(
        a.wph, a.wpl, a.ath + offQ, a.proj_b, a.out + (size_t)b0 * 256 * NPIX,
        256, NPIX, C3);
}

extern "C" void kernel_launch(void* const* d_in, const int* in_sizes, int n_in,
                              void* d_out, int out_size)
{
    PipeArgs a;
    a.x      = (const float*)d_in[0];
    const float* qkv_w = (const float*)d_in[1];
    a.qkv_b  = (const float*)d_in[2];
    a.dw3_w  = (const float*)d_in[3];
    a.dw3_b  = (const float*)d_in[4];
    a.pw3_w  = (const float*)d_in[5];
    a.pw3_b  = (const float*)d_in[6];
    a.dw5_w  = (const float*)d_in[7];
    a.dw5_b  = (const float*)d_in[8];
    a.pw5_w  = (const float*)d_in[9];
    a.pw5_b  = (const float*)d_in[10];
    const float* proj_w = (const float*)d_in[11];
    a.proj_b = (const float*)d_in[12];
    a.out    = (float*)d_out;

    void *p;
    cudaGetSymbolAddress(&p, g_qkv);  a.qkv = (float*)p;
    cudaGetSymbolAddress(&p, g_s3q);  a.s3q = (float*)p;
    cudaGetSymbolAddress(&p, g_s5q);  a.s5q = (float*)p;
    cudaGetSymbolAddress(&p, g_vk);   a.vkb = (float*)p;
    cudaGetSymbolAddress(&p, g_xt_h); a.xth = (__half*)p;
    cudaGetSymbolAddress(&p, g_xt_l); a.xtl = (__half*)p;
    cudaGetSymbolAddress(&p, g_at_h); a.ath = (__half*)p;
    cudaGetSymbolAddress(&p, g_wq_h); a.wqh = (__half*)p;
    cudaGetSymbolAddress(&p, g_wq_l); a.wql = (__half*)p;
    cudaGetSymbolAddress(&p, g_wp_h); a.wph = (__half*)p;
    cudaGetSymbolAddress(&p, g_wp_l); a.wpl = (__half*)p;

    static bool inited = false;
    static cudaStream_t s[3];
    static cudaEvent_t evW, evF, evJ[3];
    if (!inited) {
        for (int i = 0; i < 3; i++) {
            cudaStreamCreateWithFlags(&s[i], cudaStreamNonBlocking);
            cudaEventCreateWithFlags(&evJ[i], cudaEventDisableTiming);
        }
        cudaEventCreateWithFlags(&evW, cudaEventDisableTiming);
        cudaEventCreateWithFlags(&evF, cudaEventDisableTiming);
        cudaFuncSetAttribute(gemm_f16,
            cudaFuncAttributeMaxDynamicSharedMemorySize, 3 * STG2);
        cudaFuncSetAttribute(gemm_f16_2p,
            cudaFuncAttributeMaxDynamicSharedMemorySize, 3 * P2_STG);
        cudaFuncSetAttribute(dwpw_kernel,
            cudaFuncAttributeMaxDynamicSharedMemorySize, DW_SMEM);
        inited = true;
    }

    // main stream head: vk zero, then fork so side streams start x-splits
    cudaMemsetAsync(a.vkb, 0, (size_t)BATCH * 96 * 72 * sizeof(float), 0);
    cudaEventRecord(evF, 0);
    for (int i = 0; i < 3; i++) cudaStreamWaitEvent(s[i], evF, 0);

    // fused weight split on the main stream (one launch, both tensors)
    wsplit2_kernel<<<384, 256>>>(qkv_w, a.wqh, a.wql, proj_w, a.wph, a.wpl);
    cudaEventRecord(evW, 0);

    enqueue_part(0,    a, 0, 2, evW);
    enqueue_part(s[0], a, 2, 2, evW);
    enqueue_part(s[1], a, 4, 2, evW);
    enqueue_part(s[2], a, 6, 2, evW);

    for (int i = 0; i < 3; i++) {
        cudaEventRecord(evJ[i], s[i]);
        cudaStreamWaitEvent(0, evJ[i], 0);
    }
}